// round 9
// baseline (speedup 1.0000x reference)
#include <cuda_runtime.h>
#include <cuda_bf16.h>
#include <cstdint>

#define BB 4
#define CC 512
#define CQ 64
#define DD 128   // 2*CQ
#define NN 4096  // H*W

// ---------------- scratch (device globals; no allocations allowed) ----------
__device__ __align__(256) __nv_bfloat16 g_xt_hi[BB * NN * CC];  // x^T [b][n][c]
__device__ __align__(256) __nv_bfloat16 g_xt_lo[BB * NN * CC];
__device__ __align__(256) __nv_bfloat16 g_dt_hi[BB * NN * CC];  // dep^T
__device__ __align__(256) __nv_bfloat16 g_dt_lo[BB * NN * CC];
__device__ __align__(256) __nv_bfloat16 g_wqk_hi[DD * CC];      // wq rows 0-63, wk 64-127
__device__ __align__(256) __nv_bfloat16 g_wqk_lo[DD * CC];
__device__ __align__(256) __nv_bfloat16 g_wqkd_hi[DD * CC];
__device__ __align__(256) __nv_bfloat16 g_wqkd_lo[DD * CC];
__device__ __align__(256) __nv_bfloat16 g_wv_hi[CC * CC];
__device__ __align__(256) __nv_bfloat16 g_wv_lo[CC * CC];
__device__ __align__(256) __nv_bfloat16 g_qhi[BB * NN * DD];    // [b][i][d]
__device__ __align__(256) __nv_bfloat16 g_qlo[BB * NN * DD];
__device__ __align__(256) __nv_bfloat16 g_khi[BB * NN * DD];
__device__ __align__(256) __nv_bfloat16 g_klo[BB * NN * DD];
__device__ __align__(256) __nv_bfloat16 g_vhi[BB * CC * NN];    // [b][c][n]
__device__ __align__(256) __nv_bfloat16 g_vlo[BB * CC * NN];
__device__ __align__(256) float g_e[(size_t)BB * NN * NN];
__device__ __align__(256) __nv_bfloat16 g_phi[(size_t)BB * NN * NN];
__device__ __align__(256) __nv_bfloat16 g_plo[(size_t)BB * NN * NN];
__device__ __align__(256) float g_s[BB * NN];

// ---------------- low-level helpers -----------------------------------------
__device__ __forceinline__ uint32_t smem_to_u32(const void* p) {
    uint32_t a;
    asm("{ .reg .u64 t; cvta.to.shared.u64 t, %1; cvt.u32.u64 %0, t; }" : "=r"(a) : "l"(p));
    return a;
}
#define SWZ(off) ((off) ^ (((off) >> 3) & 0x70))

__device__ __forceinline__ void cp16(uint32_t dst, const void* src) {
    asm volatile("cp.async.cg.shared.global [%0], [%1], 16;" :: "r"(dst), "l"(src));
}
__device__ __forceinline__ void cp_commit() {
    asm volatile("cp.async.commit_group;" ::: "memory");
}
__device__ __forceinline__ void ldsm4(uint32_t r[4], uint32_t addr) {
    asm volatile("ldmatrix.sync.aligned.m8n8.x4.shared.b16 {%0,%1,%2,%3}, [%4];"
                 : "=r"(r[0]), "=r"(r[1]), "=r"(r[2]), "=r"(r[3]) : "r"(addr));
}
__device__ __forceinline__ void mma_bf16(float acc[4], const uint32_t a[4],
                                         uint32_t b0, uint32_t b1) {
    asm volatile("mma.sync.aligned.m16n8k16.row.col.f32.bf16.bf16.f32 "
                 "{%0,%1,%2,%3}, {%4,%5,%6,%7}, {%8,%9}, {%0,%1,%2,%3};"
                 : "+f"(acc[0]), "+f"(acc[1]), "+f"(acc[2]), "+f"(acc[3])
                 : "r"(a[0]), "r"(a[1]), "r"(a[2]), "r"(a[3]), "r"(b0), "r"(b1));
}
__device__ __forceinline__ void split4(const float f[4], __nv_bfloat16 h[4], __nv_bfloat16 l[4])
{
#pragma unroll
    for (int i = 0; i < 4; i++) {
        h[i] = __float2bfloat16(f[i]);
        l[i] = __float2bfloat16(f[i] - __bfloat162float(h[i]));
    }
}
__device__ __forceinline__ void split_store2(float v0, float v1,
                                             __nv_bfloat16* dh, __nv_bfloat16* dl)
{
    __nv_bfloat16 h0 = __float2bfloat16(v0), h1 = __float2bfloat16(v1);
    __nv_bfloat16 l0 = __float2bfloat16(v0 - __bfloat162float(h0));
    __nv_bfloat16 l1 = __float2bfloat16(v1 - __bfloat162float(h1));
    __nv_bfloat162 H; H.x = h0; H.y = h1;
    __nv_bfloat162 L; L.x = l0; L.y = l1;
    *(__nv_bfloat162*)dh = H;
    *(__nv_bfloat162*)dl = L;
}

// ---------------- split-bf16 MMA machinery -----------------------------------
// Templated on WROWS (number of 64-row warp rows in the M tile):
//   WROWS=2: 128xM tile, 8 warps (256 thr);  WROWS=4: 256xM tile, 16 warps (512 thr).
// Stage layout: A_hi [WROWS*8192 B] | A_lo | B_hi 16KB | B_lo 16KB. 2 stages.

template <int WROWS>
struct StageGeom {
    static constexpr uint32_t A_BYTES = WROWS * 8192;
    static constexpr uint32_t B_OFF   = 2 * A_BYTES;
    static constexpr uint32_t STG_SZ  = 2 * A_BYTES + 32768;
    static constexpr uint32_t SMEM    = 2 * STG_SZ;
};

template <int WROWS, int T>
__device__ __forceinline__ void stage_load(
    const __nv_bfloat16* __restrict__ Ahi, const __nv_bfloat16* __restrict__ Alo,
    size_t aStr,
    const __nv_bfloat16* __restrict__ Bhi, const __nv_bfloat16* __restrict__ Blo,
    size_t bStr, int kt, uint32_t stg, int t)
{
    constexpr uint32_t A_BYTES = StageGeom<WROWS>::A_BYTES;
    constexpr uint32_t B_OFF = StageGeom<WROWS>::B_OFF;
#pragma unroll
    for (int id = 0; id < WROWS * 512; id += T) {
        const int i = id + t;
        const int row = i >> 3, c16 = i & 7;
        const uint32_t doff = SWZ((uint32_t)(row * 128 + c16 * 16));
        const size_t so = (size_t)row * aStr + kt + c16 * 8;
        cp16(stg + doff,           Ahi + so);
        cp16(stg + A_BYTES + doff, Alo + so);
    }
#pragma unroll
    for (int id = 0; id < 1024; id += T) {
        const int i = id + t;
        const int row = i >> 3, c16 = i & 7;
        const uint32_t doff = SWZ((uint32_t)(row * 128 + c16 * 16));
        const size_t sb = (size_t)row * bStr + kt + c16 * 8;
        cp16(stg + B_OFF + doff,         Bhi + sb);
        cp16(stg + B_OFF + 16384 + doff, Blo + sb);
    }
}

// Per-mi A loads to keep live registers under the 128-reg cap at 512 threads.
template <int WROWS>
__device__ __forceinline__ void stage_compute(uint32_t stg, int wid, int lane,
                                              float acc[4][4][4])
{
    constexpr uint32_t A_BYTES = StageGeom<WROWS>::A_BYTES;
    constexpr uint32_t B_OFF = StageGeom<WROWS>::B_OFF;
    const int warp_row = wid >> 2;        // 0..WROWS-1
    const int warp_col = wid & 3;
    const int lrow = lane & 15;
    const int chalf = (lane >= 16) ? 16 : 0;

#pragma unroll
    for (int ks = 0; ks < 4; ks++) {
        const uint32_t bcol = ks * 32 + chalf;
        uint32_t bhi[2][4], blo[2][4];
#pragma unroll
        for (int nh = 0; nh < 2; nh++) {
            const uint32_t off = SWZ((uint32_t)((warp_col * 32 + nh * 16 + lrow) * 128 + bcol));
            ldsm4(bhi[nh], stg + B_OFF + off);
            ldsm4(blo[nh], stg + B_OFF + 16384 + off);
        }
#pragma unroll
        for (int mi = 0; mi < 4; mi++) {
            uint32_t ahi[4], alo[4];
            const uint32_t off = SWZ((uint32_t)((warp_row * 64 + mi * 16 + lrow) * 128 + bcol));
            ldsm4(ahi, stg + off);
            ldsm4(alo, stg + A_BYTES + off);
#pragma unroll
            for (int ni = 0; ni < 4; ni++) {
                const int nh = ni >> 1, s = ni & 1;
                mma_bf16(acc[mi][ni], ahi, bhi[nh][s], bhi[nh][s + 2]);
                mma_bf16(acc[mi][ni], alo, bhi[nh][s], bhi[nh][s + 2]);
                mma_bf16(acc[mi][ni], ahi, blo[nh][s], blo[nh][s + 2]);
            }
        }
    }
}

// R6-proven 2-stage pipelined K loop.
template <int KCHUNKS, int WROWS, int T>
__device__ __forceinline__ void mma_mainloop(
    const __nv_bfloat16* Ahi, const __nv_bfloat16* Alo, size_t aStr,
    const __nv_bfloat16* Bhi, const __nv_bfloat16* Blo, size_t bStr,
    uint32_t smemU32, int t, int wid, int lane, float acc[4][4][4])
{
    constexpr uint32_t STG_SZ = StageGeom<WROWS>::STG_SZ;
    stage_load<WROWS, T>(Ahi, Alo, aStr, Bhi, Blo, bStr, 0, smemU32, t);
    cp_commit();
    for (int c = 0; c < KCHUNKS; c++) {
        const bool more = (c + 1) < KCHUNKS;
        if (more) {
            stage_load<WROWS, T>(Ahi, Alo, aStr, Bhi, Blo, bStr, (c + 1) * 64,
                                 smemU32 + ((c + 1) & 1) * STG_SZ, t);
            cp_commit();
            asm volatile("cp.async.wait_group 1;" ::: "memory");
        } else {
            asm volatile("cp.async.wait_group 0;" ::: "memory");
        }
        __syncthreads();
        stage_compute<WROWS>(smemU32 + (c & 1) * STG_SZ, wid, lane, acc);
        __syncthreads();
    }
}

// ============================================================================
// transpose + split: src [b][C][N] fp32 -> dst [b][N][C] bf16 hi/lo
// ============================================================================
__global__ void __launch_bounds__(256)
transpose_split(const float* __restrict__ src,
                __nv_bfloat16* __restrict__ dhi, __nv_bfloat16* __restrict__ dlo)
{
    __shared__ float tile[32][33];
    const int b = blockIdx.z;
    const int n0 = blockIdx.x * 32, c0 = blockIdx.y * 32;
    const int tx = threadIdx.x, ty = threadIdx.y;   // (32, 8)
    const float* S = src + (size_t)b * CC * NN;
#pragma unroll
    for (int i = 0; i < 4; i++)
        tile[ty * 4 + i][tx] = S[(size_t)(c0 + ty * 4 + i) * NN + n0 + tx];
    __syncthreads();
    __nv_bfloat16* H = dhi + (size_t)b * NN * CC;
    __nv_bfloat16* L = dlo + (size_t)b * NN * CC;
#pragma unroll
    for (int i = 0; i < 4; i++) {
        const float f = tile[tx][ty * 4 + i];
        const __nv_bfloat16 h = __float2bfloat16(f);
        const __nv_bfloat16 l = __float2bfloat16(f - __bfloat162float(h));
        const size_t idx = (size_t)(n0 + ty * 4 + i) * CC + c0 + tx;
        H[idx] = h;
        L[idx] = l;
    }
}

// ============================================================================
// weight split
// ============================================================================
__global__ void __launch_bounds__(256)
weight_split(const float* __restrict__ wq, const float* __restrict__ wk,
             const float* __restrict__ wqd, const float* __restrict__ wkd,
             const float* __restrict__ wv,
             __nv_bfloat16* __restrict__ wqk_hi, __nv_bfloat16* __restrict__ wqk_lo,
             __nv_bfloat16* __restrict__ wqkd_hi, __nv_bfloat16* __restrict__ wqkd_lo,
             __nv_bfloat16* __restrict__ wv_hi, __nv_bfloat16* __restrict__ wv_lo)
{
    const int idx = blockIdx.x * 256 + threadIdx.x;
    if (idx >= 768 * 512) return;
    const int row = idx >> 9, col = idx & 511;
    const float* src;
    __nv_bfloat16 *dh, *dl;
    int drow;
    if (row < 512)      { src = wv  + (size_t)row * 512;         dh = wv_hi;   dl = wv_lo;   drow = row; }
    else if (row < 576) { src = wq  + (size_t)(row - 512) * 512; dh = wqk_hi;  dl = wqk_lo;  drow = row - 512; }
    else if (row < 640) { src = wk  + (size_t)(row - 576) * 512; dh = wqk_hi;  dl = wqk_lo;  drow = row - 576 + 64; }
    else if (row < 704) { src = wqd + (size_t)(row - 640) * 512; dh = wqkd_hi; dl = wqkd_lo; drow = row - 640; }
    else                { src = wkd + (size_t)(row - 704) * 512; dh = wqkd_hi; dl = wqkd_lo; drow = row - 704 + 64; }
    const float f = src[col];
    const __nv_bfloat16 h = __float2bfloat16(f);
    dh[(size_t)drow * 512 + col] = h;
    dl[(size_t)drow * 512 + col] = __float2bfloat16(f - __bfloat162float(h));
}

// ============================================================================
// proj qk (WROWS=2, 256 thr): [n][d] = xt[n][c] . wqk[d][c]
// ============================================================================
__global__ void __launch_bounds__(256, 1)
mma_proj_qk(const __nv_bfloat16* __restrict__ xt_hi, const __nv_bfloat16* __restrict__ xt_lo,
            const __nv_bfloat16* __restrict__ w_hi,  const __nv_bfloat16* __restrict__ w_lo,
            const float* __restrict__ bias_q, const float* __restrict__ bias_k,
            __nv_bfloat16* __restrict__ Qhi, __nv_bfloat16* __restrict__ Qlo,
            __nv_bfloat16* __restrict__ Khi, __nv_bfloat16* __restrict__ Klo,
            int d_off)
{
    extern __shared__ char smem[];
    const uint32_t smemU32 = smem_to_u32(smem);
    const int t = threadIdx.x, wid = t >> 5, lane = t & 31;
    const int b = blockIdx.z;
    const int i0 = blockIdx.x * 128;

    const size_t aoff = ((size_t)b * NN + i0) * CC;
    float acc[4][4][4] = {};
    mma_mainloop<8, 2, 256>(xt_hi + aoff, xt_lo + aoff, CC, w_hi, w_lo, CC,
                            smemU32, t, wid, lane, acc);

    const int warp_col = wid & 3;
    const bool isK = warp_col >= 2;
    const float* bias = isK ? bias_k : bias_q;
    __nv_bfloat16* DH = isK ? Khi : Qhi;
    __nv_bfloat16* DL = isK ? Klo : Qlo;
    const int csub = isK ? 64 : 0;

    const int rbase = i0 + (wid >> 2) * 64 + (lane >> 2);
    const int cbase = warp_col * 32 + (lane & 3) * 2;
#pragma unroll
    for (int mi = 0; mi < 4; mi++)
#pragma unroll
        for (int ni = 0; ni < 4; ni++) {
            const int col = cbase + ni * 8 - csub;   // 0..63
            const float2 bi = *(const float2*)&bias[col];
            const int r0 = rbase + mi * 16;
            const size_t a0 = ((size_t)b * NN + r0) * DD + d_off + col;
            split_store2(acc[mi][ni][0] + bi.x, acc[mi][ni][1] + bi.y, DH + a0, DL + a0);
            const size_t a1 = ((size_t)b * NN + r0 + 8) * DD + d_off + col;
            split_store2(acc[mi][ni][2] + bi.x, acc[mi][ni][3] + bi.y, DH + a1, DL + a1);
        }
}

// ============================================================================
// proj v (WROWS=4, 512 thr): [c][n] tile (256 c x 128 n) = wv[c][k] . xt[n][k]
// ============================================================================
__global__ void __launch_bounds__(512, 1)
mma_proj_v(const __nv_bfloat16* __restrict__ w_hi, const __nv_bfloat16* __restrict__ w_lo,
           const __nv_bfloat16* __restrict__ xt_hi, const __nv_bfloat16* __restrict__ xt_lo,
           const float* __restrict__ bias,
           __nv_bfloat16* __restrict__ Vhi, __nv_bfloat16* __restrict__ Vlo)
{
    extern __shared__ char smem[];
    const uint32_t smemU32 = smem_to_u32(smem);
    const int t = threadIdx.x, wid = t >> 5, lane = t & 31;
    const int b = blockIdx.z;
    const int n0 = blockIdx.x * 128, m0 = blockIdx.y * 256;

    const size_t boff = ((size_t)b * NN + n0) * CC;
    float acc[4][4][4] = {};
    mma_mainloop<8, 4, 512>(w_hi + (size_t)m0 * CC, w_lo + (size_t)m0 * CC, CC,
                            xt_hi + boff, xt_lo + boff, CC,
                            smemU32, t, wid, lane, acc);

    const int rbase = m0 + (wid >> 2) * 64 + (lane >> 2);
    const int cbase = n0 + (wid & 3) * 32 + (lane & 3) * 2;
#pragma unroll
    for (int mi = 0; mi < 4; mi++) {
        const int ch0 = rbase + mi * 16;
        const float bi0 = bias[ch0], bi1 = bias[ch0 + 8];
#pragma unroll
        for (int ni = 0; ni < 4; ni++) {
            const int cn = cbase + ni * 8;
            const size_t a0 = ((size_t)b * CC + ch0) * NN + cn;
            split_store2(acc[mi][ni][0] + bi0, acc[mi][ni][1] + bi0, Vhi + a0, Vlo + a0);
            const size_t a1 = ((size_t)b * CC + ch0 + 8) * NN + cn;
            split_store2(acc[mi][ni][2] + bi1, acc[mi][ni][3] + bi1, Vhi + a1, Vlo + a1);
        }
    }
}

// ============================================================================
// Energy (WROWS=4, 512 thr): E tile 256 i x 128 j = q[i][d] . k[j][d]
// ============================================================================
__global__ void __launch_bounds__(512, 1)
mma_energy(const __nv_bfloat16* __restrict__ qhi, const __nv_bfloat16* __restrict__ qlo,
           const __nv_bfloat16* __restrict__ khi, const __nv_bfloat16* __restrict__ klo,
           float* __restrict__ E)
{
    extern __shared__ char smem[];
    const uint32_t smemU32 = smem_to_u32(smem);
    const int t = threadIdx.x, wid = t >> 5, lane = t & 31;
    const int b = blockIdx.z;
    const int i0 = blockIdx.y * 256, j0 = blockIdx.x * 128;

    const size_t aoff = ((size_t)b * NN + i0) * DD;
    const size_t boff = ((size_t)b * NN + j0) * DD;

    float acc[4][4][4] = {};
    mma_mainloop<2, 4, 512>(qhi + aoff, qlo + aoff, DD, khi + boff, klo + boff, DD,
                            smemU32, t, wid, lane, acc);

    float* Eb = E + (size_t)b * NN * NN;
    const int rbase = i0 + (wid >> 2) * 64 + (lane >> 2);
    const int cbase = j0 + (wid & 3) * 32 + (lane & 3) * 2;
#pragma unroll
    for (int mi = 0; mi < 4; mi++)
#pragma unroll
        for (int ni = 0; ni < 4; ni++) {
            const int r = rbase + mi * 16;
            const int cjj = cbase + ni * 8;
            *(float2*)&Eb[(size_t)r * NN + cjj]       = make_float2(acc[mi][ni][0], acc[mi][ni][1]);
            *(float2*)&Eb[(size_t)(r + 8) * NN + cjj] = make_float2(acc[mi][ni][2], acc[mi][ni][3]);
        }
}

// ============================================================================
// Out (WROWS=4, 512 thr): tile 256 c x 128 i, K = 4096
// ============================================================================
__global__ void __launch_bounds__(512, 1)
mma_out(const __nv_bfloat16* __restrict__ vhi, const __nv_bfloat16* __restrict__ vlo,
        const __nv_bfloat16* __restrict__ phi, const __nv_bfloat16* __restrict__ plo,
        const float* __restrict__ X, const float* __restrict__ gamma,
        const float* __restrict__ invs, float* __restrict__ Out)
{
    extern __shared__ char smem[];
    const uint32_t smemU32 = smem_to_u32(smem);
    const int t = threadIdx.x, wid = t >> 5, lane = t & 31;
    const int b = blockIdx.z;
    const int c0 = blockIdx.x * 256, i0 = blockIdx.y * 128;

    const size_t aoff = ((size_t)b * CC + c0) * NN;
    const size_t boff = ((size_t)b * NN + i0) * NN;

    float acc[4][4][4] = {};
    mma_mainloop<64, 4, 512>(vhi + aoff, vlo + aoff, NN, phi + boff, plo + boff, NN,
                             smemU32, t, wid, lane, acc);

    const float g = __ldg(gamma);
    const int rbase = c0 + (wid >> 2) * 64 + (lane >> 2);
    const int cbase = i0 + (wid & 3) * 32 + (lane & 3) * 2;
    const float* ivb = invs + b * NN;
#pragma unroll
    for (int mi = 0; mi < 4; mi++)
#pragma unroll
        for (int ni = 0; ni < 4; ni++) {
            const int ch = rbase + mi * 16;
            const int ci = cbase + ni * 8;
            const float2 iv = *(const float2*)&ivb[ci];
            {
                const size_t idx = ((size_t)b * CC + ch) * NN + ci;
                const float2 xv = *(const float2*)&X[idx];
                float2 o;
                o.x = g * acc[mi][ni][0] * iv.x + xv.x;
                o.y = g * acc[mi][ni][1] * iv.y + xv.y;
                *(float2*)&Out[idx] = o;
            }
            {
                const size_t idx = ((size_t)b * CC + ch + 8) * NN + ci;
                const float2 xv = *(const float2*)&X[idx];
                float2 o;
                o.x = g * acc[mi][ni][2] * iv.x + xv.x;
                o.y = g * acc[mi][ni][3] * iv.y + xv.y;
                *(float2*)&Out[idx] = o;
            }
        }
}

// ============================================================================
// Softmax: fp32 energy row -> unnormalized exp bf16 hi/lo + 1/rowsum
// ============================================================================
__global__ void __launch_bounds__(256)
softmax_rows(const float* __restrict__ E,
             __nv_bfloat16* __restrict__ Phi, __nv_bfloat16* __restrict__ Plo,
             float* __restrict__ invs)
{
    __shared__ float red[8];
    const float4* E4 = (const float4*)E;
    const size_t base4 = (size_t)blockIdx.x * (NN / 4);
    const int tid = threadIdx.x;
    const int lane = tid & 31, wid = tid >> 5;

    float4 v[4];
#pragma unroll
    for (int u = 0; u < 4; u++) v[u] = E4[base4 + u * 256 + tid];

    float m = -1e30f;
#pragma unroll
    for (int u = 0; u < 4; u++)
        m = fmaxf(m, fmaxf(fmaxf(v[u].x, v[u].y), fmaxf(v[u].z, v[u].w)));
#pragma unroll
    for (int off = 16; off > 0; off >>= 1)
        m = fmaxf(m, __shfl_xor_sync(0xffffffffu, m, off));
    if (lane == 0) red[wid] = m;
    __syncthreads();
    m = red[0];
#pragma unroll
    for (int w = 1; w < 8; w++) m = fmaxf(m, red[w]);
    __syncthreads();

    float s = 0.f;
#pragma unroll
    for (int u = 0; u < 4; u++) {
        v[u].x = __expf(v[u].x - m); v[u].y = __expf(v[u].y - m);
        v[u].z = __expf(v[u].z - m); v[u].w = __expf(v[u].w - m);
        s += v[u].x + v[u].y + v[u].z + v[u].w;
    }
#pragma unroll
    for (int off = 16; off > 0; off >>= 1)
        s += __shfl_xor_sync(0xffffffffu, s, off);
    if (lane == 0) red[wid] = s;
    __syncthreads();
    s = red[0];
#pragma unroll
    for (int w = 1; w < 8; w++) s += red[w];

#pragma unroll
    for (int u = 0; u < 4; u++) {
        const size_t el = base4 * 4 + (u * 256 + tid) * 4;
        float f[4] = { v[u].x, v[u].y, v[u].z, v[u].w };
        __nv_bfloat16 h[4], l[4];
        split4(f, h, l);
        *(uint2*)&Phi[el] = *(uint2*)h;
        *(uint2*)&Plo[el] = *(uint2*)l;
    }
    if (tid == 0) invs[blockIdx.x] = 1.0f / s;
}

// ============================================================================

extern "C" void kernel_launch(void* const* d_in, const int* in_sizes, int n_in,
                              void* d_out, int out_size)
{
    const float* x     = (const float*)d_in[0];
    const float* dep   = (const float*)d_in[1];
    const float* wq    = (const float*)d_in[2];
    const float* bq    = (const float*)d_in[3];
    const float* wqd   = (const float*)d_in[4];
    const float* bqd   = (const float*)d_in[5];
    const float* wk    = (const float*)d_in[6];
    const float* bk    = (const float*)d_in[7];
    const float* wkd   = (const float*)d_in[8];
    const float* bkd   = (const float*)d_in[9];
    const float* wv    = (const float*)d_in[10];
    const float* bv    = (const float*)d_in[11];
    const float* gamma = (const float*)d_in[12];
    float* out = (float*)d_out;

    __nv_bfloat16 *xt_hi, *xt_lo, *dt_hi, *dt_lo;
    __nv_bfloat16 *wqk_hi, *wqk_lo, *wqkd_hi, *wqkd_lo, *wv_hi, *wv_lo;
    __nv_bfloat16 *qhi, *qlo, *khi, *klo, *vhi, *vlo, *phi, *plo;
    float *e, *s;
    cudaGetSymbolAddress((void**)&xt_hi, g_xt_hi);
    cudaGetSymbolAddress((void**)&xt_lo, g_xt_lo);
    cudaGetSymbolAddress((void**)&dt_hi, g_dt_hi);
    cudaGetSymbolAddress((void**)&dt_lo, g_dt_lo);
    cudaGetSymbolAddress((void**)&wqk_hi, g_wqk_hi);
    cudaGetSymbolAddress((void**)&wqk_lo, g_wqk_lo);
    cudaGetSymbolAddress((void**)&wqkd_hi, g_wqkd_hi);
    cudaGetSymbolAddress((void**)&wqkd_lo, g_wqkd_lo);
    cudaGetSymbolAddress((void**)&wv_hi, g_wv_hi);
    cudaGetSymbolAddress((void**)&wv_lo, g_wv_lo);
    cudaGetSymbolAddress((void**)&qhi, g_qhi);
    cudaGetSymbolAddress((void**)&qlo, g_qlo);
    cudaGetSymbolAddress((void**)&khi, g_khi);
    cudaGetSymbolAddress((void**)&klo, g_klo);
    cudaGetSymbolAddress((void**)&vhi, g_vhi);
    cudaGetSymbolAddress((void**)&vlo, g_vlo);
    cudaGetSymbolAddress((void**)&phi, g_phi);
    cudaGetSymbolAddress((void**)&plo, g_plo);
    cudaGetSymbolAddress((void**)&e, g_e);
    cudaGetSymbolAddress((void**)&s, g_s);

    constexpr int SMEM2 = StageGeom<2>::SMEM;   // 128 KB
    constexpr int SMEM4 = StageGeom<4>::SMEM;   // 192 KB
    cudaFuncSetAttribute(mma_proj_qk, cudaFuncAttributeMaxDynamicSharedMemorySize, SMEM2);
    cudaFuncSetAttribute(mma_proj_v,  cudaFuncAttributeMaxDynamicSharedMemorySize, SMEM4);
    cudaFuncSetAttribute(mma_energy,  cudaFuncAttributeMaxDynamicSharedMemorySize, SMEM4);
    cudaFuncSetAttribute(mma_out,     cudaFuncAttributeMaxDynamicSharedMemorySize, SMEM4);

    // input prep
    dim3 tthr(32, 8);
    transpose_split<<<dim3(NN / 32, CC / 32, BB), tthr>>>(x,   xt_hi, xt_lo);
    transpose_split<<<dim3(NN / 32, CC / 32, BB), tthr>>>(dep, dt_hi, dt_lo);
    weight_split<<<(768 * 512 + 255) / 256, 256>>>(wq, wk, wqd, wkd, wv,
                                                   wqk_hi, wqk_lo, wqkd_hi, wqkd_lo,
                                                   wv_hi, wv_lo);

    // projections
    mma_proj_qk<<<dim3(NN / 128, 1, BB), 256, SMEM2>>>(
        xt_hi, xt_lo, wqk_hi, wqk_lo, bq, bk, qhi, qlo, khi, klo, 0);
    mma_proj_qk<<<dim3(NN / 128, 1, BB), 256, SMEM2>>>(
        dt_hi, dt_lo, wqkd_hi, wqkd_lo, bqd, bkd, qhi, qlo, khi, klo, CQ);
    mma_proj_v<<<dim3(NN / 128, CC / 256, BB), 512, SMEM4>>>(
        wv_hi, wv_lo, xt_hi, xt_lo, bv, vhi, vlo);

    // energy
    mma_energy<<<dim3(NN / 128, NN / 256, BB), 512, SMEM4>>>(qhi, qlo, khi, klo, e);

    // softmax
    softmax_rows<<<BB * NN, 256>>>(e, phi, plo, s);

    // out
    mma_out<<<dim3(CC / 256, NN / 128, BB), 512, SMEM4>>>(vhi, vlo, phi, plo, x, gamma, s, out);
}

// round 10
// speedup vs baseline: 1.8158x; 1.8158x over previous
#include <cuda_runtime.h>
#include <cuda_bf16.h>
#include <cuda_fp16.h>
#include <cstdint>

#define BB 4
#define CC 512
#define CQ 64
#define DD 128   // 2*CQ
#define NN 4096  // H*W

// ---------------- scratch (device globals; no allocations allowed) ----------
__device__ __align__(256) __nv_bfloat16 g_xt_hi[BB * NN * CC];  // x^T [b][n][c]
__device__ __align__(256) __nv_bfloat16 g_xt_lo[BB * NN * CC];
__device__ __align__(256) __nv_bfloat16 g_dt_hi[BB * NN * CC];  // dep^T
__device__ __align__(256) __nv_bfloat16 g_dt_lo[BB * NN * CC];
__device__ __align__(256) __nv_bfloat16 g_wqk_hi[DD * CC];      // wq rows 0-63, wk 64-127
__device__ __align__(256) __nv_bfloat16 g_wqk_lo[DD * CC];
__device__ __align__(256) __nv_bfloat16 g_wqkd_hi[DD * CC];
__device__ __align__(256) __nv_bfloat16 g_wqkd_lo[DD * CC];
__device__ __align__(256) __nv_bfloat16 g_wv_hi[CC * CC];
__device__ __align__(256) __nv_bfloat16 g_wv_lo[CC * CC];
__device__ __align__(256) __nv_bfloat16 g_qhi[BB * NN * DD];    // [b][i][d]
__device__ __align__(256) __nv_bfloat16 g_qlo[BB * NN * DD];
__device__ __align__(256) __nv_bfloat16 g_khi[BB * NN * DD];
__device__ __align__(256) __nv_bfloat16 g_klo[BB * NN * DD];
__device__ __align__(256) __half g_vhi[BB * CC * NN];           // [b][c][n] fp16
__device__ __align__(256) __half g_vlo[BB * CC * NN];
__device__ __align__(256) float g_e[(size_t)BB * NN * NN];
__device__ __align__(256) __half g_p[(size_t)BB * NN * NN];     // exp, fp16 single
__device__ __align__(256) float g_s[BB * NN];

// ---------------- low-level helpers -----------------------------------------
__device__ __forceinline__ uint32_t smem_to_u32(const void* p) {
    uint32_t a;
    asm("{ .reg .u64 t; cvta.to.shared.u64 t, %1; cvt.u32.u64 %0, t; }" : "=r"(a) : "l"(p));
    return a;
}
#define SWZ(off) ((off) ^ (((off) >> 3) & 0x70))

__device__ __forceinline__ void cp16(uint32_t dst, const void* src) {
    asm volatile("cp.async.cg.shared.global [%0], [%1], 16;" :: "r"(dst), "l"(src));
}
__device__ __forceinline__ void cp_commit() {
    asm volatile("cp.async.commit_group;" ::: "memory");
}
__device__ __forceinline__ void ldsm4(uint32_t r[4], uint32_t addr) {
    asm volatile("ldmatrix.sync.aligned.m8n8.x4.shared.b16 {%0,%1,%2,%3}, [%4];"
                 : "=r"(r[0]), "=r"(r[1]), "=r"(r[2]), "=r"(r[3]) : "r"(addr));
}
__device__ __forceinline__ void mma_bf16(float acc[4], const uint32_t a[4],
                                         uint32_t b0, uint32_t b1) {
    asm volatile("mma.sync.aligned.m16n8k16.row.col.f32.bf16.bf16.f32 "
                 "{%0,%1,%2,%3}, {%4,%5,%6,%7}, {%8,%9}, {%0,%1,%2,%3};"
                 : "+f"(acc[0]), "+f"(acc[1]), "+f"(acc[2]), "+f"(acc[3])
                 : "r"(a[0]), "r"(a[1]), "r"(a[2]), "r"(a[3]), "r"(b0), "r"(b1));
}
__device__ __forceinline__ void mma_f16(float acc[4], const uint32_t a[4],
                                        uint32_t b0, uint32_t b1) {
    asm volatile("mma.sync.aligned.m16n8k16.row.col.f32.f16.f16.f32 "
                 "{%0,%1,%2,%3}, {%4,%5,%6,%7}, {%8,%9}, {%0,%1,%2,%3};"
                 : "+f"(acc[0]), "+f"(acc[1]), "+f"(acc[2]), "+f"(acc[3])
                 : "r"(a[0]), "r"(a[1]), "r"(a[2]), "r"(a[3]), "r"(b0), "r"(b1));
}
__device__ __forceinline__ void split4(const float f[4], __nv_bfloat16 h[4], __nv_bfloat16 l[4])
{
#pragma unroll
    for (int i = 0; i < 4; i++) {
        h[i] = __float2bfloat16(f[i]);
        l[i] = __float2bfloat16(f[i] - __bfloat162float(h[i]));
    }
}
__device__ __forceinline__ void split_store2(float v0, float v1,
                                             __nv_bfloat16* dh, __nv_bfloat16* dl)
{
    __nv_bfloat16 h0 = __float2bfloat16(v0), h1 = __float2bfloat16(v1);
    __nv_bfloat16 l0 = __float2bfloat16(v0 - __bfloat162float(h0));
    __nv_bfloat16 l1 = __float2bfloat16(v1 - __bfloat162float(h1));
    __nv_bfloat162 H; H.x = h0; H.y = h1;
    __nv_bfloat162 L; L.x = l0; L.y = l1;
    *(__nv_bfloat162*)dh = H;
    *(__nv_bfloat162*)dl = L;
}
__device__ __forceinline__ void split_store2_h(float v0, float v1,
                                               __half* dh, __half* dl)
{
    __half h0 = __float2half_rn(v0), h1 = __float2half_rn(v1);
    __half l0 = __float2half_rn(v0 - __half2float(h0));
    __half l1 = __float2half_rn(v1 - __half2float(h1));
    __half2 H; H.x = h0; H.y = h1;
    __half2 L; L.x = l0; L.y = l1;
    *(__half2*)dh = H;
    *(__half2*)dl = L;
}

// ---------------- split-bf16 MMA machinery (R8-proven, EXACT) ----------------
// Stage layout (64KB/stage, 2 stages = 128KB):
//   +0      A_hi 128x64 (128B swizzled rows)
//   +16384  A_lo
//   +32768  B_hi
//   +49152  B_lo
#define STG 65536
#define MMA_SMEM_BYTES (2 * STG)

__device__ __forceinline__ void stage_load(
    const __nv_bfloat16* __restrict__ Ahi, const __nv_bfloat16* __restrict__ Alo,
    size_t aStr,
    const __nv_bfloat16* __restrict__ Bhi, const __nv_bfloat16* __restrict__ Blo,
    size_t bStr, int kt, uint32_t stageU32, int t)
{
#pragma unroll
    for (int i = 0; i < 4; i++) {
        const int id = t + i * 256;
        const int row = id >> 3, c16 = id & 7;
        const uint32_t doff = SWZ((uint32_t)(row * 128 + c16 * 16));
        const size_t so = (size_t)row * aStr + kt + c16 * 8;
        cp16(stageU32 + doff,          Ahi + so);
        cp16(stageU32 + 16384 + doff,  Alo + so);
        const size_t sb = (size_t)row * bStr + kt + c16 * 8;
        cp16(stageU32 + 32768 + doff,  Bhi + sb);
        cp16(stageU32 + 49152 + doff,  Blo + sb);
    }
}

__device__ __forceinline__ void stage_compute(uint32_t stageU32, int wid, int lane,
                                              float acc[4][4][4])
{
    const int warp_row = wid >> 2;
    const int warp_col = wid & 3;
    const int lrow = lane & 15;
    const int chalf = (lane >= 16) ? 16 : 0;

#pragma unroll
    for (int ks = 0; ks < 4; ks++) {
        const uint32_t bcol = ks * 32 + chalf;
        uint32_t ahi[4][4], alo[4][4];
#pragma unroll
        for (int mi = 0; mi < 4; mi++) {
            const uint32_t off = SWZ((uint32_t)((warp_row * 64 + mi * 16 + lrow) * 128 + bcol));
            ldsm4(ahi[mi], stageU32 + off);
            ldsm4(alo[mi], stageU32 + 16384 + off);
        }
        uint32_t bhi[2][4], blo[2][4];
#pragma unroll
        for (int nh = 0; nh < 2; nh++) {
            const uint32_t off = SWZ((uint32_t)((warp_col * 32 + nh * 16 + lrow) * 128 + bcol));
            ldsm4(bhi[nh], stageU32 + 32768 + off);
            ldsm4(blo[nh], stageU32 + 49152 + off);
        }
#pragma unroll
        for (int mi = 0; mi < 4; mi++)
#pragma unroll
            for (int ni = 0; ni < 4; ni++) {
                const int nh = ni >> 1, s = ni & 1;
                mma_bf16(acc[mi][ni], ahi[mi], bhi[nh][s], bhi[nh][s + 2]);
                mma_bf16(acc[mi][ni], alo[mi], bhi[nh][s], bhi[nh][s + 2]);
                mma_bf16(acc[mi][ni], ahi[mi], blo[nh][s], blo[nh][s + 2]);
            }
    }
}

template <int KCHUNKS>
__device__ __forceinline__ void mma_mainloop(
    const __nv_bfloat16* Ahi, const __nv_bfloat16* Alo, size_t aStr,
    const __nv_bfloat16* Bhi, const __nv_bfloat16* Blo, size_t bStr,
    uint32_t smemU32, int t, int wid, int lane, float acc[4][4][4])
{
    stage_load(Ahi, Alo, aStr, Bhi, Blo, bStr, 0, smemU32, t);
    cp_commit();
    for (int c = 0; c < KCHUNKS; c++) {
        const bool more = (c + 1) < KCHUNKS;
        if (more) {
            stage_load(Ahi, Alo, aStr, Bhi, Blo, bStr, (c + 1) * 64,
                       smemU32 + ((c + 1) & 1) * STG, t);
            cp_commit();
            asm volatile("cp.async.wait_group 1;" ::: "memory");
        } else {
            asm volatile("cp.async.wait_group 0;" ::: "memory");
        }
        __syncthreads();
        stage_compute(smemU32 + (c & 1) * STG, wid, lane, acc);
        __syncthreads();
    }
}

// ---------------- 2-pass split-fp16 variant for the out GEMM -----------------
// Stage layout (48KB/stage, 2 stages = 96KB):
//   +0      A_hi 128x64 fp16
//   +16384  A_lo
//   +32768  B (p) single fp16
#define STG_H 49152
#define OUT_SMEM_BYTES (2 * STG_H)

__device__ __forceinline__ void stage_load_h(
    const __half* __restrict__ Ahi, const __half* __restrict__ Alo, size_t aStr,
    const __half* __restrict__ B, size_t bStr, int kt, uint32_t stg, int t)
{
#pragma unroll
    for (int i = 0; i < 4; i++) {
        const int id = t + i * 256;
        const int row = id >> 3, c16 = id & 7;
        const uint32_t doff = SWZ((uint32_t)(row * 128 + c16 * 16));
        const size_t so = (size_t)row * aStr + kt + c16 * 8;
        cp16(stg + doff,          Ahi + so);
        cp16(stg + 16384 + doff,  Alo + so);
        const size_t sb = (size_t)row * bStr + kt + c16 * 8;
        cp16(stg + 32768 + doff,  B + sb);
    }
}

__device__ __forceinline__ void stage_compute_h(uint32_t stg, int wid, int lane,
                                                float acc[4][4][4])
{
    const int warp_row = wid >> 2;
    const int warp_col = wid & 3;
    const int lrow = lane & 15;
    const int chalf = (lane >= 16) ? 16 : 0;

#pragma unroll
    for (int ks = 0; ks < 4; ks++) {
        const uint32_t bcol = ks * 32 + chalf;
        uint32_t ahi[4][4], alo[4][4];
#pragma unroll
        for (int mi = 0; mi < 4; mi++) {
            const uint32_t off = SWZ((uint32_t)((warp_row * 64 + mi * 16 + lrow) * 128 + bcol));
            ldsm4(ahi[mi], stg + off);
            ldsm4(alo[mi], stg + 16384 + off);
        }
        uint32_t bp[2][4];
#pragma unroll
        for (int nh = 0; nh < 2; nh++) {
            const uint32_t off = SWZ((uint32_t)((warp_col * 32 + nh * 16 + lrow) * 128 + bcol));
            ldsm4(bp[nh], stg + 32768 + off);
        }
#pragma unroll
        for (int mi = 0; mi < 4; mi++)
#pragma unroll
            for (int ni = 0; ni < 4; ni++) {
                const int nh = ni >> 1, s = ni & 1;
                mma_f16(acc[mi][ni], ahi[mi], bp[nh][s], bp[nh][s + 2]);
                mma_f16(acc[mi][ni], alo[mi], bp[nh][s], bp[nh][s + 2]);
            }
    }
}

template <int KCHUNKS>
__device__ __forceinline__ void mma_mainloop_h(
    const __half* Ahi, const __half* Alo, size_t aStr,
    const __half* B, size_t bStr,
    uint32_t smemU32, int t, int wid, int lane, float acc[4][4][4])
{
    stage_load_h(Ahi, Alo, aStr, B, bStr, 0, smemU32, t);
    cp_commit();
    for (int c = 0; c < KCHUNKS; c++) {
        const bool more = (c + 1) < KCHUNKS;
        if (more) {
            stage_load_h(Ahi, Alo, aStr, B, bStr, (c + 1) * 64,
                         smemU32 + ((c + 1) & 1) * STG_H, t);
            cp_commit();
            asm volatile("cp.async.wait_group 1;" ::: "memory");
        } else {
            asm volatile("cp.async.wait_group 0;" ::: "memory");
        }
        __syncthreads();
        stage_compute_h(smemU32 + (c & 1) * STG_H, wid, lane, acc);
        __syncthreads();
    }
}

// ============================================================================
// transpose + split: src [b][C][N] fp32 -> dst [b][N][C] bf16 hi/lo
// ============================================================================
__global__ void __launch_bounds__(256)
transpose_split(const float* __restrict__ src,
                __nv_bfloat16* __restrict__ dhi, __nv_bfloat16* __restrict__ dlo)
{
    __shared__ float tile[32][33];
    const int b = blockIdx.z;
    const int n0 = blockIdx.x * 32, c0 = blockIdx.y * 32;
    const int tx = threadIdx.x, ty = threadIdx.y;   // (32, 8)
    const float* S = src + (size_t)b * CC * NN;
#pragma unroll
    for (int i = 0; i < 4; i++)
        tile[ty * 4 + i][tx] = S[(size_t)(c0 + ty * 4 + i) * NN + n0 + tx];
    __syncthreads();
    __nv_bfloat16* H = dhi + (size_t)b * NN * CC;
    __nv_bfloat16* L = dlo + (size_t)b * NN * CC;
#pragma unroll
    for (int i = 0; i < 4; i++) {
        const float f = tile[tx][ty * 4 + i];
        const __nv_bfloat16 h = __float2bfloat16(f);
        const __nv_bfloat16 l = __float2bfloat16(f - __bfloat162float(h));
        const size_t idx = (size_t)(n0 + ty * 4 + i) * CC + c0 + tx;
        H[idx] = h;
        L[idx] = l;
    }
}

// ============================================================================
// weight split
// ============================================================================
__global__ void __launch_bounds__(256)
weight_split(const float* __restrict__ wq, const float* __restrict__ wk,
             const float* __restrict__ wqd, const float* __restrict__ wkd,
             const float* __restrict__ wv,
             __nv_bfloat16* __restrict__ wqk_hi, __nv_bfloat16* __restrict__ wqk_lo,
             __nv_bfloat16* __restrict__ wqkd_hi, __nv_bfloat16* __restrict__ wqkd_lo,
             __nv_bfloat16* __restrict__ wv_hi, __nv_bfloat16* __restrict__ wv_lo)
{
    const int idx = blockIdx.x * 256 + threadIdx.x;
    if (idx >= 768 * 512) return;
    const int row = idx >> 9, col = idx & 511;
    const float* src;
    __nv_bfloat16 *dh, *dl;
    int drow;
    if (row < 512)      { src = wv  + (size_t)row * 512;         dh = wv_hi;   dl = wv_lo;   drow = row; }
    else if (row < 576) { src = wq  + (size_t)(row - 512) * 512; dh = wqk_hi;  dl = wqk_lo;  drow = row - 512; }
    else if (row < 640) { src = wk  + (size_t)(row - 576) * 512; dh = wqk_hi;  dl = wqk_lo;  drow = row - 576 + 64; }
    else if (row < 704) { src = wqd + (size_t)(row - 640) * 512; dh = wqkd_hi; dl = wqkd_lo; drow = row - 640; }
    else                { src = wkd + (size_t)(row - 704) * 512; dh = wqkd_hi; dl = wqkd_lo; drow = row - 704 + 64; }
    const float f = src[col];
    const __nv_bfloat16 h = __float2bfloat16(f);
    dh[(size_t)drow * 512 + col] = h;
    dl[(size_t)drow * 512 + col] = __float2bfloat16(f - __bfloat162float(h));
}

// ============================================================================
// proj qk: [n][d] = xt[n][c] . wqk[d][c]
// ============================================================================
__global__ void __launch_bounds__(256, 1)
mma_proj_qk(const __nv_bfloat16* __restrict__ xt_hi, const __nv_bfloat16* __restrict__ xt_lo,
            const __nv_bfloat16* __restrict__ w_hi,  const __nv_bfloat16* __restrict__ w_lo,
            const float* __restrict__ bias_q, const float* __restrict__ bias_k,
            __nv_bfloat16* __restrict__ Qhi, __nv_bfloat16* __restrict__ Qlo,
            __nv_bfloat16* __restrict__ Khi, __nv_bfloat16* __restrict__ Klo,
            int d_off)
{
    extern __shared__ char smem[];
    const uint32_t smemU32 = smem_to_u32(smem);
    const int t = threadIdx.x, wid = t >> 5, lane = t & 31;
    const int b = blockIdx.z;
    const int i0 = blockIdx.x * 128;

    const size_t aoff = ((size_t)b * NN + i0) * CC;
    float acc[4][4][4] = {};
    mma_mainloop<8>(xt_hi + aoff, xt_lo + aoff, CC, w_hi, w_lo, CC,
                    smemU32, t, wid, lane, acc);

    const int warp_col = wid & 3;
    const bool isK = warp_col >= 2;
    const float* bias = isK ? bias_k : bias_q;
    __nv_bfloat16* DH = isK ? Khi : Qhi;
    __nv_bfloat16* DL = isK ? Klo : Qlo;
    const int csub = isK ? 64 : 0;

    const int rbase = i0 + (wid >> 2) * 64 + (lane >> 2);
    const int cbase = warp_col * 32 + (lane & 3) * 2;
#pragma unroll
    for (int mi = 0; mi < 4; mi++)
#pragma unroll
        for (int ni = 0; ni < 4; ni++) {
            const int col = cbase + ni * 8 - csub;   // 0..63
            const float2 bi = *(const float2*)&bias[col];
            const int r0 = rbase + mi * 16;
            const size_t a0 = ((size_t)b * NN + r0) * DD + d_off + col;
            split_store2(acc[mi][ni][0] + bi.x, acc[mi][ni][1] + bi.y, DH + a0, DL + a0);
            const size_t a1 = ((size_t)b * NN + r0 + 8) * DD + d_off + col;
            split_store2(acc[mi][ni][2] + bi.x, acc[mi][ni][3] + bi.y, DH + a1, DL + a1);
        }
}

// ============================================================================
// proj v: [c][n] tile = wv[c][k] . xt[n][k]  -> fp16 hi/lo
// ============================================================================
__global__ void __launch_bounds__(256, 1)
mma_proj_v(const __nv_bfloat16* __restrict__ w_hi, const __nv_bfloat16* __restrict__ w_lo,
           const __nv_bfloat16* __restrict__ xt_hi, const __nv_bfloat16* __restrict__ xt_lo,
           const float* __restrict__ bias,
           __half* __restrict__ Vhi, __half* __restrict__ Vlo)
{
    extern __shared__ char smem[];
    const uint32_t smemU32 = smem_to_u32(smem);
    const int t = threadIdx.x, wid = t >> 5, lane = t & 31;
    const int b = blockIdx.z;
    const int n0 = blockIdx.x * 128, m0 = blockIdx.y * 128;

    const size_t boff = ((size_t)b * NN + n0) * CC;
    float acc[4][4][4] = {};
    mma_mainloop<8>(w_hi + (size_t)m0 * CC, w_lo + (size_t)m0 * CC, CC,
                    xt_hi + boff, xt_lo + boff, CC,
                    smemU32, t, wid, lane, acc);

    const int rbase = m0 + (wid >> 2) * 64 + (lane >> 2);
    const int cbase = n0 + (wid & 3) * 32 + (lane & 3) * 2;
#pragma unroll
    for (int mi = 0; mi < 4; mi++) {
        const int ch0 = rbase + mi * 16;
        const float bi0 = bias[ch0], bi1 = bias[ch0 + 8];
#pragma unroll
        for (int ni = 0; ni < 4; ni++) {
            const int cn = cbase + ni * 8;
            const size_t a0 = ((size_t)b * CC + ch0) * NN + cn;
            split_store2_h(acc[mi][ni][0] + bi0, acc[mi][ni][1] + bi0, Vhi + a0, Vlo + a0);
            const size_t a1 = ((size_t)b * CC + ch0 + 8) * NN + cn;
            split_store2_h(acc[mi][ni][2] + bi1, acc[mi][ni][3] + bi1, Vhi + a1, Vlo + a1);
        }
    }
}

// ============================================================================
// Energy: E[b][i][j] = sum_d q[i][d] k[j][d]  (3-pass bf16, unchanged)
// ============================================================================
__global__ void __launch_bounds__(256, 1)
mma_energy(const __nv_bfloat16* __restrict__ qhi, const __nv_bfloat16* __restrict__ qlo,
           const __nv_bfloat16* __restrict__ khi, const __nv_bfloat16* __restrict__ klo,
           float* __restrict__ E)
{
    extern __shared__ char smem[];
    const uint32_t smemU32 = smem_to_u32(smem);
    const int t = threadIdx.x, wid = t >> 5, lane = t & 31;
    const int b = blockIdx.z;
    const int i0 = blockIdx.y * 128, j0 = blockIdx.x * 128;

    const size_t aoff = ((size_t)b * NN + i0) * DD;
    const size_t boff = ((size_t)b * NN + j0) * DD;

    float acc[4][4][4] = {};
    mma_mainloop<2>(qhi + aoff, qlo + aoff, DD, khi + boff, klo + boff, DD,
                    smemU32, t, wid, lane, acc);

    float* Eb = E + (size_t)b * NN * NN;
    const int rbase = i0 + (wid >> 2) * 64 + (lane >> 2);
    const int cbase = j0 + (wid & 3) * 32 + (lane & 3) * 2;
#pragma unroll
    for (int mi = 0; mi < 4; mi++)
#pragma unroll
        for (int ni = 0; ni < 4; ni++) {
            const int r = rbase + mi * 16;
            const int cjj = cbase + ni * 8;
            *(float2*)&Eb[(size_t)r * NN + cjj]       = make_float2(acc[mi][ni][0], acc[mi][ni][1]);
            *(float2*)&Eb[(size_t)(r + 8) * NN + cjj] = make_float2(acc[mi][ni][2], acc[mi][ni][3]);
        }
}

// ============================================================================
// Out: out[b][c][i] = g * (sum_j v[c][j] p[i][j]) * inv[i] + x[c][i]
// 2-pass split-fp16: A = v hi/lo fp16, B = p fp16.
// ============================================================================
__global__ void __launch_bounds__(256, 1)
mma_out(const __half* __restrict__ vhi, const __half* __restrict__ vlo,
        const __half* __restrict__ p,
        const float* __restrict__ X, const float* __restrict__ gamma,
        const float* __restrict__ invs, float* __restrict__ Out)
{
    extern __shared__ char smem[];
    const uint32_t smemU32 = smem_to_u32(smem);
    const int t = threadIdx.x, wid = t >> 5, lane = t & 31;
    const int b = blockIdx.z;
    const int c0 = blockIdx.x * 128, i0 = blockIdx.y * 128;

    const size_t aoff = ((size_t)b * CC + c0) * NN;
    const size_t boff = ((size_t)b * NN + i0) * NN;

    float acc[4][4][4] = {};
    mma_mainloop_h<64>(vhi + aoff, vlo + aoff, NN, p + boff, NN,
                       smemU32, t, wid, lane, acc);

    const float g = __ldg(gamma);
    const int rbase = c0 + (wid >> 2) * 64 + (lane >> 2);
    const int cbase = i0 + (wid & 3) * 32 + (lane & 3) * 2;
    const float* ivb = invs + b * NN;
#pragma unroll
    for (int mi = 0; mi < 4; mi++)
#pragma unroll
        for (int ni = 0; ni < 4; ni++) {
            const int ch = rbase + mi * 16;
            const int ci = cbase + ni * 8;
            const float2 iv = *(const float2*)&ivb[ci];
            {
                const size_t idx = ((size_t)b * CC + ch) * NN + ci;
                const float2 xv = *(const float2*)&X[idx];
                float2 o;
                o.x = g * acc[mi][ni][0] * iv.x + xv.x;
                o.y = g * acc[mi][ni][1] * iv.y + xv.y;
                *(float2*)&Out[idx] = o;
            }
            {
                const size_t idx = ((size_t)b * CC + ch + 8) * NN + ci;
                const float2 xv = *(const float2*)&X[idx];
                float2 o;
                o.x = g * acc[mi][ni][2] * iv.x + xv.x;
                o.y = g * acc[mi][ni][3] * iv.y + xv.y;
                *(float2*)&Out[idx] = o;
            }
        }
}

// ============================================================================
// Softmax: fp32 energy row -> unnormalized exp fp16 + 1/rowsum
// ============================================================================
__global__ void __launch_bounds__(256)
softmax_rows(const float* __restrict__ E,
             __half* __restrict__ P, float* __restrict__ invs)
{
    __shared__ float red[8];
    const float4* E4 = (const float4*)E;
    const size_t base4 = (size_t)blockIdx.x * (NN / 4);
    const int tid = threadIdx.x;
    const int lane = tid & 31, wid = tid >> 5;

    float4 v[4];
#pragma unroll
    for (int u = 0; u < 4; u++) v[u] = E4[base4 + u * 256 + tid];

    float m = -1e30f;
#pragma unroll
    for (int u = 0; u < 4; u++)
        m = fmaxf(m, fmaxf(fmaxf(v[u].x, v[u].y), fmaxf(v[u].z, v[u].w)));
#pragma unroll
    for (int off = 16; off > 0; off >>= 1)
        m = fmaxf(m, __shfl_xor_sync(0xffffffffu, m, off));
    if (lane == 0) red[wid] = m;
    __syncthreads();
    m = red[0];
#pragma unroll
    for (int w = 1; w < 8; w++) m = fmaxf(m, red[w]);
    __syncthreads();

    float s = 0.f;
#pragma unroll
    for (int u = 0; u < 4; u++) {
        v[u].x = __expf(v[u].x - m); v[u].y = __expf(v[u].y - m);
        v[u].z = __expf(v[u].z - m); v[u].w = __expf(v[u].w - m);
        s += v[u].x + v[u].y + v[u].z + v[u].w;
    }
#pragma unroll
    for (int off = 16; off > 0; off >>= 1)
        s += __shfl_xor_sync(0xffffffffu, s, off);
    if (lane == 0) red[wid] = s;
    __syncthreads();
    s = red[0];
#pragma unroll
    for (int w = 1; w < 8; w++) s += red[w];

#pragma unroll
    for (int u = 0; u < 4; u++) {
        const size_t el = base4 * 4 + (u * 256 + tid) * 4;
        __half h[4];
        h[0] = __float2half_rn(v[u].x); h[1] = __float2half_rn(v[u].y);
        h[2] = __float2half_rn(v[u].z); h[3] = __float2half_rn(v[u].w);
        *(uint2*)&P[el] = *(uint2*)h;
    }
    if (tid == 0) invs[blockIdx.x] = 1.0f / s;
}

// ============================================================================

extern "C" void kernel_launch(void* const* d_in, const int* in_sizes, int n_in,
                              void* d_out, int out_size)
{
    const float* x     = (const float*)d_in[0];
    const float* dep   = (const float*)d_in[1];
    const float* wq    = (const float*)d_in[2];
    const float* bq    = (const float*)d_in[3];
    const float* wqd   = (const float*)d_in[4];
    const float* bqd   = (const float*)d_in[5];
    const float* wk    = (const float*)d_in[6];
    const float* bk    = (const float*)d_in[7];
    const float* wkd   = (const float*)d_in[8];
    const float* bkd   = (const float*)d_in[9];
    const float* wv    = (const float*)d_in[10];
    const float* bv    = (const float*)d_in[11];
    const float* gamma = (const float*)d_in[12];
    float* out = (float*)d_out;

    __nv_bfloat16 *xt_hi, *xt_lo, *dt_hi, *dt_lo;
    __nv_bfloat16 *wqk_hi, *wqk_lo, *wqkd_hi, *wqkd_lo, *wv_hi, *wv_lo;
    __nv_bfloat16 *qhi, *qlo, *khi, *klo;
    __half *vhi, *vlo, *p;
    float *e, *s;
    cudaGetSymbolAddress((void**)&xt_hi, g_xt_hi);
    cudaGetSymbolAddress((void**)&xt_lo, g_xt_lo);
    cudaGetSymbolAddress((void**)&dt_hi, g_dt_hi);
    cudaGetSymbolAddress((void**)&dt_lo, g_dt_lo);
    cudaGetSymbolAddress((void**)&wqk_hi, g_wqk_hi);
    cudaGetSymbolAddress((void**)&wqk_lo, g_wqk_lo);
    cudaGetSymbolAddress((void**)&wqkd_hi, g_wqkd_hi);
    cudaGetSymbolAddress((void**)&wqkd_lo, g_wqkd_lo);
    cudaGetSymbolAddress((void**)&wv_hi, g_wv_hi);
    cudaGetSymbolAddress((void**)&wv_lo, g_wv_lo);
    cudaGetSymbolAddress((void**)&qhi, g_qhi);
    cudaGetSymbolAddress((void**)&qlo, g_qlo);
    cudaGetSymbolAddress((void**)&khi, g_khi);
    cudaGetSymbolAddress((void**)&klo, g_klo);
    cudaGetSymbolAddress((void**)&vhi, g_vhi);
    cudaGetSymbolAddress((void**)&vlo, g_vlo);
    cudaGetSymbolAddress((void**)&p, g_p);
    cudaGetSymbolAddress((void**)&e, g_e);
    cudaGetSymbolAddress((void**)&s, g_s);

    cudaFuncSetAttribute(mma_proj_qk, cudaFuncAttributeMaxDynamicSharedMemorySize, MMA_SMEM_BYTES);
    cudaFuncSetAttribute(mma_proj_v,  cudaFuncAttributeMaxDynamicSharedMemorySize, MMA_SMEM_BYTES);
    cudaFuncSetAttribute(mma_energy,  cudaFuncAttributeMaxDynamicSharedMemorySize, MMA_SMEM_BYTES);
    cudaFuncSetAttribute(mma_out,     cudaFuncAttributeMaxDynamicSharedMemorySize, OUT_SMEM_BYTES);

    // input prep
    dim3 tthr(32, 8);
    transpose_split<<<dim3(NN / 32, CC / 32, BB), tthr>>>(x,   xt_hi, xt_lo);
    transpose_split<<<dim3(NN / 32, CC / 32, BB), tthr>>>(dep, dt_hi, dt_lo);
    weight_split<<<(768 * 512 + 255) / 256, 256>>>(wq, wk, wqd, wkd, wv,
                                                   wqk_hi, wqk_lo, wqkd_hi, wqkd_lo,
                                                   wv_hi, wv_lo);

    // projections
    mma_proj_qk<<<dim3(NN / 128, 1, BB), 256, MMA_SMEM_BYTES>>>(
        xt_hi, xt_lo, wqk_hi, wqk_lo, bq, bk, qhi, qlo, khi, klo, 0);
    mma_proj_qk<<<dim3(NN / 128, 1, BB), 256, MMA_SMEM_BYTES>>>(
        dt_hi, dt_lo, wqkd_hi, wqkd_lo, bqd, bkd, qhi, qlo, khi, klo, CQ);
    mma_proj_v<<<dim3(NN / 128, CC / 128, BB), 256, MMA_SMEM_BYTES>>>(
        wv_hi, wv_lo, xt_hi, xt_lo, bv, vhi, vlo);

    // energy
    mma_energy<<<dim3(NN / 128, NN / 128, BB), 256, MMA_SMEM_BYTES>>>(qhi, qlo, khi, klo, e);

    // softmax -> fp16 exp + 1/rowsum
    softmax_rows<<<BB * NN, 256>>>(e, p, s);

    // out (2-pass fp16)
    mma_out<<<dim3(CC / 128, NN / 128, BB), 256, OUT_SMEM_BYTES>>>(vhi, vlo, p, x, gamma, s, out);
}

// round 11
// speedup vs baseline: 2.5379x; 1.3977x over previous
#include <cuda_runtime.h>
#include <cuda_bf16.h>
#include <cuda_fp16.h>
#include <cstdint>

#define BB 4
#define CC 512
#define CQ 64
#define DD 128   // 2*CQ
#define NN 4096  // H*W

// ---------------- scratch (device globals; no allocations allowed) ----------
__device__ __align__(256) __nv_bfloat16 g_xt_hi[BB * NN * CC];  // x^T [b][n][c]
__device__ __align__(256) __nv_bfloat16 g_xt_lo[BB * NN * CC];
__device__ __align__(256) __nv_bfloat16 g_dt_hi[BB * NN * CC];  // dep^T
__device__ __align__(256) __nv_bfloat16 g_dt_lo[BB * NN * CC];
__device__ __align__(256) __nv_bfloat16 g_wqk_hi[DD * CC];      // wq rows 0-63, wk 64-127
__device__ __align__(256) __nv_bfloat16 g_wqk_lo[DD * CC];
__device__ __align__(256) __nv_bfloat16 g_wqkd_hi[DD * CC];
__device__ __align__(256) __nv_bfloat16 g_wqkd_lo[DD * CC];
__device__ __align__(256) __nv_bfloat16 g_wv_hi[CC * CC];
__device__ __align__(256) __nv_bfloat16 g_wv_lo[CC * CC];
__device__ __align__(256) __half g_qhi[BB * NN * DD];           // [b][i][d] fp16 hi/lo
__device__ __align__(256) __half g_qlo[BB * NN * DD];
__device__ __align__(256) __half g_k[BB * NN * DD];             // [b][j][d] fp16 single
__device__ __align__(256) __half g_v[BB * CC * NN];             // [b][c][n] fp16 single
__device__ __align__(256) float g_e[(size_t)BB * NN * NN];
__device__ __align__(256) __half g_p[(size_t)BB * NN * NN];     // exp, fp16 single
__device__ __align__(256) float g_s[BB * NN];

// ---------------- low-level helpers -----------------------------------------
__device__ __forceinline__ uint32_t smem_to_u32(const void* p) {
    uint32_t a;
    asm("{ .reg .u64 t; cvta.to.shared.u64 t, %1; cvt.u32.u64 %0, t; }" : "=r"(a) : "l"(p));
    return a;
}
#define SWZ(off) ((off) ^ (((off) >> 3) & 0x70))

__device__ __forceinline__ void cp16(uint32_t dst, const void* src) {
    asm volatile("cp.async.cg.shared.global [%0], [%1], 16;" :: "r"(dst), "l"(src));
}
__device__ __forceinline__ void cp_commit() {
    asm volatile("cp.async.commit_group;" ::: "memory");
}
__device__ __forceinline__ void ldsm4(uint32_t r[4], uint32_t addr) {
    asm volatile("ldmatrix.sync.aligned.m8n8.x4.shared.b16 {%0,%1,%2,%3}, [%4];"
                 : "=r"(r[0]), "=r"(r[1]), "=r"(r[2]), "=r"(r[3]) : "r"(addr));
}
__device__ __forceinline__ void mma_bf16(float acc[4], const uint32_t a[4],
                                         uint32_t b0, uint32_t b1) {
    asm volatile("mma.sync.aligned.m16n8k16.row.col.f32.bf16.bf16.f32 "
                 "{%0,%1,%2,%3}, {%4,%5,%6,%7}, {%8,%9}, {%0,%1,%2,%3};"
                 : "+f"(acc[0]), "+f"(acc[1]), "+f"(acc[2]), "+f"(acc[3])
                 : "r"(a[0]), "r"(a[1]), "r"(a[2]), "r"(a[3]), "r"(b0), "r"(b1));
}
__device__ __forceinline__ void mma_f16(float acc[4], const uint32_t a[4],
                                        uint32_t b0, uint32_t b1) {
    asm volatile("mma.sync.aligned.m16n8k16.row.col.f32.f16.f16.f32 "
                 "{%0,%1,%2,%3}, {%4,%5,%6,%7}, {%8,%9}, {%0,%1,%2,%3};"
                 : "+f"(acc[0]), "+f"(acc[1]), "+f"(acc[2]), "+f"(acc[3])
                 : "r"(a[0]), "r"(a[1]), "r"(a[2]), "r"(a[3]), "r"(b0), "r"(b1));
}
__device__ __forceinline__ void split_store2_h(float v0, float v1,
                                               __half* dh, __half* dl)
{
    __half h0 = __float2half_rn(v0), h1 = __float2half_rn(v1);
    __half l0 = __float2half_rn(v0 - __half2float(h0));
    __half l1 = __float2half_rn(v1 - __half2float(h1));
    __half2 H; H.x = h0; H.y = h1;
    __half2 L; L.x = l0; L.y = l1;
    *(__half2*)dh = H;
    *(__half2*)dl = L;
}
__device__ __forceinline__ void store2_h(float v0, float v1, __half* d)
{
    __half2 H; H.x = __float2half_rn(v0); H.y = __float2half_rn(v1);
    *(__half2*)d = H;
}

// ---------------- 3-pass split-bf16 machinery (R8-proven, EXACT) -------------
// Stage: A_hi | A_lo | B_hi | B_lo (16KB each), 2 stages = 128KB.
#define STG 65536
#define MMA_SMEM_BYTES (2 * STG)

__device__ __forceinline__ void stage_load(
    const __nv_bfloat16* __restrict__ Ahi, const __nv_bfloat16* __restrict__ Alo,
    size_t aStr,
    const __nv_bfloat16* __restrict__ Bhi, const __nv_bfloat16* __restrict__ Blo,
    size_t bStr, int kt, uint32_t stageU32, int t)
{
#pragma unroll
    for (int i = 0; i < 4; i++) {
        const int id = t + i * 256;
        const int row = id >> 3, c16 = id & 7;
        const uint32_t doff = SWZ((uint32_t)(row * 128 + c16 * 16));
        const size_t so = (size_t)row * aStr + kt + c16 * 8;
        cp16(stageU32 + doff,          Ahi + so);
        cp16(stageU32 + 16384 + doff,  Alo + so);
        const size_t sb = (size_t)row * bStr + kt + c16 * 8;
        cp16(stageU32 + 32768 + doff,  Bhi + sb);
        cp16(stageU32 + 49152 + doff,  Blo + sb);
    }
}

__device__ __forceinline__ void stage_compute(uint32_t stageU32, int wid, int lane,
                                              float acc[4][4][4])
{
    const int warp_row = wid >> 2;
    const int warp_col = wid & 3;
    const int lrow = lane & 15;
    const int chalf = (lane >= 16) ? 16 : 0;

#pragma unroll
    for (int ks = 0; ks < 4; ks++) {
        const uint32_t bcol = ks * 32 + chalf;
        uint32_t ahi[4][4], alo[4][4];
#pragma unroll
        for (int mi = 0; mi < 4; mi++) {
            const uint32_t off = SWZ((uint32_t)((warp_row * 64 + mi * 16 + lrow) * 128 + bcol));
            ldsm4(ahi[mi], stageU32 + off);
            ldsm4(alo[mi], stageU32 + 16384 + off);
        }
        uint32_t bhi[2][4], blo[2][4];
#pragma unroll
        for (int nh = 0; nh < 2; nh++) {
            const uint32_t off = SWZ((uint32_t)((warp_col * 32 + nh * 16 + lrow) * 128 + bcol));
            ldsm4(bhi[nh], stageU32 + 32768 + off);
            ldsm4(blo[nh], stageU32 + 49152 + off);
        }
#pragma unroll
        for (int mi = 0; mi < 4; mi++)
#pragma unroll
            for (int ni = 0; ni < 4; ni++) {
                const int nh = ni >> 1, s = ni & 1;
                mma_bf16(acc[mi][ni], ahi[mi], bhi[nh][s], bhi[nh][s + 2]);
                mma_bf16(acc[mi][ni], alo[mi], bhi[nh][s], bhi[nh][s + 2]);
                mma_bf16(acc[mi][ni], ahi[mi], blo[nh][s], blo[nh][s + 2]);
            }
    }
}

template <int KCHUNKS>
__device__ __forceinline__ void mma_mainloop(
    const __nv_bfloat16* Ahi, const __nv_bfloat16* Alo, size_t aStr,
    const __nv_bfloat16* Bhi, const __nv_bfloat16* Blo, size_t bStr,
    uint32_t smemU32, int t, int wid, int lane, float acc[4][4][4])
{
    stage_load(Ahi, Alo, aStr, Bhi, Blo, bStr, 0, smemU32, t);
    cp_commit();
    for (int c = 0; c < KCHUNKS; c++) {
        const bool more = (c + 1) < KCHUNKS;
        if (more) {
            stage_load(Ahi, Alo, aStr, Bhi, Blo, bStr, (c + 1) * 64,
                       smemU32 + ((c + 1) & 1) * STG, t);
            cp_commit();
            asm volatile("cp.async.wait_group 1;" ::: "memory");
        } else {
            asm volatile("cp.async.wait_group 0;" ::: "memory");
        }
        __syncthreads();
        stage_compute(smemU32 + (c & 1) * STG, wid, lane, acc);
        __syncthreads();
    }
}

// ---------------- 2-pass split-fp16 (R10-proven, EXACT): A hi/lo, B single ---
// Stage: A_hi | A_lo | B (16KB each) = 48KB, 2 stages = 96KB.
#define STG_H 49152
#define H2_SMEM_BYTES (2 * STG_H)

__device__ __forceinline__ void stage_load_h(
    const __half* __restrict__ Ahi, const __half* __restrict__ Alo, size_t aStr,
    const __half* __restrict__ B, size_t bStr, int kt, uint32_t stg, int t)
{
#pragma unroll
    for (int i = 0; i < 4; i++) {
        const int id = t + i * 256;
        const int row = id >> 3, c16 = id & 7;
        const uint32_t doff = SWZ((uint32_t)(row * 128 + c16 * 16));
        const size_t so = (size_t)row * aStr + kt + c16 * 8;
        cp16(stg + doff,          Ahi + so);
        cp16(stg + 16384 + doff,  Alo + so);
        const size_t sb = (size_t)row * bStr + kt + c16 * 8;
        cp16(stg + 32768 + doff,  B + sb);
    }
}

__device__ __forceinline__ void stage_compute_h(uint32_t stg, int wid, int lane,
                                                float acc[4][4][4])
{
    const int warp_row = wid >> 2;
    const int warp_col = wid & 3;
    const int lrow = lane & 15;
    const int chalf = (lane >= 16) ? 16 : 0;

#pragma unroll
    for (int ks = 0; ks < 4; ks++) {
        const uint32_t bcol = ks * 32 + chalf;
        uint32_t ahi[4][4], alo[4][4];
#pragma unroll
        for (int mi = 0; mi < 4; mi++) {
            const uint32_t off = SWZ((uint32_t)((warp_row * 64 + mi * 16 + lrow) * 128 + bcol));
            ldsm4(ahi[mi], stg + off);
            ldsm4(alo[mi], stg + 16384 + off);
        }
        uint32_t bp[2][4];
#pragma unroll
        for (int nh = 0; nh < 2; nh++) {
            const uint32_t off = SWZ((uint32_t)((warp_col * 32 + nh * 16 + lrow) * 128 + bcol));
            ldsm4(bp[nh], stg + 32768 + off);
        }
#pragma unroll
        for (int mi = 0; mi < 4; mi++)
#pragma unroll
            for (int ni = 0; ni < 4; ni++) {
                const int nh = ni >> 1, s = ni & 1;
                mma_f16(acc[mi][ni], ahi[mi], bp[nh][s], bp[nh][s + 2]);
                mma_f16(acc[mi][ni], alo[mi], bp[nh][s], bp[nh][s + 2]);
            }
    }
}

template <int KCHUNKS>
__device__ __forceinline__ void mma_mainloop_h(
    const __half* Ahi, const __half* Alo, size_t aStr,
    const __half* B, size_t bStr,
    uint32_t smemU32, int t, int wid, int lane, float acc[4][4][4])
{
    stage_load_h(Ahi, Alo, aStr, B, bStr, 0, smemU32, t);
    cp_commit();
    for (int c = 0; c < KCHUNKS; c++) {
        const bool more = (c + 1) < KCHUNKS;
        if (more) {
            stage_load_h(Ahi, Alo, aStr, B, bStr, (c + 1) * 64,
                         smemU32 + ((c + 1) & 1) * STG_H, t);
            cp_commit();
            asm volatile("cp.async.wait_group 1;" ::: "memory");
        } else {
            asm volatile("cp.async.wait_group 0;" ::: "memory");
        }
        __syncthreads();
        stage_compute_h(smemU32 + (c & 1) * STG_H, wid, lane, acc);
        __syncthreads();
    }
}

// ---------------- 1-pass fp16 (same skeleton): A single, B single ------------
// Stage: A | B (16KB each) = 32KB, 2 stages = 64KB.
#define STG_1 32768
#define H1_SMEM_BYTES (2 * STG_1)

__device__ __forceinline__ void stage_load_1(
    const __half* __restrict__ A, size_t aStr,
    const __half* __restrict__ B, size_t bStr, int kt, uint32_t stg, int t)
{
#pragma unroll
    for (int i = 0; i < 4; i++) {
        const int id = t + i * 256;
        const int row = id >> 3, c16 = id & 7;
        const uint32_t doff = SWZ((uint32_t)(row * 128 + c16 * 16));
        cp16(stg + doff,          A + (size_t)row * aStr + kt + c16 * 8);
        cp16(stg + 16384 + doff,  B + (size_t)row * bStr + kt + c16 * 8);
    }
}

__device__ __forceinline__ void stage_compute_1(uint32_t stg, int wid, int lane,
                                                float acc[4][4][4])
{
    const int warp_row = wid >> 2;
    const int warp_col = wid & 3;
    const int lrow = lane & 15;
    const int chalf = (lane >= 16) ? 16 : 0;

#pragma unroll
    for (int ks = 0; ks < 4; ks++) {
        const uint32_t bcol = ks * 32 + chalf;
        uint32_t a[4][4];
#pragma unroll
        for (int mi = 0; mi < 4; mi++) {
            const uint32_t off = SWZ((uint32_t)((warp_row * 64 + mi * 16 + lrow) * 128 + bcol));
            ldsm4(a[mi], stg + off);
        }
        uint32_t bp[2][4];
#pragma unroll
        for (int nh = 0; nh < 2; nh++) {
            const uint32_t off = SWZ((uint32_t)((warp_col * 32 + nh * 16 + lrow) * 128 + bcol));
            ldsm4(bp[nh], stg + 16384 + off);
        }
#pragma unroll
        for (int mi = 0; mi < 4; mi++)
#pragma unroll
            for (int ni = 0; ni < 4; ni++) {
                const int nh = ni >> 1, s = ni & 1;
                mma_f16(acc[mi][ni], a[mi], bp[nh][s], bp[nh][s + 2]);
            }
    }
}

template <int KCHUNKS>
__device__ __forceinline__ void mma_mainloop_1(
    const __half* A, size_t aStr, const __half* B, size_t bStr,
    uint32_t smemU32, int t, int wid, int lane, float acc[4][4][4])
{
    stage_load_1(A, aStr, B, bStr, 0, smemU32, t);
    cp_commit();
    for (int c = 0; c < KCHUNKS; c++) {
        const bool more = (c + 1) < KCHUNKS;
        if (more) {
            stage_load_1(A, aStr, B, bStr, (c + 1) * 64,
                         smemU32 + ((c + 1) & 1) * STG_1, t);
            cp_commit();
            asm volatile("cp.async.wait_group 1;" ::: "memory");
        } else {
            asm volatile("cp.async.wait_group 0;" ::: "memory");
        }
        __syncthreads();
        stage_compute_1(smemU32 + (c & 1) * STG_1, wid, lane, acc);
        __syncthreads();
    }
}

// ============================================================================
// transpose + split: src [b][C][N] fp32 -> dst [b][N][C] bf16 hi/lo
// ============================================================================
__global__ void __launch_bounds__(256)
transpose_split(const float* __restrict__ src,
                __nv_bfloat16* __restrict__ dhi, __nv_bfloat16* __restrict__ dlo)
{
    __shared__ float tile[32][33];
    const int b = blockIdx.z;
    const int n0 = blockIdx.x * 32, c0 = blockIdx.y * 32;
    const int tx = threadIdx.x, ty = threadIdx.y;   // (32, 8)
    const float* S = src + (size_t)b * CC * NN;
#pragma unroll
    for (int i = 0; i < 4; i++)
        tile[ty * 4 + i][tx] = S[(size_t)(c0 + ty * 4 + i) * NN + n0 + tx];
    __syncthreads();
    __nv_bfloat16* H = dhi + (size_t)b * NN * CC;
    __nv_bfloat16* L = dlo + (size_t)b * NN * CC;
#pragma unroll
    for (int i = 0; i < 4; i++) {
        const float f = tile[tx][ty * 4 + i];
        const __nv_bfloat16 h = __float2bfloat16(f);
        const __nv_bfloat16 l = __float2bfloat16(f - __bfloat162float(h));
        const size_t idx = (size_t)(n0 + ty * 4 + i) * CC + c0 + tx;
        H[idx] = h;
        L[idx] = l;
    }
}

// ============================================================================
// weight split
// ============================================================================
__global__ void __launch_bounds__(256)
weight_split(const float* __restrict__ wq, const float* __restrict__ wk,
             const float* __restrict__ wqd, const float* __restrict__ wkd,
             const float* __restrict__ wv,
             __nv_bfloat16* __restrict__ wqk_hi, __nv_bfloat16* __restrict__ wqk_lo,
             __nv_bfloat16* __restrict__ wqkd_hi, __nv_bfloat16* __restrict__ wqkd_lo,
             __nv_bfloat16* __restrict__ wv_hi, __nv_bfloat16* __restrict__ wv_lo)
{
    const int idx = blockIdx.x * 256 + threadIdx.x;
    if (idx >= 768 * 512) return;
    const int row = idx >> 9, col = idx & 511;
    const float* src;
    __nv_bfloat16 *dh, *dl;
    int drow;
    if (row < 512)      { src = wv  + (size_t)row * 512;         dh = wv_hi;   dl = wv_lo;   drow = row; }
    else if (row < 576) { src = wq  + (size_t)(row - 512) * 512; dh = wqk_hi;  dl = wqk_lo;  drow = row - 512; }
    else if (row < 640) { src = wk  + (size_t)(row - 576) * 512; dh = wqk_hi;  dl = wqk_lo;  drow = row - 576 + 64; }
    else if (row < 704) { src = wqd + (size_t)(row - 640) * 512; dh = wqkd_hi; dl = wqkd_lo; drow = row - 640; }
    else                { src = wkd + (size_t)(row - 704) * 512; dh = wqkd_hi; dl = wqkd_lo; drow = row - 704 + 64; }
    const float f = src[col];
    const __nv_bfloat16 h = __float2bfloat16(f);
    dh[(size_t)drow * 512 + col] = h;
    dl[(size_t)drow * 512 + col] = __float2bfloat16(f - __bfloat162float(h));
}

// ============================================================================
// proj qk: [n][d] = xt[n][c] . wqk[d][c]; q -> fp16 hi/lo, k -> fp16 single
// ============================================================================
__global__ void __launch_bounds__(256, 1)
mma_proj_qk(const __nv_bfloat16* __restrict__ xt_hi, const __nv_bfloat16* __restrict__ xt_lo,
            const __nv_bfloat16* __restrict__ w_hi,  const __nv_bfloat16* __restrict__ w_lo,
            const float* __restrict__ bias_q, const float* __restrict__ bias_k,
            __half* __restrict__ Qhi, __half* __restrict__ Qlo,
            __half* __restrict__ K,
            int d_off)
{
    extern __shared__ char smem[];
    const uint32_t smemU32 = smem_to_u32(smem);
    const int t = threadIdx.x, wid = t >> 5, lane = t & 31;
    const int b = blockIdx.z;
    const int i0 = blockIdx.x * 128;

    const size_t aoff = ((size_t)b * NN + i0) * CC;
    float acc[4][4][4] = {};
    mma_mainloop<8>(xt_hi + aoff, xt_lo + aoff, CC, w_hi, w_lo, CC,
                    smemU32, t, wid, lane, acc);

    const int warp_col = wid & 3;
    const bool isK = warp_col >= 2;
    const float* bias = isK ? bias_k : bias_q;
    const int csub = isK ? 64 : 0;

    const int rbase = i0 + (wid >> 2) * 64 + (lane >> 2);
    const int cbase = warp_col * 32 + (lane & 3) * 2;
#pragma unroll
    for (int mi = 0; mi < 4; mi++)
#pragma unroll
        for (int ni = 0; ni < 4; ni++) {
            const int col = cbase + ni * 8 - csub;   // 0..63
            const float2 bi = *(const float2*)&bias[col];
            const int r0 = rbase + mi * 16;
            const size_t a0 = ((size_t)b * NN + r0) * DD + d_off + col;
            const size_t a1 = ((size_t)b * NN + r0 + 8) * DD + d_off + col;
            if (!isK) {
                split_store2_h(acc[mi][ni][0] + bi.x, acc[mi][ni][1] + bi.y, Qhi + a0, Qlo + a0);
                split_store2_h(acc[mi][ni][2] + bi.x, acc[mi][ni][3] + bi.y, Qhi + a1, Qlo + a1);
            } else {
                store2_h(acc[mi][ni][0] + bi.x, acc[mi][ni][1] + bi.y, K + a0);
                store2_h(acc[mi][ni][2] + bi.x, acc[mi][ni][3] + bi.y, K + a1);
            }
        }
}

// ============================================================================
// proj v: [c][n] tile = wv[c][k] . xt[n][k]  -> fp16 single
// ============================================================================
__global__ void __launch_bounds__(256, 1)
mma_proj_v(const __nv_bfloat16* __restrict__ w_hi, const __nv_bfloat16* __restrict__ w_lo,
           const __nv_bfloat16* __restrict__ xt_hi, const __nv_bfloat16* __restrict__ xt_lo,
           const float* __restrict__ bias,
           __half* __restrict__ V)
{
    extern __shared__ char smem[];
    const uint32_t smemU32 = smem_to_u32(smem);
    const int t = threadIdx.x, wid = t >> 5, lane = t & 31;
    const int b = blockIdx.z;
    const int n0 = blockIdx.x * 128, m0 = blockIdx.y * 128;

    const size_t boff = ((size_t)b * NN + n0) * CC;
    float acc[4][4][4] = {};
    mma_mainloop<8>(w_hi + (size_t)m0 * CC, w_lo + (size_t)m0 * CC, CC,
                    xt_hi + boff, xt_lo + boff, CC,
                    smemU32, t, wid, lane, acc);

    const int rbase = m0 + (wid >> 2) * 64 + (lane >> 2);
    const int cbase = n0 + (wid & 3) * 32 + (lane & 3) * 2;
#pragma unroll
    for (int mi = 0; mi < 4; mi++) {
        const int ch0 = rbase + mi * 16;
        const float bi0 = bias[ch0], bi1 = bias[ch0 + 8];
#pragma unroll
        for (int ni = 0; ni < 4; ni++) {
            const int cn = cbase + ni * 8;
            store2_h(acc[mi][ni][0] + bi0, acc[mi][ni][1] + bi0,
                     V + ((size_t)b * CC + ch0) * NN + cn);
            store2_h(acc[mi][ni][2] + bi1, acc[mi][ni][3] + bi1,
                     V + ((size_t)b * CC + ch0 + 8) * NN + cn);
        }
    }
}

// ============================================================================
// Energy: E[b][i][j] = sum_d q[i][d] k[j][d]  (2-pass fp16: q hi/lo, k single)
// ============================================================================
__global__ void __launch_bounds__(256, 1)
mma_energy(const __half* __restrict__ qhi, const __half* __restrict__ qlo,
           const __half* __restrict__ k,
           float* __restrict__ E)
{
    extern __shared__ char smem[];
    const uint32_t smemU32 = smem_to_u32(smem);
    const int t = threadIdx.x, wid = t >> 5, lane = t & 31;
    const int b = blockIdx.z;
    const int i0 = blockIdx.y * 128, j0 = blockIdx.x * 128;

    const size_t aoff = ((size_t)b * NN + i0) * DD;
    const size_t boff = ((size_t)b * NN + j0) * DD;

    float acc[4][4][4] = {};
    mma_mainloop_h<2>(qhi + aoff, qlo + aoff, DD, k + boff, DD,
                      smemU32, t, wid, lane, acc);

    float* Eb = E + (size_t)b * NN * NN;
    const int rbase = i0 + (wid >> 2) * 64 + (lane >> 2);
    const int cbase = j0 + (wid & 3) * 32 + (lane & 3) * 2;
#pragma unroll
    for (int mi = 0; mi < 4; mi++)
#pragma unroll
        for (int ni = 0; ni < 4; ni++) {
            const int r = rbase + mi * 16;
            const int cjj = cbase + ni * 8;
            *(float2*)&Eb[(size_t)r * NN + cjj]       = make_float2(acc[mi][ni][0], acc[mi][ni][1]);
            *(float2*)&Eb[(size_t)(r + 8) * NN + cjj] = make_float2(acc[mi][ni][2], acc[mi][ni][3]);
        }
}

// ============================================================================
// Out: out[b][c][i] = g * (sum_j v[c][j] p[i][j]) * inv[i] + x[c][i]
// 1-pass fp16: A = v single, B = p single.
// ============================================================================
__global__ void __launch_bounds__(256, 1)
mma_out(const __half* __restrict__ v, const __half* __restrict__ p,
        const float* __restrict__ X, const float* __restrict__ gamma,
        const float* __restrict__ invs, float* __restrict__ Out)
{
    extern __shared__ char smem[];
    const uint32_t smemU32 = smem_to_u32(smem);
    const int t = threadIdx.x, wid = t >> 5, lane = t & 31;
    const int b = blockIdx.z;
    const int c0 = blockIdx.x * 128, i0 = blockIdx.y * 128;

    const size_t aoff = ((size_t)b * CC + c0) * NN;
    const size_t boff = ((size_t)b * NN + i0) * NN;

    float acc[4][4][4] = {};
    mma_mainloop_1<64>(v + aoff, NN, p + boff, NN, smemU32, t, wid, lane, acc);

    const float g = __ldg(gamma);
    const int rbase = c0 + (wid >> 2) * 64 + (lane >> 2);
    const int cbase = i0 + (wid & 3) * 32 + (lane & 3) * 2;
    const float* ivb = invs + b * NN;
#pragma unroll
    for (int mi = 0; mi < 4; mi++)
#pragma unroll
        for (int ni = 0; ni < 4; ni++) {
            const int ch = rbase + mi * 16;
            const int ci = cbase + ni * 8;
            const float2 iv = *(const float2*)&ivb[ci];
            {
                const size_t idx = ((size_t)b * CC + ch) * NN + ci;
                const float2 xv = *(const float2*)&X[idx];
                float2 o;
                o.x = g * acc[mi][ni][0] * iv.x + xv.x;
                o.y = g * acc[mi][ni][1] * iv.y + xv.y;
                *(float2*)&Out[idx] = o;
            }
            {
                const size_t idx = ((size_t)b * CC + ch + 8) * NN + ci;
                const float2 xv = *(const float2*)&X[idx];
                float2 o;
                o.x = g * acc[mi][ni][2] * iv.x + xv.x;
                o.y = g * acc[mi][ni][3] * iv.y + xv.y;
                *(float2*)&Out[idx] = o;
            }
        }
}

// ============================================================================
// Softmax: fp32 energy row -> unnormalized exp fp16 + 1/rowsum
// ============================================================================
__global__ void __launch_bounds__(256)
softmax_rows(const float* __restrict__ E,
             __half* __restrict__ P, float* __restrict__ invs)
{
    __shared__ float red[8];
    const float4* E4 = (const float4*)E;
    const size_t base4 = (size_t)blockIdx.x * (NN / 4);
    const int tid = threadIdx.x;
    const int lane = tid & 31, wid = tid >> 5;

    float4 v[4];
#pragma unroll
    for (int u = 0; u < 4; u++) v[u] = E4[base4 + u * 256 + tid];

    float m = -1e30f;
#pragma unroll
    for (int u = 0; u < 4; u++)
        m = fmaxf(m, fmaxf(fmaxf(v[u].x, v[u].y), fmaxf(v[u].z, v[u].w)));
#pragma unroll
    for (int off = 16; off > 0; off >>= 1)
        m = fmaxf(m, __shfl_xor_sync(0xffffffffu, m, off));
    if (lane == 0) red[wid] = m;
    __syncthreads();
    m = red[0];
#pragma unroll
    for (int w = 1; w < 8; w++) m = fmaxf(m, red[w]);
    __syncthreads();

    float s = 0.f;
#pragma unroll
    for (int u = 0; u < 4; u++) {
        v[u].x = __expf(v[u].x - m); v[u].y = __expf(v[u].y - m);
        v[u].z = __expf(v[u].z - m); v[u].w = __expf(v[u].w - m);
        s += v[u].x + v[u].y + v[u].z + v[u].w;
    }
#pragma unroll
    for (int off = 16; off > 0; off >>= 1)
        s += __shfl_xor_sync(0xffffffffu, s, off);
    if (lane == 0) red[wid] = s;
    __syncthreads();
    s = red[0];
#pragma unroll
    for (int w = 1; w < 8; w++) s += red[w];

#pragma unroll
    for (int u = 0; u < 4; u++) {
        const size_t el = base4 * 4 + (u * 256 + tid) * 4;
        __half h[4];
        h[0] = __float2half_rn(v[u].x); h[1] = __float2half_rn(v[u].y);
        h[2] = __float2half_rn(v[u].z); h[3] = __float2half_rn(v[u].w);
        *(uint2*)&P[el] = *(uint2*)h;
    }
    if (tid == 0) invs[blockIdx.x] = 1.0f / s;
}

// ============================================================================

extern "C" void kernel_launch(void* const* d_in, const int* in_sizes, int n_in,
                              void* d_out, int out_size)
{
    const float* x     = (const float*)d_in[0];
    const float* dep   = (const float*)d_in[1];
    const float* wq    = (const float*)d_in[2];
    const float* bq    = (const float*)d_in[3];
    const float* wqd   = (const float*)d_in[4];
    const float* bqd   = (const float*)d_in[5];
    const float* wk    = (const float*)d_in[6];
    const float* bk    = (const float*)d_in[7];
    const float* wkd   = (const float*)d_in[8];
    const float* bkd   = (const float*)d_in[9];
    const float* wv    = (const float*)d_in[10];
    const float* bv    = (const float*)d_in[11];
    const float* gamma = (const float*)d_in[12];
    float* out = (float*)d_out;

    __nv_bfloat16 *xt_hi, *xt_lo, *dt_hi, *dt_lo;
    __nv_bfloat16 *wqk_hi, *wqk_lo, *wqkd_hi, *wqkd_lo, *wv_hi, *wv_lo;
    __half *qhi, *qlo, *kk, *vv, *p;
    float *e, *s;
    cudaGetSymbolAddress((void**)&xt_hi, g_xt_hi);
    cudaGetSymbolAddress((void**)&xt_lo, g_xt_lo);
    cudaGetSymbolAddress((void**)&dt_hi, g_dt_hi);
    cudaGetSymbolAddress((void**)&dt_lo, g_dt_lo);
    cudaGetSymbolAddress((void**)&wqk_hi, g_wqk_hi);
    cudaGetSymbolAddress((void**)&wqk_lo, g_wqk_lo);
    cudaGetSymbolAddress((void**)&wqkd_hi, g_wqkd_hi);
    cudaGetSymbolAddress((void**)&wqkd_lo, g_wqkd_lo);
    cudaGetSymbolAddress((void**)&wv_hi, g_wv_hi);
    cudaGetSymbolAddress((void**)&wv_lo, g_wv_lo);
    cudaGetSymbolAddress((void**)&qhi, g_qhi);
    cudaGetSymbolAddress((void**)&qlo, g_qlo);
    cudaGetSymbolAddress((void**)&kk, g_k);
    cudaGetSymbolAddress((void**)&vv, g_v);
    cudaGetSymbolAddress((void**)&p, g_p);
    cudaGetSymbolAddress((void**)&e, g_e);
    cudaGetSymbolAddress((void**)&s, g_s);

    cudaFuncSetAttribute(mma_proj_qk, cudaFuncAttributeMaxDynamicSharedMemorySize, MMA_SMEM_BYTES);
    cudaFuncSetAttribute(mma_proj_v,  cudaFuncAttributeMaxDynamicSharedMemorySize, MMA_SMEM_BYTES);
    cudaFuncSetAttribute(mma_energy,  cudaFuncAttributeMaxDynamicSharedMemorySize, H2_SMEM_BYTES);
    cudaFuncSetAttribute(mma_out,     cudaFuncAttributeMaxDynamicSharedMemorySize, H1_SMEM_BYTES);

    // input prep
    dim3 tthr(32, 8);
    transpose_split<<<dim3(NN / 32, CC / 32, BB), tthr>>>(x,   xt_hi, xt_lo);
    transpose_split<<<dim3(NN / 32, CC / 32, BB), tthr>>>(dep, dt_hi, dt_lo);
    weight_split<<<(768 * 512 + 255) / 256, 256>>>(wq, wk, wqd, wkd, wv,
                                                   wqk_hi, wqk_lo, wqkd_hi, wqkd_lo,
                                                   wv_hi, wv_lo);

    // projections
    mma_proj_qk<<<dim3(NN / 128, 1, BB), 256, MMA_SMEM_BYTES>>>(
        xt_hi, xt_lo, wqk_hi, wqk_lo, bq, bk, qhi, qlo, kk, 0);
    mma_proj_qk<<<dim3(NN / 128, 1, BB), 256, MMA_SMEM_BYTES>>>(
        dt_hi, dt_lo, wqkd_hi, wqkd_lo, bqd, bkd, qhi, qlo, kk, CQ);
    mma_proj_v<<<dim3(NN / 128, CC / 128, BB), 256, MMA_SMEM_BYTES>>>(
        wv_hi, wv_lo, xt_hi, xt_lo, bv, vv);

    // energy (2-pass fp16)
    mma_energy<<<dim3(NN / 128, NN / 128, BB), 256, H2_SMEM_BYTES>>>(qhi, qlo, kk, e);

    // softmax -> fp16 exp + 1/rowsum
    softmax_rows<<<BB * NN, 256>>>(e, p, s);

    // out (1-pass fp16)
    mma_out<<<dim3(CC / 128, NN / 128, BB), 256, H1_SMEM_BYTES>>>(vv, p, x, gamma, s, out);
}

// round 12
// speedup vs baseline: 2.5649x; 1.0106x over previous
#include <cuda_runtime.h>
#include <cuda_bf16.h>
#include <cuda_fp16.h>
#include <cstdint>

#define BB 4
#define CC 512
#define CQ 64
#define DD 128   // 2*CQ
#define NN 4096  // H*W

// ---------------- scratch (device globals; no allocations allowed) ----------
__device__ __align__(256) __nv_bfloat16 g_xt_hi[BB * NN * CC];  // x^T [b][n][c]
__device__ __align__(256) __nv_bfloat16 g_xt_lo[BB * NN * CC];
__device__ __align__(256) __nv_bfloat16 g_dt_hi[BB * NN * CC];  // dep^T
__device__ __align__(256) __nv_bfloat16 g_dt_lo[BB * NN * CC];
__device__ __align__(256) __nv_bfloat16 g_wqk_hi[DD * CC];      // wq rows 0-63, wk 64-127
__device__ __align__(256) __nv_bfloat16 g_wqk_lo[DD * CC];
__device__ __align__(256) __nv_bfloat16 g_wqkd_hi[DD * CC];
__device__ __align__(256) __nv_bfloat16 g_wqkd_lo[DD * CC];
__device__ __align__(256) __nv_bfloat16 g_wv_hi[CC * CC];
__device__ __align__(256) __nv_bfloat16 g_wv_lo[CC * CC];
__device__ __align__(256) __half g_qhi[BB * NN * DD];           // [b][i][d] fp16 hi/lo
__device__ __align__(256) __half g_qlo[BB * NN * DD];
__device__ __align__(256) __half g_k[BB * NN * DD];             // [b][j][d] fp16 single
__device__ __align__(256) __half g_v[BB * CC * NN];             // [b][c][n] fp16 single
__device__ __align__(256) float g_e[(size_t)BB * NN * NN];
__device__ __align__(256) __half g_p[(size_t)BB * NN * NN];     // exp, fp16 single
__device__ __align__(256) float g_s[BB * NN];

// ---------------- low-level helpers -----------------------------------------
__device__ __forceinline__ uint32_t smem_to_u32(const void* p) {
    uint32_t a;
    asm("{ .reg .u64 t; cvta.to.shared.u64 t, %1; cvt.u32.u64 %0, t; }" : "=r"(a) : "l"(p));
    return a;
}
#define SWZ(off) ((off) ^ (((off) >> 3) & 0x70))

__device__ __forceinline__ void cp16(uint32_t dst, const void* src) {
    asm volatile("cp.async.cg.shared.global [%0], [%1], 16;" :: "r"(dst), "l"(src));
}
__device__ __forceinline__ void cp_commit() {
    asm volatile("cp.async.commit_group;" ::: "memory");
}
__device__ __forceinline__ void ldsm4(uint32_t r[4], uint32_t addr) {
    asm volatile("ldmatrix.sync.aligned.m8n8.x4.shared.b16 {%0,%1,%2,%3}, [%4];"
                 : "=r"(r[0]), "=r"(r[1]), "=r"(r[2]), "=r"(r[3]) : "r"(addr));
}
__device__ __forceinline__ void mma_bf16(float acc[4], const uint32_t a[4],
                                         uint32_t b0, uint32_t b1) {
    asm volatile("mma.sync.aligned.m16n8k16.row.col.f32.bf16.bf16.f32 "
                 "{%0,%1,%2,%3}, {%4,%5,%6,%7}, {%8,%9}, {%0,%1,%2,%3};"
                 : "+f"(acc[0]), "+f"(acc[1]), "+f"(acc[2]), "+f"(acc[3])
                 : "r"(a[0]), "r"(a[1]), "r"(a[2]), "r"(a[3]), "r"(b0), "r"(b1));
}
__device__ __forceinline__ void mma_f16(float acc[4], const uint32_t a[4],
                                        uint32_t b0, uint32_t b1) {
    asm volatile("mma.sync.aligned.m16n8k16.row.col.f32.f16.f16.f32 "
                 "{%0,%1,%2,%3}, {%4,%5,%6,%7}, {%8,%9}, {%0,%1,%2,%3};"
                 : "+f"(acc[0]), "+f"(acc[1]), "+f"(acc[2]), "+f"(acc[3])
                 : "r"(a[0]), "r"(a[1]), "r"(a[2]), "r"(a[3]), "r"(b0), "r"(b1));
}
__device__ __forceinline__ void split_store2_h(float v0, float v1,
                                               __half* dh, __half* dl)
{
    __half h0 = __float2half_rn(v0), h1 = __float2half_rn(v1);
    __half l0 = __float2half_rn(v0 - __half2float(h0));
    __half l1 = __float2half_rn(v1 - __half2float(h1));
    __half2 H; H.x = h0; H.y = h1;
    __half2 L; L.x = l0; L.y = l1;
    *(__half2*)dh = H;
    *(__half2*)dl = L;
}
__device__ __forceinline__ void store2_h(float v0, float v1, __half* d)
{
    __half2 H; H.x = __float2half_rn(v0); H.y = __float2half_rn(v1);
    *(__half2*)d = H;
}

// ---------------- 3-pass split-bf16 machinery (R8-proven, EXACT) -------------
#define STG 65536
#define MMA_SMEM_BYTES (2 * STG)

__device__ __forceinline__ void stage_load(
    const __nv_bfloat16* __restrict__ Ahi, const __nv_bfloat16* __restrict__ Alo,
    size_t aStr,
    const __nv_bfloat16* __restrict__ Bhi, const __nv_bfloat16* __restrict__ Blo,
    size_t bStr, int kt, uint32_t stageU32, int t)
{
#pragma unroll
    for (int i = 0; i < 4; i++) {
        const int id = t + i * 256;
        const int row = id >> 3, c16 = id & 7;
        const uint32_t doff = SWZ((uint32_t)(row * 128 + c16 * 16));
        const size_t so = (size_t)row * aStr + kt + c16 * 8;
        cp16(stageU32 + doff,          Ahi + so);
        cp16(stageU32 + 16384 + doff,  Alo + so);
        const size_t sb = (size_t)row * bStr + kt + c16 * 8;
        cp16(stageU32 + 32768 + doff,  Bhi + sb);
        cp16(stageU32 + 49152 + doff,  Blo + sb);
    }
}

__device__ __forceinline__ void stage_compute(uint32_t stageU32, int wid, int lane,
                                              float acc[4][4][4])
{
    const int warp_row = wid >> 2;
    const int warp_col = wid & 3;
    const int lrow = lane & 15;
    const int chalf = (lane >= 16) ? 16 : 0;

#pragma unroll
    for (int ks = 0; ks < 4; ks++) {
        const uint32_t bcol = ks * 32 + chalf;
        uint32_t ahi[4][4], alo[4][4];
#pragma unroll
        for (int mi = 0; mi < 4; mi++) {
            const uint32_t off = SWZ((uint32_t)((warp_row * 64 + mi * 16 + lrow) * 128 + bcol));
            ldsm4(ahi[mi], stageU32 + off);
            ldsm4(alo[mi], stageU32 + 16384 + off);
        }
        uint32_t bhi[2][4], blo[2][4];
#pragma unroll
        for (int nh = 0; nh < 2; nh++) {
            const uint32_t off = SWZ((uint32_t)((warp_col * 32 + nh * 16 + lrow) * 128 + bcol));
            ldsm4(bhi[nh], stageU32 + 32768 + off);
            ldsm4(blo[nh], stageU32 + 49152 + off);
        }
#pragma unroll
        for (int mi = 0; mi < 4; mi++)
#pragma unroll
            for (int ni = 0; ni < 4; ni++) {
                const int nh = ni >> 1, s = ni & 1;
                mma_bf16(acc[mi][ni], ahi[mi], bhi[nh][s], bhi[nh][s + 2]);
                mma_bf16(acc[mi][ni], alo[mi], bhi[nh][s], bhi[nh][s + 2]);
                mma_bf16(acc[mi][ni], ahi[mi], blo[nh][s], blo[nh][s + 2]);
            }
    }
}

template <int KCHUNKS>
__device__ __forceinline__ void mma_mainloop(
    const __nv_bfloat16* Ahi, const __nv_bfloat16* Alo, size_t aStr,
    const __nv_bfloat16* Bhi, const __nv_bfloat16* Blo, size_t bStr,
    uint32_t smemU32, int t, int wid, int lane, float acc[4][4][4])
{
    stage_load(Ahi, Alo, aStr, Bhi, Blo, bStr, 0, smemU32, t);
    cp_commit();
    for (int c = 0; c < KCHUNKS; c++) {
        const bool more = (c + 1) < KCHUNKS;
        if (more) {
            stage_load(Ahi, Alo, aStr, Bhi, Blo, bStr, (c + 1) * 64,
                       smemU32 + ((c + 1) & 1) * STG, t);
            cp_commit();
            asm volatile("cp.async.wait_group 1;" ::: "memory");
        } else {
            asm volatile("cp.async.wait_group 0;" ::: "memory");
        }
        __syncthreads();
        stage_compute(smemU32 + (c & 1) * STG, wid, lane, acc);
        __syncthreads();
    }
}

// ---------------- 2-pass split-fp16 (R10-proven, EXACT): A hi/lo, B single ---
#define STG_H 49152
#define H2_SMEM_BYTES (2 * STG_H)

__device__ __forceinline__ void stage_load_h(
    const __half* __restrict__ Ahi, const __half* __restrict__ Alo, size_t aStr,
    const __half* __restrict__ B, size_t bStr, int kt, uint32_t stg, int t)
{
#pragma unroll
    for (int i = 0; i < 4; i++) {
        const int id = t + i * 256;
        const int row = id >> 3, c16 = id & 7;
        const uint32_t doff = SWZ((uint32_t)(row * 128 + c16 * 16));
        const size_t so = (size_t)row * aStr + kt + c16 * 8;
        cp16(stg + doff,          Ahi + so);
        cp16(stg + 16384 + doff,  Alo + so);
        const size_t sb = (size_t)row * bStr + kt + c16 * 8;
        cp16(stg + 32768 + doff,  B + sb);
    }
}

__device__ __forceinline__ void stage_compute_h(uint32_t stg, int wid, int lane,
                                                float acc[4][4][4])
{
    const int warp_row = wid >> 2;
    const int warp_col = wid & 3;
    const int lrow = lane & 15;
    const int chalf = (lane >= 16) ? 16 : 0;

#pragma unroll
    for (int ks = 0; ks < 4; ks++) {
        const uint32_t bcol = ks * 32 + chalf;
        uint32_t ahi[4][4], alo[4][4];
#pragma unroll
        for (int mi = 0; mi < 4; mi++) {
            const uint32_t off = SWZ((uint32_t)((warp_row * 64 + mi * 16 + lrow) * 128 + bcol));
            ldsm4(ahi[mi], stg + off);
            ldsm4(alo[mi], stg + 16384 + off);
        }
        uint32_t bp[2][4];
#pragma unroll
        for (int nh = 0; nh < 2; nh++) {
            const uint32_t off = SWZ((uint32_t)((warp_col * 32 + nh * 16 + lrow) * 128 + bcol));
            ldsm4(bp[nh], stg + 32768 + off);
        }
#pragma unroll
        for (int mi = 0; mi < 4; mi++)
#pragma unroll
            for (int ni = 0; ni < 4; ni++) {
                const int nh = ni >> 1, s = ni & 1;
                mma_f16(acc[mi][ni], ahi[mi], bp[nh][s], bp[nh][s + 2]);
                mma_f16(acc[mi][ni], alo[mi], bp[nh][s], bp[nh][s + 2]);
            }
    }
}

template <int KCHUNKS>
__device__ __forceinline__ void mma_mainloop_h(
    const __half* Ahi, const __half* Alo, size_t aStr,
    const __half* B, size_t bStr,
    uint32_t smemU32, int t, int wid, int lane, float acc[4][4][4])
{
    stage_load_h(Ahi, Alo, aStr, B, bStr, 0, smemU32, t);
    cp_commit();
    for (int c = 0; c < KCHUNKS; c++) {
        const bool more = (c + 1) < KCHUNKS;
        if (more) {
            stage_load_h(Ahi, Alo, aStr, B, bStr, (c + 1) * 64,
                         smemU32 + ((c + 1) & 1) * STG_H, t);
            cp_commit();
            asm volatile("cp.async.wait_group 1;" ::: "memory");
        } else {
            asm volatile("cp.async.wait_group 0;" ::: "memory");
        }
        __syncthreads();
        stage_compute_h(smemU32 + (c & 1) * STG_H, wid, lane, acc);
        __syncthreads();
    }
}

// ---------------- 1-pass fp16, DOUBLE K-chunk per stage ----------------------
// Stage (64KB): A_k0 | A_k1 | B_k0 | B_k1 (16KB each). 2 stages = 128KB.
// stage_compute_1 body identical to R11, just explicit A/B smem addresses.
#define STG_1 65536
#define H1_SMEM_BYTES (2 * STG_1)

__device__ __forceinline__ void stage_load_1(
    const __half* __restrict__ A, size_t aStr,
    const __half* __restrict__ B, size_t bStr, int kt, uint32_t stg, int t)
{
#pragma unroll
    for (int i = 0; i < 4; i++) {
        const int id = t + i * 256;
        const int row = id >> 3, c16 = id & 7;
        const uint32_t doff = SWZ((uint32_t)(row * 128 + c16 * 16));
        const size_t sa = (size_t)row * aStr + kt + c16 * 8;
        const size_t sb = (size_t)row * bStr + kt + c16 * 8;
        cp16(stg + doff,          A + sa);
        cp16(stg + 16384 + doff,  A + sa + 64);
        cp16(stg + 32768 + doff,  B + sb);
        cp16(stg + 49152 + doff,  B + sb + 64);
    }
}

__device__ __forceinline__ void stage_compute_1(uint32_t stgA, uint32_t stgB,
                                                int wid, int lane,
                                                float acc[4][4][4])
{
    const int warp_row = wid >> 2;
    const int warp_col = wid & 3;
    const int lrow = lane & 15;
    const int chalf = (lane >= 16) ? 16 : 0;

#pragma unroll
    for (int ks = 0; ks < 4; ks++) {
        const uint32_t bcol = ks * 32 + chalf;
        uint32_t a[4][4];
#pragma unroll
        for (int mi = 0; mi < 4; mi++) {
            const uint32_t off = SWZ((uint32_t)((warp_row * 64 + mi * 16 + lrow) * 128 + bcol));
            ldsm4(a[mi], stgA + off);
        }
        uint32_t bp[2][4];
#pragma unroll
        for (int nh = 0; nh < 2; nh++) {
            const uint32_t off = SWZ((uint32_t)((warp_col * 32 + nh * 16 + lrow) * 128 + bcol));
            ldsm4(bp[nh], stgB + off);
        }
#pragma unroll
        for (int mi = 0; mi < 4; mi++)
#pragma unroll
            for (int ni = 0; ni < 4; ni++) {
                const int nh = ni >> 1, s = ni & 1;
                mma_f16(acc[mi][ni], a[mi], bp[nh][s], bp[nh][s + 2]);
            }
    }
}

// KCHUNKS counts 128-wide chunks now.
template <int KCHUNKS>
__device__ __forceinline__ void mma_mainloop_1(
    const __half* A, size_t aStr, const __half* B, size_t bStr,
    uint32_t smemU32, int t, int wid, int lane, float acc[4][4][4])
{
    stage_load_1(A, aStr, B, bStr, 0, smemU32, t);
    cp_commit();
    for (int c = 0; c < KCHUNKS; c++) {
        const bool more = (c + 1) < KCHUNKS;
        if (more) {
            stage_load_1(A, aStr, B, bStr, (c + 1) * 128,
                         smemU32 + ((c + 1) & 1) * STG_1, t);
            cp_commit();
            asm volatile("cp.async.wait_group 1;" ::: "memory");
        } else {
            asm volatile("cp.async.wait_group 0;" ::: "memory");
        }
        __syncthreads();
        const uint32_t stg = smemU32 + (c & 1) * STG_1;
        stage_compute_1(stg,         stg + 32768, wid, lane, acc);
        stage_compute_1(stg + 16384, stg + 49152, wid, lane, acc);
        __syncthreads();
    }
}

// ============================================================================
// transpose + split: src [b][C][N] fp32 -> dst [b][N][C] bf16 hi/lo
// ============================================================================
__global__ void __launch_bounds__(256)
transpose_split(const float* __restrict__ src,
                __nv_bfloat16* __restrict__ dhi, __nv_bfloat16* __restrict__ dlo)
{
    __shared__ float tile[32][33];
    const int b = blockIdx.z;
    const int n0 = blockIdx.x * 32, c0 = blockIdx.y * 32;
    const int tx = threadIdx.x, ty = threadIdx.y;   // (32, 8)
    const float* S = src + (size_t)b * CC * NN;
#pragma unroll
    for (int i = 0; i < 4; i++)
        tile[ty * 4 + i][tx] = S[(size_t)(c0 + ty * 4 + i) * NN + n0 + tx];
    __syncthreads();
    __nv_bfloat16* H = dhi + (size_t)b * NN * CC;
    __nv_bfloat16* L = dlo + (size_t)b * NN * CC;
#pragma unroll
    for (int i = 0; i < 4; i++) {
        const float f = tile[tx][ty * 4 + i];
        const __nv_bfloat16 h = __float2bfloat16(f);
        const __nv_bfloat16 l = __float2bfloat16(f - __bfloat162float(h));
        const size_t idx = (size_t)(n0 + ty * 4 + i) * CC + c0 + tx;
        H[idx] = h;
        L[idx] = l;
    }
}

// ============================================================================
// weight split
// ============================================================================
__global__ void __launch_bounds__(256)
weight_split(const float* __restrict__ wq, const float* __restrict__ wk,
             const float* __restrict__ wqd, const float* __restrict__ wkd,
             const float* __restrict__ wv,
             __nv_bfloat16* __restrict__ wqk_hi, __nv_bfloat16* __restrict__ wqk_lo,
             __nv_bfloat16* __restrict__ wqkd_hi, __nv_bfloat16* __restrict__ wqkd_lo,
             __nv_bfloat16* __restrict__ wv_hi, __nv_bfloat16* __restrict__ wv_lo)
{
    const int idx = blockIdx.x * 256 + threadIdx.x;
    if (idx >= 768 * 512) return;
    const int row = idx >> 9, col = idx & 511;
    const float* src;
    __nv_bfloat16 *dh, *dl;
    int drow;
    if (row < 512)      { src = wv  + (size_t)row * 512;         dh = wv_hi;   dl = wv_lo;   drow = row; }
    else if (row < 576) { src = wq  + (size_t)(row - 512) * 512; dh = wqk_hi;  dl = wqk_lo;  drow = row - 512; }
    else if (row < 640) { src = wk  + (size_t)(row - 576) * 512; dh = wqk_hi;  dl = wqk_lo;  drow = row - 576 + 64; }
    else if (row < 704) { src = wqd + (size_t)(row - 640) * 512; dh = wqkd_hi; dl = wqkd_lo; drow = row - 640; }
    else                { src = wkd + (size_t)(row - 704) * 512; dh = wqkd_hi; dl = wqkd_lo; drow = row - 704 + 64; }
    const float f = src[col];
    const __nv_bfloat16 h = __float2bfloat16(f);
    dh[(size_t)drow * 512 + col] = h;
    dl[(size_t)drow * 512 + col] = __float2bfloat16(f - __bfloat162float(h));
}

// ============================================================================
// proj qk (merged x/dep via blockIdx.y): [n][d] = in[n][c] . w[d][c]
// q -> fp16 hi/lo, k -> fp16 single
// ============================================================================
__global__ void __launch_bounds__(256, 1)
mma_proj_qk(const __nv_bfloat16* __restrict__ xt_hi, const __nv_bfloat16* __restrict__ xt_lo,
            const __nv_bfloat16* __restrict__ dt_hi, const __nv_bfloat16* __restrict__ dt_lo,
            const __nv_bfloat16* __restrict__ wqk_hi, const __nv_bfloat16* __restrict__ wqk_lo,
            const __nv_bfloat16* __restrict__ wqkd_hi, const __nv_bfloat16* __restrict__ wqkd_lo,
            const float* __restrict__ bq, const float* __restrict__ bk,
            const float* __restrict__ bqd, const float* __restrict__ bkd,
            __half* __restrict__ Qhi, __half* __restrict__ Qlo,
            __half* __restrict__ K)
{
    extern __shared__ char smem[];
    const uint32_t smemU32 = smem_to_u32(smem);
    const int t = threadIdx.x, wid = t >> 5, lane = t & 31;
    const int b = blockIdx.z;
    const int i0 = blockIdx.x * 128;
    const int sel = blockIdx.y;   // 0 = x path (d 0-63), 1 = dep path (d 64-127)

    const __nv_bfloat16* Ahi = sel ? dt_hi : xt_hi;
    const __nv_bfloat16* Alo = sel ? dt_lo : xt_lo;
    const __nv_bfloat16* Whi = sel ? wqkd_hi : wqk_hi;
    const __nv_bfloat16* Wlo = sel ? wqkd_lo : wqk_lo;
    const float* bias_q = sel ? bqd : bq;
    const float* bias_k = sel ? bkd : bk;
    const int d_off = sel ? CQ : 0;

    const size_t aoff = ((size_t)b * NN + i0) * CC;
    float acc[4][4][4] = {};
    mma_mainloop<8>(Ahi + aoff, Alo + aoff, CC, Whi, Wlo, CC,
                    smemU32, t, wid, lane, acc);

    const int warp_col = wid & 3;
    const bool isK = warp_col >= 2;
    const float* bias = isK ? bias_k : bias_q;
    const int csub = isK ? 64 : 0;

    const int rbase = i0 + (wid >> 2) * 64 + (lane >> 2);
    const int cbase = warp_col * 32 + (lane & 3) * 2;
#pragma unroll
    for (int mi = 0; mi < 4; mi++)
#pragma unroll
        for (int ni = 0; ni < 4; ni++) {
            const int col = cbase + ni * 8 - csub;   // 0..63
            const float2 bi = *(const float2*)&bias[col];
            const int r0 = rbase + mi * 16;
            const size_t a0 = ((size_t)b * NN + r0) * DD + d_off + col;
            const size_t a1 = ((size_t)b * NN + r0 + 8) * DD + d_off + col;
            if (!isK) {
                split_store2_h(acc[mi][ni][0] + bi.x, acc[mi][ni][1] + bi.y, Qhi + a0, Qlo + a0);
                split_store2_h(acc[mi][ni][2] + bi.x, acc[mi][ni][3] + bi.y, Qhi + a1, Qlo + a1);
            } else {
                store2_h(acc[mi][ni][0] + bi.x, acc[mi][ni][1] + bi.y, K + a0);
                store2_h(acc[mi][ni][2] + bi.x, acc[mi][ni][3] + bi.y, K + a1);
            }
        }
}

// ============================================================================
// proj v: [c][n] tile = wv[c][k] . xt[n][k]  -> fp16 single
// ============================================================================
__global__ void __launch_bounds__(256, 1)
mma_proj_v(const __nv_bfloat16* __restrict__ w_hi, const __nv_bfloat16* __restrict__ w_lo,
           const __nv_bfloat16* __restrict__ xt_hi, const __nv_bfloat16* __restrict__ xt_lo,
           const float* __restrict__ bias,
           __half* __restrict__ V)
{
    extern __shared__ char smem[];
    const uint32_t smemU32 = smem_to_u32(smem);
    const int t = threadIdx.x, wid = t >> 5, lane = t & 31;
    const int b = blockIdx.z;
    const int n0 = blockIdx.x * 128, m0 = blockIdx.y * 128;

    const size_t boff = ((size_t)b * NN + n0) * CC;
    float acc[4][4][4] = {};
    mma_mainloop<8>(w_hi + (size_t)m0 * CC, w_lo + (size_t)m0 * CC, CC,
                    xt_hi + boff, xt_lo + boff, CC,
                    smemU32, t, wid, lane, acc);

    const int rbase = m0 + (wid >> 2) * 64 + (lane >> 2);
    const int cbase = n0 + (wid & 3) * 32 + (lane & 3) * 2;
#pragma unroll
    for (int mi = 0; mi < 4; mi++) {
        const int ch0 = rbase + mi * 16;
        const float bi0 = bias[ch0], bi1 = bias[ch0 + 8];
#pragma unroll
        for (int ni = 0; ni < 4; ni++) {
            const int cn = cbase + ni * 8;
            store2_h(acc[mi][ni][0] + bi0, acc[mi][ni][1] + bi0,
                     V + ((size_t)b * CC + ch0) * NN + cn);
            store2_h(acc[mi][ni][2] + bi1, acc[mi][ni][3] + bi1,
                     V + ((size_t)b * CC + ch0 + 8) * NN + cn);
        }
    }
}

// ============================================================================
// Energy: E[b][i][j] = sum_d q[i][d] k[j][d]  (2-pass fp16: q hi/lo, k single)
// ============================================================================
__global__ void __launch_bounds__(256, 1)
mma_energy(const __half* __restrict__ qhi, const __half* __restrict__ qlo,
           const __half* __restrict__ k,
           float* __restrict__ E)
{
    extern __shared__ char smem[];
    const uint32_t smemU32 = smem_to_u32(smem);
    const int t = threadIdx.x, wid = t >> 5, lane = t & 31;
    const int b = blockIdx.z;
    const int i0 = blockIdx.y * 128, j0 = blockIdx.x * 128;

    const size_t aoff = ((size_t)b * NN + i0) * DD;
    const size_t boff = ((size_t)b * NN + j0) * DD;

    float acc[4][4][4] = {};
    mma_mainloop_h<2>(qhi + aoff, qlo + aoff, DD, k + boff, DD,
                      smemU32, t, wid, lane, acc);

    float* Eb = E + (size_t)b * NN * NN;
    const int rbase = i0 + (wid >> 2) * 64 + (lane >> 2);
    const int cbase = j0 + (wid & 3) * 32 + (lane & 3) * 2;
#pragma unroll
    for (int mi = 0; mi < 4; mi++)
#pragma unroll
        for (int ni = 0; ni < 4; ni++) {
            const int r = rbase + mi * 16;
            const int cjj = cbase + ni * 8;
            *(float2*)&Eb[(size_t)r * NN + cjj]       = make_float2(acc[mi][ni][0], acc[mi][ni][1]);
            *(float2*)&Eb[(size_t)(r + 8) * NN + cjj] = make_float2(acc[mi][ni][2], acc[mi][ni][3]);
        }
}

// ============================================================================
// Out: out[b][c][i] = g * (sum_j v[c][j] p[i][j]) * inv[i] + x[c][i]
// 1-pass fp16, 128-wide K chunks (32 chunks).
// ============================================================================
__global__ void __launch_bounds__(256, 1)
mma_out(const __half* __restrict__ v, const __half* __restrict__ p,
        const float* __restrict__ X, const float* __restrict__ gamma,
        const float* __restrict__ invs, float* __restrict__ Out)
{
    extern __shared__ char smem[];
    const uint32_t smemU32 = smem_to_u32(smem);
    const int t = threadIdx.x, wid = t >> 5, lane = t & 31;
    const int b = blockIdx.z;
    const int c0 = blockIdx.x * 128, i0 = blockIdx.y * 128;

    const size_t aoff = ((size_t)b * CC + c0) * NN;
    const size_t boff = ((size_t)b * NN + i0) * NN;

    float acc[4][4][4] = {};
    mma_mainloop_1<32>(v + aoff, NN, p + boff, NN, smemU32, t, wid, lane, acc);

    const float g = __ldg(gamma);
    const int rbase = c0 + (wid >> 2) * 64 + (lane >> 2);
    const int cbase = i0 + (wid & 3) * 32 + (lane & 3) * 2;
    const float* ivb = invs + b * NN;
#pragma unroll
    for (int mi = 0; mi < 4; mi++)
#pragma unroll
        for (int ni = 0; ni < 4; ni++) {
            const int ch = rbase + mi * 16;
            const int ci = cbase + ni * 8;
            const float2 iv = *(const float2*)&ivb[ci];
            {
                const size_t idx = ((size_t)b * CC + ch) * NN + ci;
                const float2 xv = *(const float2*)&X[idx];
                float2 o;
                o.x = g * acc[mi][ni][0] * iv.x + xv.x;
                o.y = g * acc[mi][ni][1] * iv.y + xv.y;
                *(float2*)&Out[idx] = o;
            }
            {
                const size_t idx = ((size_t)b * CC + ch + 8) * NN + ci;
                const float2 xv = *(const float2*)&X[idx];
                float2 o;
                o.x = g * acc[mi][ni][2] * iv.x + xv.x;
                o.y = g * acc[mi][ni][3] * iv.y + xv.y;
                *(float2*)&Out[idx] = o;
            }
        }
}

// ============================================================================
// Softmax: fp32 energy row -> unnormalized exp fp16 + 1/rowsum
// ============================================================================
__global__ void __launch_bounds__(256)
softmax_rows(const float* __restrict__ E,
             __half* __restrict__ P, float* __restrict__ invs)
{
    __shared__ float red[8];
    const float4* E4 = (const float4*)E;
    const size_t base4 = (size_t)blockIdx.x * (NN / 4);
    const int tid = threadIdx.x;
    const int lane = tid & 31, wid = tid >> 5;

    float4 v[4];
#pragma unroll
    for (int u = 0; u < 4; u++) v[u] = E4[base4 + u * 256 + tid];

    float m = -1e30f;
#pragma unroll
    for (int u = 0; u < 4; u++)
        m = fmaxf(m, fmaxf(fmaxf(v[u].x, v[u].y), fmaxf(v[u].z, v[u].w)));
#pragma unroll
    for (int off = 16; off > 0; off >>= 1)
        m = fmaxf(m, __shfl_xor_sync(0xffffffffu, m, off));
    if (lane == 0) red[wid] = m;
    __syncthreads();
    m = red[0];
#pragma unroll
    for (int w = 1; w < 8; w++) m = fmaxf(m, red[w]);
    __syncthreads();

    float s = 0.f;
#pragma unroll
    for (int u = 0; u < 4; u++) {
        v[u].x = __expf(v[u].x - m); v[u].y = __expf(v[u].y - m);
        v[u].z = __expf(v[u].z - m); v[u].w = __expf(v[u].w - m);
        s += v[u].x + v[u].y + v[u].z + v[u].w;
    }
#pragma unroll
    for (int off = 16; off > 0; off >>= 1)
        s += __shfl_xor_sync(0xffffffffu, s, off);
    if (lane == 0) red[wid] = s;
    __syncthreads();
    s = red[0];
#pragma unroll
    for (int w = 1; w < 8; w++) s += red[w];

#pragma unroll
    for (int u = 0; u < 4; u++) {
        const size_t el = base4 * 4 + (u * 256 + tid) * 4;
        __half h[4];
        h[0] = __float2half_rn(v[u].x); h[1] = __float2half_rn(v[u].y);
        h[2] = __float2half_rn(v[u].z); h[3] = __float2half_rn(v[u].w);
        *(uint2*)&P[el] = *(uint2*)h;
    }
    if (tid == 0) invs[blockIdx.x] = 1.0f / s;
}

// ============================================================================

extern "C" void kernel_launch(void* const* d_in, const int* in_sizes, int n_in,
                              void* d_out, int out_size)
{
    const float* x     = (const float*)d_in[0];
    const float* dep   = (const float*)d_in[1];
    const float* wq    = (const float*)d_in[2];
    const float* bq    = (const float*)d_in[3];
    const float* wqd   = (const float*)d_in[4];
    const float* bqd   = (const float*)d_in[5];
    const float* wk    = (const float*)d_in[6];
    const float* bk    = (const float*)d_in[7];
    const float* wkd   = (const float*)d_in[8];
    const float* bkd   = (const float*)d_in[9];
    const float* wv    = (const float*)d_in[10];
    const float* bv    = (const float*)d_in[11];
    const float* gamma = (const float*)d_in[12];
    float* out = (float*)d_out;

    __nv_bfloat16 *xt_hi, *xt_lo, *dt_hi, *dt_lo;
    __nv_bfloat16 *wqk_hi, *wqk_lo, *wqkd_hi, *wqkd_lo, *wv_hi, *wv_lo;
    __half *qhi, *qlo, *kk, *vv, *p;
    float *e, *s;
    cudaGetSymbolAddress((void**)&xt_hi, g_xt_hi);
    cudaGetSymbolAddress((void**)&xt_lo, g_xt_lo);
    cudaGetSymbolAddress((void**)&dt_hi, g_dt_hi);
    cudaGetSymbolAddress((void**)&dt_lo, g_dt_lo);
    cudaGetSymbolAddress((void**)&wqk_hi, g_wqk_hi);
    cudaGetSymbolAddress((void**)&wqk_lo, g_wqk_lo);
    cudaGetSymbolAddress((void**)&wqkd_hi, g_wqkd_hi);
    cudaGetSymbolAddress((void**)&wqkd_lo, g_wqkd_lo);
    cudaGetSymbolAddress((void**)&wv_hi, g_wv_hi);
    cudaGetSymbolAddress((void**)&wv_lo, g_wv_lo);
    cudaGetSymbolAddress((void**)&qhi, g_qhi);
    cudaGetSymbolAddress((void**)&qlo, g_qlo);
    cudaGetSymbolAddress((void**)&kk, g_k);
    cudaGetSymbolAddress((void**)&vv, g_v);
    cudaGetSymbolAddress((void**)&p, g_p);
    cudaGetSymbolAddress((void**)&e, g_e);
    cudaGetSymbolAddress((void**)&s, g_s);

    cudaFuncSetAttribute(mma_proj_qk, cudaFuncAttributeMaxDynamicSharedMemorySize, MMA_SMEM_BYTES);
    cudaFuncSetAttribute(mma_proj_v,  cudaFuncAttributeMaxDynamicSharedMemorySize, MMA_SMEM_BYTES);
    cudaFuncSetAttribute(mma_energy,  cudaFuncAttributeMaxDynamicSharedMemorySize, H2_SMEM_BYTES);
    cudaFuncSetAttribute(mma_out,     cudaFuncAttributeMaxDynamicSharedMemorySize, H1_SMEM_BYTES);

    // input prep
    dim3 tthr(32, 8);
    transpose_split<<<dim3(NN / 32, CC / 32, BB), tthr>>>(x,   xt_hi, xt_lo);
    transpose_split<<<dim3(NN / 32, CC / 32, BB), tthr>>>(dep, dt_hi, dt_lo);
    weight_split<<<(768 * 512 + 255) / 256, 256>>>(wq, wk, wqd, wkd, wv,
                                                   wqk_hi, wqk_lo, wqkd_hi, wqkd_lo,
                                                   wv_hi, wv_lo);

    // projections (q/k merged over x+dep via grid.y)
    mma_proj_qk<<<dim3(NN / 128, 2, BB), 256, MMA_SMEM_BYTES>>>(
        xt_hi, xt_lo, dt_hi, dt_lo, wqk_hi, wqk_lo, wqkd_hi, wqkd_lo,
        bq, bk, bqd, bkd, qhi, qlo, kk);
    mma_proj_v<<<dim3(NN / 128, CC / 128, BB), 256, MMA_SMEM_BYTES>>>(
        wv_hi, wv_lo, xt_hi, xt_lo, bv, vv);

    // energy (2-pass fp16)
    mma_energy<<<dim3(NN / 128, NN / 128, BB), 256, H2_SMEM_BYTES>>>(qhi, qlo, kk, e);

    // softmax -> fp16 exp + 1/rowsum
    softmax_rows<<<BB * NN, 256>>>(e, p, s);

    // out (1-pass fp16, double K-chunk)
    mma_out<<<dim3(CC / 128, NN / 128, BB), 256, H1_SMEM_BYTES>>>(vv, p, x, gamma, s, out);
}

// round 13
// speedup vs baseline: 2.7535x; 1.0735x over previous
#include <cuda_runtime.h>
#include <cuda_bf16.h>
#include <cuda_fp16.h>
#include <cstdint>

#define BB 4
#define CC 512
#define CQ 64
#define DD 128   // 2*CQ
#define NN 4096  // H*W

// ---------------- scratch (device globals; no allocations allowed) ----------
__device__ __align__(256) __nv_bfloat16 g_xt_hi[BB * NN * CC];  // x^T [b][n][c]
__device__ __align__(256) __nv_bfloat16 g_xt_lo[BB * NN * CC];
__device__ __align__(256) __nv_bfloat16 g_dt_hi[BB * NN * CC];  // dep^T
__device__ __align__(256) __nv_bfloat16 g_dt_lo[BB * NN * CC];
__device__ __align__(256) __nv_bfloat16 g_wqk_hi[DD * CC];      // wq rows 0-63, wk 64-127
__device__ __align__(256) __nv_bfloat16 g_wqk_lo[DD * CC];
__device__ __align__(256) __nv_bfloat16 g_wqkd_hi[DD * CC];
__device__ __align__(256) __nv_bfloat16 g_wqkd_lo[DD * CC];
__device__ __align__(256) __nv_bfloat16 g_wv_hi[CC * CC];
__device__ __align__(256) __nv_bfloat16 g_wv_lo[CC * CC];
__device__ __align__(256) __half g_qhi[BB * NN * DD];           // [b][i][d] fp16 hi/lo
__device__ __align__(256) __half g_qlo[BB * NN * DD];
__device__ __align__(256) __half g_k[BB * NN * DD];             // [b][j][d] fp16 single
__device__ __align__(256) __half g_v[BB * CC * NN];             // [b][c][n] fp16 single
__device__ __align__(256) float g_e[(size_t)BB * NN * NN];
__device__ __align__(256) __half g_p[(size_t)BB * NN * NN];     // exp, fp16 single
__device__ __align__(256) float g_s[BB * NN];

// ---------------- low-level helpers -----------------------------------------
__device__ __forceinline__ uint32_t smem_to_u32(const void* p) {
    uint32_t a;
    asm("{ .reg .u64 t; cvta.to.shared.u64 t, %1; cvt.u32.u64 %0, t; }" : "=r"(a) : "l"(p));
    return a;
}
#define SWZ(off) ((off) ^ (((off) >> 3) & 0x70))

__device__ __forceinline__ void cp16(uint32_t dst, const void* src) {
    asm volatile("cp.async.cg.shared.global [%0], [%1], 16;" :: "r"(dst), "l"(src));
}
__device__ __forceinline__ void cp_commit() {
    asm volatile("cp.async.commit_group;" ::: "memory");
}
__device__ __forceinline__ void ldsm4(uint32_t r[4], uint32_t addr) {
    asm volatile("ldmatrix.sync.aligned.m8n8.x4.shared.b16 {%0,%1,%2,%3}, [%4];"
                 : "=r"(r[0]), "=r"(r[1]), "=r"(r[2]), "=r"(r[3]) : "r"(addr));
}
__device__ __forceinline__ void mma_bf16(float acc[4], const uint32_t a[4],
                                         uint32_t b0, uint32_t b1) {
    asm volatile("mma.sync.aligned.m16n8k16.row.col.f32.bf16.bf16.f32 "
                 "{%0,%1,%2,%3}, {%4,%5,%6,%7}, {%8,%9}, {%0,%1,%2,%3};"
                 : "+f"(acc[0]), "+f"(acc[1]), "+f"(acc[2]), "+f"(acc[3])
                 : "r"(a[0]), "r"(a[1]), "r"(a[2]), "r"(a[3]), "r"(b0), "r"(b1));
}
__device__ __forceinline__ void mma_f16(float acc[4], const uint32_t a[4],
                                        uint32_t b0, uint32_t b1) {
    asm volatile("mma.sync.aligned.m16n8k16.row.col.f32.f16.f16.f32 "
                 "{%0,%1,%2,%3}, {%4,%5,%6,%7}, {%8,%9}, {%0,%1,%2,%3};"
                 : "+f"(acc[0]), "+f"(acc[1]), "+f"(acc[2]), "+f"(acc[3])
                 : "r"(a[0]), "r"(a[1]), "r"(a[2]), "r"(a[3]), "r"(b0), "r"(b1));
}
__device__ __forceinline__ void split_store2_h(float v0, float v1,
                                               __half* dh, __half* dl)
{
    __half h0 = __float2half_rn(v0), h1 = __float2half_rn(v1);
    __half l0 = __float2half_rn(v0 - __half2float(h0));
    __half l1 = __float2half_rn(v1 - __half2float(h1));
    __half2 H; H.x = h0; H.y = h1;
    __half2 L; L.x = l0; L.y = l1;
    *(__half2*)dh = H;
    *(__half2*)dl = L;
}
__device__ __forceinline__ void store2_h(float v0, float v1, __half* d)
{
    __half2 H; H.x = __float2half_rn(v0); H.y = __float2half_rn(v1);
    *(__half2*)d = H;
}

// ---------------- 3-pass split-bf16 machinery (R8-proven, EXACT) -------------
#define STG 65536
#define MMA_SMEM_BYTES (2 * STG)

__device__ __forceinline__ void stage_load(
    const __nv_bfloat16* __restrict__ Ahi, const __nv_bfloat16* __restrict__ Alo,
    size_t aStr,
    const __nv_bfloat16* __restrict__ Bhi, const __nv_bfloat16* __restrict__ Blo,
    size_t bStr, int kt, uint32_t stageU32, int t)
{
#pragma unroll
    for (int i = 0; i < 4; i++) {
        const int id = t + i * 256;
        const int row = id >> 3, c16 = id & 7;
        const uint32_t doff = SWZ((uint32_t)(row * 128 + c16 * 16));
        const size_t so = (size_t)row * aStr + kt + c16 * 8;
        cp16(stageU32 + doff,          Ahi + so);
        cp16(stageU32 + 16384 + doff,  Alo + so);
        const size_t sb = (size_t)row * bStr + kt + c16 * 8;
        cp16(stageU32 + 32768 + doff,  Bhi + sb);
        cp16(stageU32 + 49152 + doff,  Blo + sb);
    }
}

__device__ __forceinline__ void stage_compute(uint32_t stageU32, int wid, int lane,
                                              float acc[4][4][4])
{
    const int warp_row = wid >> 2;
    const int warp_col = wid & 3;
    const int lrow = lane & 15;
    const int chalf = (lane >= 16) ? 16 : 0;

#pragma unroll
    for (int ks = 0; ks < 4; ks++) {
        const uint32_t bcol = ks * 32 + chalf;
        uint32_t ahi[4][4], alo[4][4];
#pragma unroll
        for (int mi = 0; mi < 4; mi++) {
            const uint32_t off = SWZ((uint32_t)((warp_row * 64 + mi * 16 + lrow) * 128 + bcol));
            ldsm4(ahi[mi], stageU32 + off);
            ldsm4(alo[mi], stageU32 + 16384 + off);
        }
        uint32_t bhi[2][4], blo[2][4];
#pragma unroll
        for (int nh = 0; nh < 2; nh++) {
            const uint32_t off = SWZ((uint32_t)((warp_col * 32 + nh * 16 + lrow) * 128 + bcol));
            ldsm4(bhi[nh], stageU32 + 32768 + off);
            ldsm4(blo[nh], stageU32 + 49152 + off);
        }
#pragma unroll
        for (int mi = 0; mi < 4; mi++)
#pragma unroll
            for (int ni = 0; ni < 4; ni++) {
                const int nh = ni >> 1, s = ni & 1;
                mma_bf16(acc[mi][ni], ahi[mi], bhi[nh][s], bhi[nh][s + 2]);
                mma_bf16(acc[mi][ni], alo[mi], bhi[nh][s], bhi[nh][s + 2]);
                mma_bf16(acc[mi][ni], ahi[mi], blo[nh][s], blo[nh][s + 2]);
            }
    }
}

template <int KCHUNKS>
__device__ __forceinline__ void mma_mainloop(
    const __nv_bfloat16* Ahi, const __nv_bfloat16* Alo, size_t aStr,
    const __nv_bfloat16* Bhi, const __nv_bfloat16* Blo, size_t bStr,
    uint32_t smemU32, int t, int wid, int lane, float acc[4][4][4])
{
    stage_load(Ahi, Alo, aStr, Bhi, Blo, bStr, 0, smemU32, t);
    cp_commit();
    for (int c = 0; c < KCHUNKS; c++) {
        const bool more = (c + 1) < KCHUNKS;
        if (more) {
            stage_load(Ahi, Alo, aStr, Bhi, Blo, bStr, (c + 1) * 64,
                       smemU32 + ((c + 1) & 1) * STG, t);
            cp_commit();
            asm volatile("cp.async.wait_group 1;" ::: "memory");
        } else {
            asm volatile("cp.async.wait_group 0;" ::: "memory");
        }
        __syncthreads();
        stage_compute(smemU32 + (c & 1) * STG, wid, lane, acc);
        __syncthreads();
    }
}

// ---------------- 2-pass split-fp16 (R10-proven, EXACT): A hi/lo, B single ---
#define STG_H 49152
#define H2_SMEM_BYTES (2 * STG_H)

__device__ __forceinline__ void stage_load_h(
    const __half* __restrict__ Ahi, const __half* __restrict__ Alo, size_t aStr,
    const __half* __restrict__ B, size_t bStr, int kt, uint32_t stg, int t)
{
#pragma unroll
    for (int i = 0; i < 4; i++) {
        const int id = t + i * 256;
        const int row = id >> 3, c16 = id & 7;
        const uint32_t doff = SWZ((uint32_t)(row * 128 + c16 * 16));
        const size_t so = (size_t)row * aStr + kt + c16 * 8;
        cp16(stg + doff,          Ahi + so);
        cp16(stg + 16384 + doff,  Alo + so);
        const size_t sb = (size_t)row * bStr + kt + c16 * 8;
        cp16(stg + 32768 + doff,  B + sb);
    }
}

__device__ __forceinline__ void stage_compute_h(uint32_t stg, int wid, int lane,
                                                float acc[4][4][4])
{
    const int warp_row = wid >> 2;
    const int warp_col = wid & 3;
    const int lrow = lane & 15;
    const int chalf = (lane >= 16) ? 16 : 0;

#pragma unroll
    for (int ks = 0; ks < 4; ks++) {
        const uint32_t bcol = ks * 32 + chalf;
        uint32_t ahi[4][4], alo[4][4];
#pragma unroll
        for (int mi = 0; mi < 4; mi++) {
            const uint32_t off = SWZ((uint32_t)((warp_row * 64 + mi * 16 + lrow) * 128 + bcol));
            ldsm4(ahi[mi], stg + off);
            ldsm4(alo[mi], stg + 16384 + off);
        }
        uint32_t bp[2][4];
#pragma unroll
        for (int nh = 0; nh < 2; nh++) {
            const uint32_t off = SWZ((uint32_t)((warp_col * 32 + nh * 16 + lrow) * 128 + bcol));
            ldsm4(bp[nh], stg + 32768 + off);
        }
#pragma unroll
        for (int mi = 0; mi < 4; mi++)
#pragma unroll
            for (int ni = 0; ni < 4; ni++) {
                const int nh = ni >> 1, s = ni & 1;
                mma_f16(acc[mi][ni], ahi[mi], bp[nh][s], bp[nh][s + 2]);
                mma_f16(acc[mi][ni], alo[mi], bp[nh][s], bp[nh][s + 2]);
            }
    }
}

template <int KCHUNKS>
__device__ __forceinline__ void mma_mainloop_h(
    const __half* Ahi, const __half* Alo, size_t aStr,
    const __half* B, size_t bStr,
    uint32_t smemU32, int t, int wid, int lane, float acc[4][4][4])
{
    stage_load_h(Ahi, Alo, aStr, B, bStr, 0, smemU32, t);
    cp_commit();
    for (int c = 0; c < KCHUNKS; c++) {
        const bool more = (c + 1) < KCHUNKS;
        if (more) {
            stage_load_h(Ahi, Alo, aStr, B, bStr, (c + 1) * 64,
                         smemU32 + ((c + 1) & 1) * STG_H, t);
            cp_commit();
            asm volatile("cp.async.wait_group 1;" ::: "memory");
        } else {
            asm volatile("cp.async.wait_group 0;" ::: "memory");
        }
        __syncthreads();
        stage_compute_h(smemU32 + (c & 1) * STG_H, wid, lane, acc);
        __syncthreads();
    }
}

// ---------------- 1-pass fp16 (R11-proven): A single, B single ---------------
// Stage: A | B (16KB each) = 32KB, 2 stages = 64KB (2 CTAs/SM co-reside).
#define STG_1 32768
#define H1_SMEM_BYTES (2 * STG_1)

__device__ __forceinline__ void stage_load_1(
    const __half* __restrict__ A, size_t aStr,
    const __half* __restrict__ B, size_t bStr, int kt, uint32_t stg, int t)
{
#pragma unroll
    for (int i = 0; i < 4; i++) {
        const int id = t + i * 256;
        const int row = id >> 3, c16 = id & 7;
        const uint32_t doff = SWZ((uint32_t)(row * 128 + c16 * 16));
        cp16(stg + doff,          A + (size_t)row * aStr + kt + c16 * 8);
        cp16(stg + 16384 + doff,  B + (size_t)row * bStr + kt + c16 * 8);
    }
}

__device__ __forceinline__ void stage_compute_1(uint32_t stg, int wid, int lane,
                                                float acc[4][4][4])
{
    const int warp_row = wid >> 2;
    const int warp_col = wid & 3;
    const int lrow = lane & 15;
    const int chalf = (lane >= 16) ? 16 : 0;

#pragma unroll
    for (int ks = 0; ks < 4; ks++) {
        const uint32_t bcol = ks * 32 + chalf;
        uint32_t a[4][4];
#pragma unroll
        for (int mi = 0; mi < 4; mi++) {
            const uint32_t off = SWZ((uint32_t)((warp_row * 64 + mi * 16 + lrow) * 128 + bcol));
            ldsm4(a[mi], stg + off);
        }
        uint32_t bp[2][4];
#pragma unroll
        for (int nh = 0; nh < 2; nh++) {
            const uint32_t off = SWZ((uint32_t)((warp_col * 32 + nh * 16 + lrow) * 128 + bcol));
            ldsm4(bp[nh], stg + 16384 + off);
        }
#pragma unroll
        for (int mi = 0; mi < 4; mi++)
#pragma unroll
            for (int ni = 0; ni < 4; ni++) {
                const int nh = ni >> 1, s = ni & 1;
                mma_f16(acc[mi][ni], a[mi], bp[nh][s], bp[nh][s + 2]);
            }
    }
}

template <int KCHUNKS>
__device__ __forceinline__ void mma_mainloop_1(
    const __half* A, size_t aStr, const __half* B, size_t bStr,
    uint32_t smemU32, int t, int wid, int lane, float acc[4][4][4])
{
    stage_load_1(A, aStr, B, bStr, 0, smemU32, t);
    cp_commit();
    for (int c = 0; c < KCHUNKS; c++) {
        const bool more = (c + 1) < KCHUNKS;
        if (more) {
            stage_load_1(A, aStr, B, bStr, (c + 1) * 64,
                         smemU32 + ((c + 1) & 1) * STG_1, t);
            cp_commit();
            asm volatile("cp.async.wait_group 1;" ::: "memory");
        } else {
            asm volatile("cp.async.wait_group 0;" ::: "memory");
        }
        __syncthreads();
        stage_compute_1(smemU32 + (c & 1) * STG_1, wid, lane, acc);
        __syncthreads();
    }
}

// ============================================================================
// transpose + split: src [b][C][N] fp32 -> dst [b][N][C] bf16 hi/lo
// ============================================================================
__global__ void __launch_bounds__(256)
transpose_split(const float* __restrict__ src,
                __nv_bfloat16* __restrict__ dhi, __nv_bfloat16* __restrict__ dlo)
{
    __shared__ float tile[32][33];
    const int b = blockIdx.z;
    const int n0 = blockIdx.x * 32, c0 = blockIdx.y * 32;
    const int tx = threadIdx.x, ty = threadIdx.y;   // (32, 8)
    const float* S = src + (size_t)b * CC * NN;
#pragma unroll
    for (int i = 0; i < 4; i++)
        tile[ty * 4 + i][tx] = S[(size_t)(c0 + ty * 4 + i) * NN + n0 + tx];
    __syncthreads();
    __nv_bfloat16* H = dhi + (size_t)b * NN * CC;
    __nv_bfloat16* L = dlo + (size_t)b * NN * CC;
#pragma unroll
    for (int i = 0; i < 4; i++) {
        const float f = tile[tx][ty * 4 + i];
        const __nv_bfloat16 h = __float2bfloat16(f);
        const __nv_bfloat16 l = __float2bfloat16(f - __bfloat162float(h));
        const size_t idx = (size_t)(n0 + ty * 4 + i) * CC + c0 + tx;
        H[idx] = h;
        L[idx] = l;
    }
}

// ============================================================================
// weight split
// ============================================================================
__global__ void __launch_bounds__(256)
weight_split(const float* __restrict__ wq, const float* __restrict__ wk,
             const float* __restrict__ wqd, const float* __restrict__ wkd,
             const float* __restrict__ wv,
             __nv_bfloat16* __restrict__ wqk_hi, __nv_bfloat16* __restrict__ wqk_lo,
             __nv_bfloat16* __restrict__ wqkd_hi, __nv_bfloat16* __restrict__ wqkd_lo,
             __nv_bfloat16* __restrict__ wv_hi, __nv_bfloat16* __restrict__ wv_lo)
{
    const int idx = blockIdx.x * 256 + threadIdx.x;
    if (idx >= 768 * 512) return;
    const int row = idx >> 9, col = idx & 511;
    const float* src;
    __nv_bfloat16 *dh, *dl;
    int drow;
    if (row < 512)      { src = wv  + (size_t)row * 512;         dh = wv_hi;   dl = wv_lo;   drow = row; }
    else if (row < 576) { src = wq  + (size_t)(row - 512) * 512; dh = wqk_hi;  dl = wqk_lo;  drow = row - 512; }
    else if (row < 640) { src = wk  + (size_t)(row - 576) * 512; dh = wqk_hi;  dl = wqk_lo;  drow = row - 576 + 64; }
    else if (row < 704) { src = wqd + (size_t)(row - 640) * 512; dh = wqkd_hi; dl = wqkd_lo; drow = row - 640; }
    else                { src = wkd + (size_t)(row - 704) * 512; dh = wqkd_hi; dl = wqkd_lo; drow = row - 704 + 64; }
    const float f = src[col];
    const __nv_bfloat16 h = __float2bfloat16(f);
    dh[(size_t)drow * 512 + col] = h;
    dl[(size_t)drow * 512 + col] = __float2bfloat16(f - __bfloat162float(h));
}

// ============================================================================
// proj qk (merged x/dep via blockIdx.y): [n][d] = in[n][c] . w[d][c]
// q -> fp16 hi/lo, k -> fp16 single
// ============================================================================
__global__ void __launch_bounds__(256, 1)
mma_proj_qk(const __nv_bfloat16* __restrict__ xt_hi, const __nv_bfloat16* __restrict__ xt_lo,
            const __nv_bfloat16* __restrict__ dt_hi, const __nv_bfloat16* __restrict__ dt_lo,
            const __nv_bfloat16* __restrict__ wqk_hi, const __nv_bfloat16* __restrict__ wqk_lo,
            const __nv_bfloat16* __restrict__ wqkd_hi, const __nv_bfloat16* __restrict__ wqkd_lo,
            const float* __restrict__ bq, const float* __restrict__ bk,
            const float* __restrict__ bqd, const float* __restrict__ bkd,
            __half* __restrict__ Qhi, __half* __restrict__ Qlo,
            __half* __restrict__ K)
{
    extern __shared__ char smem[];
    const uint32_t smemU32 = smem_to_u32(smem);
    const int t = threadIdx.x, wid = t >> 5, lane = t & 31;
    const int b = blockIdx.z;
    const int i0 = blockIdx.x * 128;
    const int sel = blockIdx.y;   // 0 = x path (d 0-63), 1 = dep path (d 64-127)

    const __nv_bfloat16* Ahi = sel ? dt_hi : xt_hi;
    const __nv_bfloat16* Alo = sel ? dt_lo : xt_lo;
    const __nv_bfloat16* Whi = sel ? wqkd_hi : wqk_hi;
    const __nv_bfloat16* Wlo = sel ? wqkd_lo : wqk_lo;
    const float* bias_q = sel ? bqd : bq;
    const float* bias_k = sel ? bkd : bk;
    const int d_off = sel ? CQ : 0;

    const size_t aoff = ((size_t)b * NN + i0) * CC;
    float acc[4][4][4] = {};
    mma_mainloop<8>(Ahi + aoff, Alo + aoff, CC, Whi, Wlo, CC,
                    smemU32, t, wid, lane, acc);

    const int warp_col = wid & 3;
    const bool isK = warp_col >= 2;
    const float* bias = isK ? bias_k : bias_q;
    const int csub = isK ? 64 : 0;

    const int rbase = i0 + (wid >> 2) * 64 + (lane >> 2);
    const int cbase = warp_col * 32 + (lane & 3) * 2;
#pragma unroll
    for (int mi = 0; mi < 4; mi++)
#pragma unroll
        for (int ni = 0; ni < 4; ni++) {
            const int col = cbase + ni * 8 - csub;   // 0..63
            const float2 bi = *(const float2*)&bias[col];
            const int r0 = rbase + mi * 16;
            const size_t a0 = ((size_t)b * NN + r0) * DD + d_off + col;
            const size_t a1 = ((size_t)b * NN + r0 + 8) * DD + d_off + col;
            if (!isK) {
                split_store2_h(acc[mi][ni][0] + bi.x, acc[mi][ni][1] + bi.y, Qhi + a0, Qlo + a0);
                split_store2_h(acc[mi][ni][2] + bi.x, acc[mi][ni][3] + bi.y, Qhi + a1, Qlo + a1);
            } else {
                store2_h(acc[mi][ni][0] + bi.x, acc[mi][ni][1] + bi.y, K + a0);
                store2_h(acc[mi][ni][2] + bi.x, acc[mi][ni][3] + bi.y, K + a1);
            }
        }
}

// ============================================================================
// proj v: [c][n] tile = wv[c][k] . xt[n][k]  -> fp16 single
// ============================================================================
__global__ void __launch_bounds__(256, 1)
mma_proj_v(const __nv_bfloat16* __restrict__ w_hi, const __nv_bfloat16* __restrict__ w_lo,
           const __nv_bfloat16* __restrict__ xt_hi, const __nv_bfloat16* __restrict__ xt_lo,
           const float* __restrict__ bias,
           __half* __restrict__ V)
{
    extern __shared__ char smem[];
    const uint32_t smemU32 = smem_to_u32(smem);
    const int t = threadIdx.x, wid = t >> 5, lane = t & 31;
    const int b = blockIdx.z;
    const int n0 = blockIdx.x * 128, m0 = blockIdx.y * 128;

    const size_t boff = ((size_t)b * NN + n0) * CC;
    float acc[4][4][4] = {};
    mma_mainloop<8>(w_hi + (size_t)m0 * CC, w_lo + (size_t)m0 * CC, CC,
                    xt_hi + boff, xt_lo + boff, CC,
                    smemU32, t, wid, lane, acc);

    const int rbase = m0 + (wid >> 2) * 64 + (lane >> 2);
    const int cbase = n0 + (wid & 3) * 32 + (lane & 3) * 2;
#pragma unroll
    for (int mi = 0; mi < 4; mi++) {
        const int ch0 = rbase + mi * 16;
        const float bi0 = bias[ch0], bi1 = bias[ch0 + 8];
#pragma unroll
        for (int ni = 0; ni < 4; ni++) {
            const int cn = cbase + ni * 8;
            store2_h(acc[mi][ni][0] + bi0, acc[mi][ni][1] + bi0,
                     V + ((size_t)b * CC + ch0) * NN + cn);
            store2_h(acc[mi][ni][2] + bi1, acc[mi][ni][3] + bi1,
                     V + ((size_t)b * CC + ch0 + 8) * NN + cn);
        }
    }
}

// ============================================================================
// Energy: E[b][i][j] = sum_d q[i][d] k[j][d]  (2-pass fp16; occ 2)
// ============================================================================
__global__ void __launch_bounds__(256, 2)
mma_energy(const __half* __restrict__ qhi, const __half* __restrict__ qlo,
           const __half* __restrict__ k,
           float* __restrict__ E)
{
    extern __shared__ char smem[];
    const uint32_t smemU32 = smem_to_u32(smem);
    const int t = threadIdx.x, wid = t >> 5, lane = t & 31;
    const int b = blockIdx.z;
    const int i0 = blockIdx.y * 128, j0 = blockIdx.x * 128;

    const size_t aoff = ((size_t)b * NN + i0) * DD;
    const size_t boff = ((size_t)b * NN + j0) * DD;

    float acc[4][4][4] = {};
    mma_mainloop_h<2>(qhi + aoff, qlo + aoff, DD, k + boff, DD,
                      smemU32, t, wid, lane, acc);

    float* Eb = E + (size_t)b * NN * NN;
    const int rbase = i0 + (wid >> 2) * 64 + (lane >> 2);
    const int cbase = j0 + (wid & 3) * 32 + (lane & 3) * 2;
#pragma unroll
    for (int mi = 0; mi < 4; mi++)
#pragma unroll
        for (int ni = 0; ni < 4; ni++) {
            const int r = rbase + mi * 16;
            const int cjj = cbase + ni * 8;
            *(float2*)&Eb[(size_t)r * NN + cjj]       = make_float2(acc[mi][ni][0], acc[mi][ni][1]);
            *(float2*)&Eb[(size_t)(r + 8) * NN + cjj] = make_float2(acc[mi][ni][2], acc[mi][ni][3]);
        }
}

// ============================================================================
// Out: out[b][c][i] = g * (sum_j v[c][j] p[i][j]) * inv[i] + x[c][i]
// 1-pass fp16, 64-wide K chunks; occ 2 (64KB smem, <=128 regs).
// ============================================================================
__global__ void __launch_bounds__(256, 2)
mma_out(const __half* __restrict__ v, const __half* __restrict__ p,
        const float* __restrict__ X, const float* __restrict__ gamma,
        const float* __restrict__ invs, float* __restrict__ Out)
{
    extern __shared__ char smem[];
    const uint32_t smemU32 = smem_to_u32(smem);
    const int t = threadIdx.x, wid = t >> 5, lane = t & 31;
    const int b = blockIdx.z;
    const int c0 = blockIdx.x * 128, i0 = blockIdx.y * 128;

    const size_t aoff = ((size_t)b * CC + c0) * NN;
    const size_t boff = ((size_t)b * NN + i0) * NN;

    float acc[4][4][4] = {};
    mma_mainloop_1<64>(v + aoff, NN, p + boff, NN, smemU32, t, wid, lane, acc);

    const float g = __ldg(gamma);
    const int rbase = c0 + (wid >> 2) * 64 + (lane >> 2);
    const int cbase = i0 + (wid & 3) * 32 + (lane & 3) * 2;
    const float* ivb = invs + b * NN;
#pragma unroll
    for (int mi = 0; mi < 4; mi++)
#pragma unroll
        for (int ni = 0; ni < 4; ni++) {
            const int ch = rbase + mi * 16;
            const int ci = cbase + ni * 8;
            const float2 iv = *(const float2*)&ivb[ci];
            {
                const size_t idx = ((size_t)b * CC + ch) * NN + ci;
                const float2 xv = *(const float2*)&X[idx];
                float2 o;
                o.x = g * acc[mi][ni][0] * iv.x + xv.x;
                o.y = g * acc[mi][ni][1] * iv.y + xv.y;
                *(float2*)&Out[idx] = o;
            }
            {
                const size_t idx = ((size_t)b * CC + ch + 8) * NN + ci;
                const float2 xv = *(const float2*)&X[idx];
                float2 o;
                o.x = g * acc[mi][ni][2] * iv.x + xv.x;
                o.y = g * acc[mi][ni][3] * iv.y + xv.y;
                *(float2*)&Out[idx] = o;
            }
        }
}

// ============================================================================
// Softmax: fp32 energy row -> unnormalized exp fp16 + 1/rowsum
// ============================================================================
__global__ void __launch_bounds__(256)
softmax_rows(const float* __restrict__ E,
             __half* __restrict__ P, float* __restrict__ invs)
{
    __shared__ float red[8];
    const float4* E4 = (const float4*)E;
    const size_t base4 = (size_t)blockIdx.x * (NN / 4);
    const int tid = threadIdx.x;
    const int lane = tid & 31, wid = tid >> 5;

    float4 v[4];
#pragma unroll
    for (int u = 0; u < 4; u++) v[u] = E4[base4 + u * 256 + tid];

    float m = -1e30f;
#pragma unroll
    for (int u = 0; u < 4; u++)
        m = fmaxf(m, fmaxf(fmaxf(v[u].x, v[u].y), fmaxf(v[u].z, v[u].w)));
#pragma unroll
    for (int off = 16; off > 0; off >>= 1)
        m = fmaxf(m, __shfl_xor_sync(0xffffffffu, m, off));
    if (lane == 0) red[wid] = m;
    __syncthreads();
    m = red[0];
#pragma unroll
    for (int w = 1; w < 8; w++) m = fmaxf(m, red[w]);
    __syncthreads();

    float s = 0.f;
#pragma unroll
    for (int u = 0; u < 4; u++) {
        v[u].x = __expf(v[u].x - m); v[u].y = __expf(v[u].y - m);
        v[u].z = __expf(v[u].z - m); v[u].w = __expf(v[u].w - m);
        s += v[u].x + v[u].y + v[u].z + v[u].w;
    }
#pragma unroll
    for (int off = 16; off > 0; off >>= 1)
        s += __shfl_xor_sync(0xffffffffu, s, off);
    if (lane == 0) red[wid] = s;
    __syncthreads();
    s = red[0];
#pragma unroll
    for (int w = 1; w < 8; w++) s += red[w];

#pragma unroll
    for (int u = 0; u < 4; u++) {
        const size_t el = base4 * 4 + (u * 256 + tid) * 4;
        __half h[4];
        h[0] = __float2half_rn(v[u].x); h[1] = __float2half_rn(v[u].y);
        h[2] = __float2half_rn(v[u].z); h[3] = __float2half_rn(v[u].w);
        *(uint2*)&P[el] = *(uint2*)h;
    }
    if (tid == 0) invs[blockIdx.x] = 1.0f / s;
}

// ============================================================================

extern "C" void kernel_launch(void* const* d_in, const int* in_sizes, int n_in,
                              void* d_out, int out_size)
{
    const float* x     = (const float*)d_in[0];
    const float* dep   = (const float*)d_in[1];
    const float* wq    = (const float*)d_in[2];
    const float* bq    = (const float*)d_in[3];
    const float* wqd   = (const float*)d_in[4];
    const float* bqd   = (const float*)d_in[5];
    const float* wk    = (const float*)d_in[6];
    const float* bk    = (const float*)d_in[7];
    const float* wkd   = (const float*)d_in[8];
    const float* bkd   = (const float*)d_in[9];
    const float* wv    = (const float*)d_in[10];
    const float* bv    = (const float*)d_in[11];
    const float* gamma = (const float*)d_in[12];
    float* out = (float*)d_out;

    __nv_bfloat16 *xt_hi, *xt_lo, *dt_hi, *dt_lo;
    __nv_bfloat16 *wqk_hi, *wqk_lo, *wqkd_hi, *wqkd_lo, *wv_hi, *wv_lo;
    __half *qhi, *qlo, *kk, *vv, *p;
    float *e, *s;
    cudaGetSymbolAddress((void**)&xt_hi, g_xt_hi);
    cudaGetSymbolAddress((void**)&xt_lo, g_xt_lo);
    cudaGetSymbolAddress((void**)&dt_hi, g_dt_hi);
    cudaGetSymbolAddress((void**)&dt_lo, g_dt_lo);
    cudaGetSymbolAddress((void**)&wqk_hi, g_wqk_hi);
    cudaGetSymbolAddress((void**)&wqk_lo, g_wqk_lo);
    cudaGetSymbolAddress((void**)&wqkd_hi, g_wqkd_hi);
    cudaGetSymbolAddress((void**)&wqkd_lo, g_wqkd_lo);
    cudaGetSymbolAddress((void**)&wv_hi, g_wv_hi);
    cudaGetSymbolAddress((void**)&wv_lo, g_wv_lo);
    cudaGetSymbolAddress((void**)&qhi, g_qhi);
    cudaGetSymbolAddress((void**)&qlo, g_qlo);
    cudaGetSymbolAddress((void**)&kk, g_k);
    cudaGetSymbolAddress((void**)&vv, g_v);
    cudaGetSymbolAddress((void**)&p, g_p);
    cudaGetSymbolAddress((void**)&e, g_e);
    cudaGetSymbolAddress((void**)&s, g_s);

    cudaFuncSetAttribute(mma_proj_qk, cudaFuncAttributeMaxDynamicSharedMemorySize, MMA_SMEM_BYTES);
    cudaFuncSetAttribute(mma_proj_v,  cudaFuncAttributeMaxDynamicSharedMemorySize, MMA_SMEM_BYTES);
    cudaFuncSetAttribute(mma_energy,  cudaFuncAttributeMaxDynamicSharedMemorySize, H2_SMEM_BYTES);
    cudaFuncSetAttribute(mma_out,     cudaFuncAttributeMaxDynamicSharedMemorySize, H1_SMEM_BYTES);

    // input prep
    dim3 tthr(32, 8);
    transpose_split<<<dim3(NN / 32, CC / 32, BB), tthr>>>(x,   xt_hi, xt_lo);
    transpose_split<<<dim3(NN / 32, CC / 32, BB), tthr>>>(dep, dt_hi, dt_lo);
    weight_split<<<(768 * 512 + 255) / 256, 256>>>(wq, wk, wqd, wkd, wv,
                                                   wqk_hi, wqk_lo, wqkd_hi, wqkd_lo,
                                                   wv_hi, wv_lo);

    // projections (q/k merged over x+dep via grid.y)
    mma_proj_qk<<<dim3(NN / 128, 2, BB), 256, MMA_SMEM_BYTES>>>(
        xt_hi, xt_lo, dt_hi, dt_lo, wqk_hi, wqk_lo, wqkd_hi, wqkd_lo,
        bq, bk, bqd, bkd, qhi, qlo, kk);
    mma_proj_v<<<dim3(NN / 128, CC / 128, BB), 256, MMA_SMEM_BYTES>>>(
        wv_hi, wv_lo, xt_hi, xt_lo, bv, vv);

    // energy (2-pass fp16, occ 2)
    mma_energy<<<dim3(NN / 128, NN / 128, BB), 256, H2_SMEM_BYTES>>>(qhi, qlo, kk, e);

    // softmax -> fp16 exp + 1/rowsum
    softmax_rows<<<BB * NN, 256>>>(e, p, s);

    // out (1-pass fp16, occ 2)
    mma_out<<<dim3(CC / 128, NN / 128, BB), 256, H1_SMEM_BYTES>>>(vv, p, x, gamma, s, out);
}

// round 14
// speedup vs baseline: 2.8682x; 1.0417x over previous
#include <cuda_runtime.h>
#include <cuda_bf16.h>
#include <cuda_fp16.h>
#include <cstdint>

#define BB 4
#define CC 512
#define CQ 64
#define DD 128   // 2*CQ
#define NN 4096  // H*W

// ---------------- scratch (device globals; no allocations allowed) ----------
__device__ __align__(256) __nv_bfloat16 g_xt_hi[BB * NN * CC];  // x^T [b][n][c] bf16 hi/lo
__device__ __align__(256) __nv_bfloat16 g_xt_lo[BB * NN * CC];
__device__ __align__(256) __half        g_xt_h[BB * NN * CC];   // x^T fp16 single
__device__ __align__(256) __nv_bfloat16 g_dt_hi[BB * NN * CC];  // dep^T bf16 hi/lo
__device__ __align__(256) __nv_bfloat16 g_dt_lo[BB * NN * CC];
__device__ __align__(256) __nv_bfloat16 g_wqk_hi[DD * CC];      // wq rows 0-63, wk 64-127
__device__ __align__(256) __nv_bfloat16 g_wqk_lo[DD * CC];
__device__ __align__(256) __nv_bfloat16 g_wqkd_hi[DD * CC];
__device__ __align__(256) __nv_bfloat16 g_wqkd_lo[DD * CC];
__device__ __align__(256) __half g_wv_hi[CC * CC];              // wv fp16 hi/lo
__device__ __align__(256) __half g_wv_lo[CC * CC];
__device__ __align__(256) __half g_qhi[BB * NN * DD];           // [b][i][d] fp16 hi/lo
__device__ __align__(256) __half g_qlo[BB * NN * DD];
__device__ __align__(256) __half g_k[BB * NN * DD];             // [b][j][d] fp16 single
__device__ __align__(256) __half g_v[BB * CC * NN];             // [b][c][n] fp16 single
__device__ __align__(256) float g_e[(size_t)BB * NN * NN];
__device__ __align__(256) __half g_p[(size_t)BB * NN * NN];     // exp, fp16 single
__device__ __align__(256) float g_s[BB * NN];

// ---------------- low-level helpers -----------------------------------------
__device__ __forceinline__ uint32_t smem_to_u32(const void* p) {
    uint32_t a;
    asm("{ .reg .u64 t; cvta.to.shared.u64 t, %1; cvt.u32.u64 %0, t; }" : "=r"(a) : "l"(p));
    return a;
}
#define SWZ(off) ((off) ^ (((off) >> 3) & 0x70))

__device__ __forceinline__ void cp16(uint32_t dst, const void* src) {
    asm volatile("cp.async.cg.shared.global [%0], [%1], 16;" :: "r"(dst), "l"(src));
}
__device__ __forceinline__ void cp_commit() {
    asm volatile("cp.async.commit_group;" ::: "memory");
}
__device__ __forceinline__ void ldsm4(uint32_t r[4], uint32_t addr) {
    asm volatile("ldmatrix.sync.aligned.m8n8.x4.shared.b16 {%0,%1,%2,%3}, [%4];"
                 : "=r"(r[0]), "=r"(r[1]), "=r"(r[2]), "=r"(r[3]) : "r"(addr));
}
__device__ __forceinline__ void mma_bf16(float acc[4], const uint32_t a[4],
                                         uint32_t b0, uint32_t b1) {
    asm volatile("mma.sync.aligned.m16n8k16.row.col.f32.bf16.bf16.f32 "
                 "{%0,%1,%2,%3}, {%4,%5,%6,%7}, {%8,%9}, {%0,%1,%2,%3};"
                 : "+f"(acc[0]), "+f"(acc[1]), "+f"(acc[2]), "+f"(acc[3])
                 : "r"(a[0]), "r"(a[1]), "r"(a[2]), "r"(a[3]), "r"(b0), "r"(b1));
}
__device__ __forceinline__ void mma_f16(float acc[4], const uint32_t a[4],
                                        uint32_t b0, uint32_t b1) {
    asm volatile("mma.sync.aligned.m16n8k16.row.col.f32.f16.f16.f32 "
                 "{%0,%1,%2,%3}, {%4,%5,%6,%7}, {%8,%9}, {%0,%1,%2,%3};"
                 : "+f"(acc[0]), "+f"(acc[1]), "+f"(acc[2]), "+f"(acc[3])
                 : "r"(a[0]), "r"(a[1]), "r"(a[2]), "r"(a[3]), "r"(b0), "r"(b1));
}
__device__ __forceinline__ void split_store2_h(float v0, float v1,
                                               __half* dh, __half* dl)
{
    __half h0 = __float2half_rn(v0), h1 = __float2half_rn(v1);
    __half l0 = __float2half_rn(v0 - __half2float(h0));
    __half l1 = __float2half_rn(v1 - __half2float(h1));
    __half2 H; H.x = h0; H.y = h1;
    __half2 L; L.x = l0; L.y = l1;
    *(__half2*)dh = H;
    *(__half2*)dl = L;
}
__device__ __forceinline__ void store2_h(float v0, float v1, __half* d)
{
    __half2 H; H.x = __float2half_rn(v0); H.y = __float2half_rn(v1);
    *(__half2*)d = H;
}

// ---------------- 3-pass split-bf16 machinery (R8-proven, EXACT) -------------
#define STG 65536
#define MMA_SMEM_BYTES (2 * STG)

__device__ __forceinline__ void stage_load(
    const __nv_bfloat16* __restrict__ Ahi, const __nv_bfloat16* __restrict__ Alo,
    size_t aStr,
    const __nv_bfloat16* __restrict__ Bhi, const __nv_bfloat16* __restrict__ Blo,
    size_t bStr, int kt, uint32_t stageU32, int t)
{
#pragma unroll
    for (int i = 0; i < 4; i++) {
        const int id = t + i * 256;
        const int row = id >> 3, c16 = id & 7;
        const uint32_t doff = SWZ((uint32_t)(row * 128 + c16 * 16));
        const size_t so = (size_t)row * aStr + kt + c16 * 8;
        cp16(stageU32 + doff,          Ahi + so);
        cp16(stageU32 + 16384 + doff,  Alo + so);
        const size_t sb = (size_t)row * bStr + kt + c16 * 8;
        cp16(stageU32 + 32768 + doff,  Bhi + sb);
        cp16(stageU32 + 49152 + doff,  Blo + sb);
    }
}

__device__ __forceinline__ void stage_compute(uint32_t stageU32, int wid, int lane,
                                              float acc[4][4][4])
{
    const int warp_row = wid >> 2;
    const int warp_col = wid & 3;
    const int lrow = lane & 15;
    const int chalf = (lane >= 16) ? 16 : 0;

#pragma unroll
    for (int ks = 0; ks < 4; ks++) {
        const uint32_t bcol = ks * 32 + chalf;
        uint32_t ahi[4][4], alo[4][4];
#pragma unroll
        for (int mi = 0; mi < 4; mi++) {
            const uint32_t off = SWZ((uint32_t)((warp_row * 64 + mi * 16 + lrow) * 128 + bcol));
            ldsm4(ahi[mi], stageU32 + off);
            ldsm4(alo[mi], stageU32 + 16384 + off);
        }
        uint32_t bhi[2][4], blo[2][4];
#pragma unroll
        for (int nh = 0; nh < 2; nh++) {
            const uint32_t off = SWZ((uint32_t)((warp_col * 32 + nh * 16 + lrow) * 128 + bcol));
            ldsm4(bhi[nh], stageU32 + 32768 + off);
            ldsm4(blo[nh], stageU32 + 49152 + off);
        }
#pragma unroll
        for (int mi = 0; mi < 4; mi++)
#pragma unroll
            for (int ni = 0; ni < 4; ni++) {
                const int nh = ni >> 1, s = ni & 1;
                mma_bf16(acc[mi][ni], ahi[mi], bhi[nh][s], bhi[nh][s + 2]);
                mma_bf16(acc[mi][ni], alo[mi], bhi[nh][s], bhi[nh][s + 2]);
                mma_bf16(acc[mi][ni], ahi[mi], blo[nh][s], blo[nh][s + 2]);
            }
    }
}

template <int KCHUNKS>
__device__ __forceinline__ void mma_mainloop(
    const __nv_bfloat16* Ahi, const __nv_bfloat16* Alo, size_t aStr,
    const __nv_bfloat16* Bhi, const __nv_bfloat16* Blo, size_t bStr,
    uint32_t smemU32, int t, int wid, int lane, float acc[4][4][4])
{
    stage_load(Ahi, Alo, aStr, Bhi, Blo, bStr, 0, smemU32, t);
    cp_commit();
    for (int c = 0; c < KCHUNKS; c++) {
        const bool more = (c + 1) < KCHUNKS;
        if (more) {
            stage_load(Ahi, Alo, aStr, Bhi, Blo, bStr, (c + 1) * 64,
                       smemU32 + ((c + 1) & 1) * STG, t);
            cp_commit();
            asm volatile("cp.async.wait_group 1;" ::: "memory");
        } else {
            asm volatile("cp.async.wait_group 0;" ::: "memory");
        }
        __syncthreads();
        stage_compute(smemU32 + (c & 1) * STG, wid, lane, acc);
        __syncthreads();
    }
}

// ---------------- 2-pass split-fp16 (R10-proven, EXACT): A hi/lo, B single ---
#define STG_H 49152
#define H2_SMEM_BYTES (2 * STG_H)

__device__ __forceinline__ void stage_load_h(
    const __half* __restrict__ Ahi, const __half* __restrict__ Alo, size_t aStr,
    const __half* __restrict__ B, size_t bStr, int kt, uint32_t stg, int t)
{
#pragma unroll
    for (int i = 0; i < 4; i++) {
        const int id = t + i * 256;
        const int row = id >> 3, c16 = id & 7;
        const uint32_t doff = SWZ((uint32_t)(row * 128 + c16 * 16));
        const size_t so = (size_t)row * aStr + kt + c16 * 8;
        cp16(stg + doff,          Ahi + so);
        cp16(stg + 16384 + doff,  Alo + so);
        const size_t sb = (size_t)row * bStr + kt + c16 * 8;
        cp16(stg + 32768 + doff,  B + sb);
    }
}

__device__ __forceinline__ void stage_compute_h(uint32_t stg, int wid, int lane,
                                                float acc[4][4][4])
{
    const int warp_row = wid >> 2;
    const int warp_col = wid & 3;
    const int lrow = lane & 15;
    const int chalf = (lane >= 16) ? 16 : 0;

#pragma unroll
    for (int ks = 0; ks < 4; ks++) {
        const uint32_t bcol = ks * 32 + chalf;
        uint32_t ahi[4][4], alo[4][4];
#pragma unroll
        for (int mi = 0; mi < 4; mi++) {
            const uint32_t off = SWZ((uint32_t)((warp_row * 64 + mi * 16 + lrow) * 128 + bcol));
            ldsm4(ahi[mi], stg + off);
            ldsm4(alo[mi], stg + 16384 + off);
        }
        uint32_t bp[2][4];
#pragma unroll
        for (int nh = 0; nh < 2; nh++) {
            const uint32_t off = SWZ((uint32_t)((warp_col * 32 + nh * 16 + lrow) * 128 + bcol));
            ldsm4(bp[nh], stg + 32768 + off);
        }
#pragma unroll
        for (int mi = 0; mi < 4; mi++)
#pragma unroll
            for (int ni = 0; ni < 4; ni++) {
                const int nh = ni >> 1, s = ni & 1;
                mma_f16(acc[mi][ni], ahi[mi], bp[nh][s], bp[nh][s + 2]);
                mma_f16(acc[mi][ni], alo[mi], bp[nh][s], bp[nh][s + 2]);
            }
    }
}

template <int KCHUNKS>
__device__ __forceinline__ void mma_mainloop_h(
    const __half* Ahi, const __half* Alo, size_t aStr,
    const __half* B, size_t bStr,
    uint32_t smemU32, int t, int wid, int lane, float acc[4][4][4])
{
    stage_load_h(Ahi, Alo, aStr, B, bStr, 0, smemU32, t);
    cp_commit();
    for (int c = 0; c < KCHUNKS; c++) {
        const bool more = (c + 1) < KCHUNKS;
        if (more) {
            stage_load_h(Ahi, Alo, aStr, B, bStr, (c + 1) * 64,
                         smemU32 + ((c + 1) & 1) * STG_H, t);
            cp_commit();
            asm volatile("cp.async.wait_group 1;" ::: "memory");
        } else {
            asm volatile("cp.async.wait_group 0;" ::: "memory");
        }
        __syncthreads();
        stage_compute_h(smemU32 + (c & 1) * STG_H, wid, lane, acc);
        __syncthreads();
    }
}

// ---------------- 1-pass fp16 (R11-proven): A single, B single ---------------
#define STG_1 32768
#define H1_SMEM_BYTES (2 * STG_1)

__device__ __forceinline__ void stage_load_1(
    const __half* __restrict__ A, size_t aStr,
    const __half* __restrict__ B, size_t bStr, int kt, uint32_t stg, int t)
{
#pragma unroll
    for (int i = 0; i < 4; i++) {
        const int id = t + i * 256;
        const int row = id >> 3, c16 = id & 7;
        const uint32_t doff = SWZ((uint32_t)(row * 128 + c16 * 16));
        cp16(stg + doff,          A + (size_t)row * aStr + kt + c16 * 8);
        cp16(stg + 16384 + doff,  B + (size_t)row * bStr + kt + c16 * 8);
    }
}

__device__ __forceinline__ void stage_compute_1(uint32_t stg, int wid, int lane,
                                                float acc[4][4][4])
{
    const int warp_row = wid >> 2;
    const int warp_col = wid & 3;
    const int lrow = lane & 15;
    const int chalf = (lane >= 16) ? 16 : 0;

#pragma unroll
    for (int ks = 0; ks < 4; ks++) {
        const uint32_t bcol = ks * 32 + chalf;
        uint32_t a[4][4];
#pragma unroll
        for (int mi = 0; mi < 4; mi++) {
            const uint32_t off = SWZ((uint32_t)((warp_row * 64 + mi * 16 + lrow) * 128 + bcol));
            ldsm4(a[mi], stg + off);
        }
        uint32_t bp[2][4];
#pragma unroll
        for (int nh = 0; nh < 2; nh++) {
            const uint32_t off = SWZ((uint32_t)((warp_col * 32 + nh * 16 + lrow) * 128 + bcol));
            ldsm4(bp[nh], stg + 16384 + off);
        }
#pragma unroll
        for (int mi = 0; mi < 4; mi++)
#pragma unroll
            for (int ni = 0; ni < 4; ni++) {
                const int nh = ni >> 1, s = ni & 1;
                mma_f16(acc[mi][ni], a[mi], bp[nh][s], bp[nh][s + 2]);
            }
    }
}

template <int KCHUNKS>
__device__ __forceinline__ void mma_mainloop_1(
    const __half* A, size_t aStr, const __half* B, size_t bStr,
    uint32_t smemU32, int t, int wid, int lane, float acc[4][4][4])
{
    stage_load_1(A, aStr, B, bStr, 0, smemU32, t);
    cp_commit();
    for (int c = 0; c < KCHUNKS; c++) {
        const bool more = (c + 1) < KCHUNKS;
        if (more) {
            stage_load_1(A, aStr, B, bStr, (c + 1) * 64,
                         smemU32 + ((c + 1) & 1) * STG_1, t);
            cp_commit();
            asm volatile("cp.async.wait_group 1;" ::: "memory");
        } else {
            asm volatile("cp.async.wait_group 0;" ::: "memory");
        }
        __syncthreads();
        stage_compute_1(smemU32 + (c & 1) * STG_1, wid, lane, acc);
        __syncthreads();
    }
}

// ============================================================================
// transpose + split: src [b][C][N] fp32 -> dst [b][N][C] bf16 hi/lo
//                    (+ optional fp16 single output for the v-proj B operand)
// ============================================================================
__global__ void __launch_bounds__(256)
transpose_split(const float* __restrict__ src,
                __nv_bfloat16* __restrict__ dhi, __nv_bfloat16* __restrict__ dlo,
                __half* __restrict__ dh16)
{
    __shared__ float tile[32][33];
    const int b = blockIdx.z;
    const int n0 = blockIdx.x * 32, c0 = blockIdx.y * 32;
    const int tx = threadIdx.x, ty = threadIdx.y;   // (32, 8)
    const float* S = src + (size_t)b * CC * NN;
#pragma unroll
    for (int i = 0; i < 4; i++)
        tile[ty * 4 + i][tx] = S[(size_t)(c0 + ty * 4 + i) * NN + n0 + tx];
    __syncthreads();
    __nv_bfloat16* H = dhi + (size_t)b * NN * CC;
    __nv_bfloat16* L = dlo + (size_t)b * NN * CC;
    __half* H16 = dh16 ? dh16 + (size_t)b * NN * CC : nullptr;
#pragma unroll
    for (int i = 0; i < 4; i++) {
        const float f = tile[tx][ty * 4 + i];
        const __nv_bfloat16 h = __float2bfloat16(f);
        const __nv_bfloat16 l = __float2bfloat16(f - __bfloat162float(h));
        const size_t idx = (size_t)(n0 + ty * 4 + i) * CC + c0 + tx;
        H[idx] = h;
        L[idx] = l;
        if (H16) H16[idx] = __float2half_rn(f);
    }
}

// ============================================================================
// weight split: the four q/k weights -> bf16 hi/lo (256 rows total)
// ============================================================================
__global__ void __launch_bounds__(256)
weight_split(const float* __restrict__ wq, const float* __restrict__ wk,
             const float* __restrict__ wqd, const float* __restrict__ wkd,
             __nv_bfloat16* __restrict__ wqk_hi, __nv_bfloat16* __restrict__ wqk_lo,
             __nv_bfloat16* __restrict__ wqkd_hi, __nv_bfloat16* __restrict__ wqkd_lo)
{
    const int idx = blockIdx.x * 256 + threadIdx.x;
    if (idx >= 256 * 512) return;
    const int row = idx >> 9, col = idx & 511;
    const float* src;
    __nv_bfloat16 *dh, *dl;
    int drow;
    if (row < 64)       { src = wq  + (size_t)row * 512;         dh = wqk_hi;  dl = wqk_lo;  drow = row; }
    else if (row < 128) { src = wk  + (size_t)(row - 64) * 512;  dh = wqk_hi;  dl = wqk_lo;  drow = row; }
    else if (row < 192) { src = wqd + (size_t)(row - 128) * 512; dh = wqkd_hi; dl = wqkd_lo; drow = row - 128; }
    else                { src = wkd + (size_t)(row - 192) * 512; dh = wqkd_hi; dl = wqkd_lo; drow = row - 128; }
    const float f = src[col];
    const __nv_bfloat16 h = __float2bfloat16(f);
    dh[(size_t)drow * 512 + col] = h;
    dl[(size_t)drow * 512 + col] = __float2bfloat16(f - __bfloat162float(h));
}

// wv -> fp16 hi/lo
__global__ void __launch_bounds__(256)
wv_split(const float* __restrict__ wv,
         __half* __restrict__ wv_hi, __half* __restrict__ wv_lo)
{
    const int idx = blockIdx.x * 256 + threadIdx.x;
    if (idx >= 512 * 512) return;
    const float f = wv[idx];
    const __half h = __float2half_rn(f);
    wv_hi[idx] = h;
    wv_lo[idx] = __float2half_rn(f - __half2float(h));
}

// ============================================================================
// proj qk (merged x/dep via blockIdx.y): [n][d] = in[n][c] . w[d][c]
// q -> fp16 hi/lo, k -> fp16 single.  bf16 3-pass, occ 1 (exp-sensitive path).
// ============================================================================
__global__ void __launch_bounds__(256, 1)
mma_proj_qk(const __nv_bfloat16* __restrict__ xt_hi, const __nv_bfloat16* __restrict__ xt_lo,
            const __nv_bfloat16* __restrict__ dt_hi, const __nv_bfloat16* __restrict__ dt_lo,
            const __nv_bfloat16* __restrict__ wqk_hi, const __nv_bfloat16* __restrict__ wqk_lo,
            const __nv_bfloat16* __restrict__ wqkd_hi, const __nv_bfloat16* __restrict__ wqkd_lo,
            const float* __restrict__ bq, const float* __restrict__ bk,
            const float* __restrict__ bqd, const float* __restrict__ bkd,
            __half* __restrict__ Qhi, __half* __restrict__ Qlo,
            __half* __restrict__ K)
{
    extern __shared__ char smem[];
    const uint32_t smemU32 = smem_to_u32(smem);
    const int t = threadIdx.x, wid = t >> 5, lane = t & 31;
    const int b = blockIdx.z;
    const int i0 = blockIdx.x * 128;
    const int sel = blockIdx.y;   // 0 = x path (d 0-63), 1 = dep path (d 64-127)

    const __nv_bfloat16* Ahi = sel ? dt_hi : xt_hi;
    const __nv_bfloat16* Alo = sel ? dt_lo : xt_lo;
    const __nv_bfloat16* Whi = sel ? wqkd_hi : wqk_hi;
    const __nv_bfloat16* Wlo = sel ? wqkd_lo : wqk_lo;
    const float* bias_q = sel ? bqd : bq;
    const float* bias_k = sel ? bkd : bk;
    const int d_off = sel ? CQ : 0;

    const size_t aoff = ((size_t)b * NN + i0) * CC;
    float acc[4][4][4] = {};
    mma_mainloop<8>(Ahi + aoff, Alo + aoff, CC, Whi, Wlo, CC,
                    smemU32, t, wid, lane, acc);

    const int warp_col = wid & 3;
    const bool isK = warp_col >= 2;
    const float* bias = isK ? bias_k : bias_q;
    const int csub = isK ? 64 : 0;

    const int rbase = i0 + (wid >> 2) * 64 + (lane >> 2);
    const int cbase = warp_col * 32 + (lane & 3) * 2;
#pragma unroll
    for (int mi = 0; mi < 4; mi++)
#pragma unroll
        for (int ni = 0; ni < 4; ni++) {
            const int col = cbase + ni * 8 - csub;   // 0..63
            const float2 bi = *(const float2*)&bias[col];
            const int r0 = rbase + mi * 16;
            const size_t a0 = ((size_t)b * NN + r0) * DD + d_off + col;
            const size_t a1 = ((size_t)b * NN + r0 + 8) * DD + d_off + col;
            if (!isK) {
                split_store2_h(acc[mi][ni][0] + bi.x, acc[mi][ni][1] + bi.y, Qhi + a0, Qlo + a0);
                split_store2_h(acc[mi][ni][2] + bi.x, acc[mi][ni][3] + bi.y, Qhi + a1, Qlo + a1);
            } else {
                store2_h(acc[mi][ni][0] + bi.x, acc[mi][ni][1] + bi.y, K + a0);
                store2_h(acc[mi][ni][2] + bi.x, acc[mi][ni][3] + bi.y, K + a1);
            }
        }
}

// ============================================================================
// proj v: [c][n] tile = wv[c][k] . xt[n][k]  -> fp16 single
// 2-pass split-fp16 (wv hi/lo fp16, xt single fp16), occ 2.
// ============================================================================
__global__ void __launch_bounds__(256, 2)
mma_proj_v(const __half* __restrict__ w_hi, const __half* __restrict__ w_lo,
           const __half* __restrict__ xt_h,
           const float* __restrict__ bias,
           __half* __restrict__ V)
{
    extern __shared__ char smem[];
    const uint32_t smemU32 = smem_to_u32(smem);
    const int t = threadIdx.x, wid = t >> 5, lane = t & 31;
    const int b = blockIdx.z;
    const int n0 = blockIdx.x * 128, m0 = blockIdx.y * 128;

    const size_t boff = ((size_t)b * NN + n0) * CC;
    float acc[4][4][4] = {};
    mma_mainloop_h<8>(w_hi + (size_t)m0 * CC, w_lo + (size_t)m0 * CC, CC,
                      xt_h + boff, CC,
                      smemU32, t, wid, lane, acc);

    const int rbase = m0 + (wid >> 2) * 64 + (lane >> 2);
    const int cbase = n0 + (wid & 3) * 32 + (lane & 3) * 2;
#pragma unroll
    for (int mi = 0; mi < 4; mi++) {
        const int ch0 = rbase + mi * 16;
        const float bi0 = bias[ch0], bi1 = bias[ch0 + 8];
#pragma unroll
        for (int ni = 0; ni < 4; ni++) {
            const int cn = cbase + ni * 8;
            store2_h(acc[mi][ni][0] + bi0, acc[mi][ni][1] + bi0,
                     V + ((size_t)b * CC + ch0) * NN + cn);
            store2_h(acc[mi][ni][2] + bi1, acc[mi][ni][3] + bi1,
                     V + ((size_t)b * CC + ch0 + 8) * NN + cn);
        }
    }
}

// ============================================================================
// Energy: E[b][i][j] = sum_d q[i][d] k[j][d]  (2-pass fp16; occ 2)
// ============================================================================
__global__ void __launch_bounds__(256, 2)
mma_energy(const __half* __restrict__ qhi, const __half* __restrict__ qlo,
           const __half* __restrict__ k,
           float* __restrict__ E)
{
    extern __shared__ char smem[];
    const uint32_t smemU32 = smem_to_u32(smem);
    const int t = threadIdx.x, wid = t >> 5, lane = t & 31;
    const int b = blockIdx.z;
    const int i0 = blockIdx.y * 128, j0 = blockIdx.x * 128;

    const size_t aoff = ((size_t)b * NN + i0) * DD;
    const size_t boff = ((size_t)b * NN + j0) * DD;

    float acc[4][4][4] = {};
    mma_mainloop_h<2>(qhi + aoff, qlo + aoff, DD, k + boff, DD,
                      smemU32, t, wid, lane, acc);

    float* Eb = E + (size_t)b * NN * NN;
    const int rbase = i0 + (wid >> 2) * 64 + (lane >> 2);
    const int cbase = j0 + (wid & 3) * 32 + (lane & 3) * 2;
#pragma unroll
    for (int mi = 0; mi < 4; mi++)
#pragma unroll
        for (int ni = 0; ni < 4; ni++) {
            const int r = rbase + mi * 16;
            const int cjj = cbase + ni * 8;
            *(float2*)&Eb[(size_t)r * NN + cjj]       = make_float2(acc[mi][ni][0], acc[mi][ni][1]);
            *(float2*)&Eb[(size_t)(r + 8) * NN + cjj] = make_float2(acc[mi][ni][2], acc[mi][ni][3]);
        }
}

// ============================================================================
// Out: out[b][c][i] = g * (sum_j v[c][j] p[i][j]) * inv[i] + x[c][i]
// 1-pass fp16, occ 2.
// ============================================================================
__global__ void __launch_bounds__(256, 2)
mma_out(const __half* __restrict__ v, const __half* __restrict__ p,
        const float* __restrict__ X, const float* __restrict__ gamma,
        const float* __restrict__ invs, float* __restrict__ Out)
{
    extern __shared__ char smem[];
    const uint32_t smemU32 = smem_to_u32(smem);
    const int t = threadIdx.x, wid = t >> 5, lane = t & 31;
    const int b = blockIdx.z;
    const int c0 = blockIdx.x * 128, i0 = blockIdx.y * 128;

    const size_t aoff = ((size_t)b * CC + c0) * NN;
    const size_t boff = ((size_t)b * NN + i0) * NN;

    float acc[4][4][4] = {};
    mma_mainloop_1<64>(v + aoff, NN, p + boff, NN, smemU32, t, wid, lane, acc);

    const float g = __ldg(gamma);
    const int rbase = c0 + (wid >> 2) * 64 + (lane >> 2);
    const int cbase = i0 + (wid & 3) * 32 + (lane & 3) * 2;
    const float* ivb = invs + b * NN;
#pragma unroll
    for (int mi = 0; mi < 4; mi++)
#pragma unroll
        for (int ni = 0; ni < 4; ni++) {
            const int ch = rbase + mi * 16;
            const int ci = cbase + ni * 8;
            const float2 iv = *(const float2*)&ivb[ci];
            {
                const size_t idx = ((size_t)b * CC + ch) * NN + ci;
                const float2 xv = *(const float2*)&X[idx];
                float2 o;
                o.x = g * acc[mi][ni][0] * iv.x + xv.x;
                o.y = g * acc[mi][ni][1] * iv.y + xv.y;
                *(float2*)&Out[idx] = o;
            }
            {
                const size_t idx = ((size_t)b * CC + ch + 8) * NN + ci;
                const float2 xv = *(const float2*)&X[idx];
                float2 o;
                o.x = g * acc[mi][ni][2] * iv.x + xv.x;
                o.y = g * acc[mi][ni][3] * iv.y + xv.y;
                *(float2*)&Out[idx] = o;
            }
        }
}

// ============================================================================
// Softmax: fp32 energy row -> unnormalized exp fp16 + 1/rowsum
// ============================================================================
__global__ void __launch_bounds__(256)
softmax_rows(const float* __restrict__ E,
             __half* __restrict__ P, float* __restrict__ invs)
{
    __shared__ float red[8];
    const float4* E4 = (const float4*)E;
    const size_t base4 = (size_t)blockIdx.x * (NN / 4);
    const int tid = threadIdx.x;
    const int lane = tid & 31, wid = tid >> 5;

    float4 v[4];
#pragma unroll
    for (int u = 0; u < 4; u++) v[u] = E4[base4 + u * 256 + tid];

    float m = -1e30f;
#pragma unroll
    for (int u = 0; u < 4; u++)
        m = fmaxf(m, fmaxf(fmaxf(v[u].x, v[u].y), fmaxf(v[u].z, v[u].w)));
#pragma unroll
    for (int off = 16; off > 0; off >>= 1)
        m = fmaxf(m, __shfl_xor_sync(0xffffffffu, m, off));
    if (lane == 0) red[wid] = m;
    __syncthreads();
    m = red[0];
#pragma unroll
    for (int w = 1; w < 8; w++) m = fmaxf(m, red[w]);
    __syncthreads();

    float s = 0.f;
#pragma unroll
    for (int u = 0; u < 4; u++) {
        v[u].x = __expf(v[u].x - m); v[u].y = __expf(v[u].y - m);
        v[u].z = __expf(v[u].z - m); v[u].w = __expf(v[u].w - m);
        s += v[u].x + v[u].y + v[u].z + v[u].w;
    }
#pragma unroll
    for (int off = 16; off > 0; off >>= 1)
        s += __shfl_xor_sync(0xffffffffu, s, off);
    if (lane == 0) red[wid] = s;
    __syncthreads();
    s = red[0];
#pragma unroll
    for (int w = 1; w < 8; w++) s += red[w];

#pragma unroll
    for (int u = 0; u < 4; u++) {
        const size_t el = base4 * 4 + (u * 256 + tid) * 4;
        __half h[4];
        h[0] = __float2half_rn(v[u].x); h[1] = __float2half_rn(v[u].y);
        h[2] = __float2half_rn(v[u].z); h[3] = __float2half_rn(v[u].w);
        *(uint2*)&P[el] = *(uint2*)h;
    }
    if (tid == 0) invs[blockIdx.x] = 1.0f / s;
}

// ============================================================================

extern "C" void kernel_launch(void* const* d_in, const int* in_sizes, int n_in,
                              void* d_out, int out_size)
{
    const float* x     = (const float*)d_in[0];
    const float* dep   = (const float*)d_in[1];
    const float* wq    = (const float*)d_in[2];
    const float* bq    = (const float*)d_in[3];
    const float* wqd   = (const float*)d_in[4];
    const float* bqd   = (const float*)d_in[5];
    const float* wk    = (const float*)d_in[6];
    const float* bk    = (const float*)d_in[7];
    const float* wkd   = (const float*)d_in[8];
    const float* bkd   = (const float*)d_in[9];
    const float* wv    = (const float*)d_in[10];
    const float* bv    = (const float*)d_in[11];
    const float* gamma = (const float*)d_in[12];
    float* out = (float*)d_out;

    __nv_bfloat16 *xt_hi, *xt_lo, *dt_hi, *dt_lo;
    __nv_bfloat16 *wqk_hi, *wqk_lo, *wqkd_hi, *wqkd_lo;
    __half *xt_h, *wv_hi, *wv_lo;
    __half *qhi, *qlo, *kk, *vv, *p;
    float *e, *s;
    cudaGetSymbolAddress((void**)&xt_hi, g_xt_hi);
    cudaGetSymbolAddress((void**)&xt_lo, g_xt_lo);
    cudaGetSymbolAddress((void**)&xt_h,  g_xt_h);
    cudaGetSymbolAddress((void**)&dt_hi, g_dt_hi);
    cudaGetSymbolAddress((void**)&dt_lo, g_dt_lo);
    cudaGetSymbolAddress((void**)&wqk_hi, g_wqk_hi);
    cudaGetSymbolAddress((void**)&wqk_lo, g_wqk_lo);
    cudaGetSymbolAddress((void**)&wqkd_hi, g_wqkd_hi);
    cudaGetSymbolAddress((void**)&wqkd_lo, g_wqkd_lo);
    cudaGetSymbolAddress((void**)&wv_hi, g_wv_hi);
    cudaGetSymbolAddress((void**)&wv_lo, g_wv_lo);
    cudaGetSymbolAddress((void**)&qhi, g_qhi);
    cudaGetSymbolAddress((void**)&qlo, g_qlo);
    cudaGetSymbolAddress((void**)&kk, g_k);
    cudaGetSymbolAddress((void**)&vv, g_v);
    cudaGetSymbolAddress((void**)&p, g_p);
    cudaGetSymbolAddress((void**)&e, g_e);
    cudaGetSymbolAddress((void**)&s, g_s);

    cudaFuncSetAttribute(mma_proj_qk, cudaFuncAttributeMaxDynamicSharedMemorySize, MMA_SMEM_BYTES);
    cudaFuncSetAttribute(mma_proj_v,  cudaFuncAttributeMaxDynamicSharedMemorySize, H2_SMEM_BYTES);
    cudaFuncSetAttribute(mma_energy,  cudaFuncAttributeMaxDynamicSharedMemorySize, H2_SMEM_BYTES);
    cudaFuncSetAttribute(mma_out,     cudaFuncAttributeMaxDynamicSharedMemorySize, H1_SMEM_BYTES);

    // input prep
    dim3 tthr(32, 8);
    transpose_split<<<dim3(NN / 32, CC / 32, BB), tthr>>>(x,   xt_hi, xt_lo, xt_h);
    transpose_split<<<dim3(NN / 32, CC / 32, BB), tthr>>>(dep, dt_hi, dt_lo, (__half*)nullptr);
    weight_split<<<(256 * 512 + 255) / 256, 256>>>(wq, wk, wqd, wkd,
                                                   wqk_hi, wqk_lo, wqkd_hi, wqkd_lo);
    wv_split<<<(512 * 512 + 255) / 256, 256>>>(wv, wv_hi, wv_lo);

    // projections
    mma_proj_qk<<<dim3(NN / 128, 2, BB), 256, MMA_SMEM_BYTES>>>(
        xt_hi, xt_lo, dt_hi, dt_lo, wqk_hi, wqk_lo, wqkd_hi, wqkd_lo,
        bq, bk, bqd, bkd, qhi, qlo, kk);
    mma_proj_v<<<dim3(NN / 128, CC / 128, BB), 256, H2_SMEM_BYTES>>>(
        wv_hi, wv_lo, xt_h, bv, vv);

    // energy (2-pass fp16, occ 2)
    mma_energy<<<dim3(NN / 128, NN / 128, BB), 256, H2_SMEM_BYTES>>>(qhi, qlo, kk, e);

    // softmax -> fp16 exp + 1/rowsum
    softmax_rows<<<BB * NN, 256>>>(e, p, s);

    // out (1-pass fp16, occ 2)
    mma_out<<<dim3(CC / 128, NN / 128, BB), 256, H1_SMEM_BYTES>>>(vv, p, x, gamma, s, out);
}

// round 15
// speedup vs baseline: 2.9120x; 1.0153x over previous
#include <cuda_runtime.h>
#include <cuda_bf16.h>
#include <cuda_fp16.h>
#include <cstdint>

#define BB 4
#define CC 512
#define CQ 64
#define DD 128   // 2*CQ
#define NN 4096  // H*W

// ---------------- scratch (device globals; no allocations allowed) ----------
__device__ __align__(256) __nv_bfloat16 g_xt_hi[BB * NN * CC];  // x^T [b][n][c] bf16 hi/lo
__device__ __align__(256) __nv_bfloat16 g_xt_lo[BB * NN * CC];
__device__ __align__(256) __half        g_xt_h[BB * NN * CC];   // x^T fp16 single
__device__ __align__(256) __nv_bfloat16 g_dt_hi[BB * NN * CC];  // dep^T bf16 hi/lo
__device__ __align__(256) __nv_bfloat16 g_dt_lo[BB * NN * CC];
__device__ __align__(256) __nv_bfloat16 g_wqk_hi[DD * CC];      // wq rows 0-63, wk 64-127
__device__ __align__(256) __nv_bfloat16 g_wqk_lo[DD * CC];
__device__ __align__(256) __nv_bfloat16 g_wqkd_hi[DD * CC];
__device__ __align__(256) __nv_bfloat16 g_wqkd_lo[DD * CC];
__device__ __align__(256) __half g_wv_hi[CC * CC];              // wv fp16 hi/lo
__device__ __align__(256) __half g_wv_lo[CC * CC];
__device__ __align__(256) __half g_qhi[BB * NN * DD];           // [b][i][d] fp16 hi/lo
__device__ __align__(256) __half g_qlo[BB * NN * DD];
__device__ __align__(256) __half g_k[BB * NN * DD];             // [b][j][d] fp16 single
__device__ __align__(256) __half g_v[BB * CC * NN];             // [b][c][n] fp16 single
__device__ __align__(256) float g_e[(size_t)BB * NN * NN];
__device__ __align__(256) __half g_p[(size_t)BB * NN * NN];     // exp, fp16 single
__device__ __align__(256) float g_s[BB * NN];

// ---------------- low-level helpers -----------------------------------------
__device__ __forceinline__ uint32_t smem_to_u32(const void* p) {
    uint32_t a;
    asm("{ .reg .u64 t; cvta.to.shared.u64 t, %1; cvt.u32.u64 %0, t; }" : "=r"(a) : "l"(p));
    return a;
}
#define SWZ(off) ((off) ^ (((off) >> 3) & 0x70))

__device__ __forceinline__ void cp16(uint32_t dst, const void* src) {
    asm volatile("cp.async.cg.shared.global [%0], [%1], 16;" :: "r"(dst), "l"(src));
}
__device__ __forceinline__ void cp_commit() {
    asm volatile("cp.async.commit_group;" ::: "memory");
}
__device__ __forceinline__ void ldsm4(uint32_t r[4], uint32_t addr) {
    asm volatile("ldmatrix.sync.aligned.m8n8.x4.shared.b16 {%0,%1,%2,%3}, [%4];"
                 : "=r"(r[0]), "=r"(r[1]), "=r"(r[2]), "=r"(r[3]) : "r"(addr));
}
__device__ __forceinline__ void mma_bf16(float acc[4], const uint32_t a[4],
                                         uint32_t b0, uint32_t b1) {
    asm volatile("mma.sync.aligned.m16n8k16.row.col.f32.bf16.bf16.f32 "
                 "{%0,%1,%2,%3}, {%4,%5,%6,%7}, {%8,%9}, {%0,%1,%2,%3};"
                 : "+f"(acc[0]), "+f"(acc[1]), "+f"(acc[2]), "+f"(acc[3])
                 : "r"(a[0]), "r"(a[1]), "r"(a[2]), "r"(a[3]), "r"(b0), "r"(b1));
}
__device__ __forceinline__ void mma_f16(float acc[4], const uint32_t a[4],
                                        uint32_t b0, uint32_t b1) {
    asm volatile("mma.sync.aligned.m16n8k16.row.col.f32.f16.f16.f32 "
                 "{%0,%1,%2,%3}, {%4,%5,%6,%7}, {%8,%9}, {%0,%1,%2,%3};"
                 : "+f"(acc[0]), "+f"(acc[1]), "+f"(acc[2]), "+f"(acc[3])
                 : "r"(a[0]), "r"(a[1]), "r"(a[2]), "r"(a[3]), "r"(b0), "r"(b1));
}
__device__ __forceinline__ void split_store2_h(float v0, float v1,
                                               __half* dh, __half* dl)
{
    __half h0 = __float2half_rn(v0), h1 = __float2half_rn(v1);
    __half l0 = __float2half_rn(v0 - __half2float(h0));
    __half l1 = __float2half_rn(v1 - __half2float(h1));
    __half2 H; H.x = h0; H.y = h1;
    __half2 L; L.x = l0; L.y = l1;
    *(__half2*)dh = H;
    *(__half2*)dl = L;
}
__device__ __forceinline__ void store2_h(float v0, float v1, __half* d)
{
    __half2 H; H.x = __float2half_rn(v0); H.y = __float2half_rn(v1);
    *(__half2*)d = H;
}

// ---------------- 3-pass split-bf16 machinery (R8-proven, EXACT) -------------
#define STG 65536
#define MMA_SMEM_BYTES (2 * STG)

__device__ __forceinline__ void stage_load(
    const __nv_bfloat16* __restrict__ Ahi, const __nv_bfloat16* __restrict__ Alo,
    size_t aStr,
    const __nv_bfloat16* __restrict__ Bhi, const __nv_bfloat16* __restrict__ Blo,
    size_t bStr, int kt, uint32_t stageU32, int t)
{
#pragma unroll
    for (int i = 0; i < 4; i++) {
        const int id = t + i * 256;
        const int row = id >> 3, c16 = id & 7;
        const uint32_t doff = SWZ((uint32_t)(row * 128 + c16 * 16));
        const size_t so = (size_t)row * aStr + kt + c16 * 8;
        cp16(stageU32 + doff,          Ahi + so);
        cp16(stageU32 + 16384 + doff,  Alo + so);
        const size_t sb = (size_t)row * bStr + kt + c16 * 8;
        cp16(stageU32 + 32768 + doff,  Bhi + sb);
        cp16(stageU32 + 49152 + doff,  Blo + sb);
    }
}

__device__ __forceinline__ void stage_compute(uint32_t stageU32, int wid, int lane,
                                              float acc[4][4][4])
{
    const int warp_row = wid >> 2;
    const int warp_col = wid & 3;
    const int lrow = lane & 15;
    const int chalf = (lane >= 16) ? 16 : 0;

#pragma unroll
    for (int ks = 0; ks < 4; ks++) {
        const uint32_t bcol = ks * 32 + chalf;
        uint32_t ahi[4][4], alo[4][4];
#pragma unroll
        for (int mi = 0; mi < 4; mi++) {
            const uint32_t off = SWZ((uint32_t)((warp_row * 64 + mi * 16 + lrow) * 128 + bcol));
            ldsm4(ahi[mi], stageU32 + off);
            ldsm4(alo[mi], stageU32 + 16384 + off);
        }
        uint32_t bhi[2][4], blo[2][4];
#pragma unroll
        for (int nh = 0; nh < 2; nh++) {
            const uint32_t off = SWZ((uint32_t)((warp_col * 32 + nh * 16 + lrow) * 128 + bcol));
            ldsm4(bhi[nh], stageU32 + 32768 + off);
            ldsm4(blo[nh], stageU32 + 49152 + off);
        }
#pragma unroll
        for (int mi = 0; mi < 4; mi++)
#pragma unroll
            for (int ni = 0; ni < 4; ni++) {
                const int nh = ni >> 1, s = ni & 1;
                mma_bf16(acc[mi][ni], ahi[mi], bhi[nh][s], bhi[nh][s + 2]);
                mma_bf16(acc[mi][ni], alo[mi], bhi[nh][s], bhi[nh][s + 2]);
                mma_bf16(acc[mi][ni], ahi[mi], blo[nh][s], blo[nh][s + 2]);
            }
    }
}

template <int KCHUNKS>
__device__ __forceinline__ void mma_mainloop(
    const __nv_bfloat16* Ahi, const __nv_bfloat16* Alo, size_t aStr,
    const __nv_bfloat16* Bhi, const __nv_bfloat16* Blo, size_t bStr,
    uint32_t smemU32, int t, int wid, int lane, float acc[4][4][4])
{
    stage_load(Ahi, Alo, aStr, Bhi, Blo, bStr, 0, smemU32, t);
    cp_commit();
    for (int c = 0; c < KCHUNKS; c++) {
        const bool more = (c + 1) < KCHUNKS;
        if (more) {
            stage_load(Ahi, Alo, aStr, Bhi, Blo, bStr, (c + 1) * 64,
                       smemU32 + ((c + 1) & 1) * STG, t);
            cp_commit();
            asm volatile("cp.async.wait_group 1;" ::: "memory");
        } else {
            asm volatile("cp.async.wait_group 0;" ::: "memory");
        }
        __syncthreads();
        stage_compute(smemU32 + (c & 1) * STG, wid, lane, acc);
        __syncthreads();
    }
}

// ---------------- 2-pass split-fp16 (R10-proven, EXACT): A hi/lo, B single ---
#define STG_H 49152
#define H2_SMEM_BYTES (2 * STG_H)

__device__ __forceinline__ void stage_load_h(
    const __half* __restrict__ Ahi, const __half* __restrict__ Alo, size_t aStr,
    const __half* __restrict__ B, size_t bStr, int kt, uint32_t stg, int t)
{
#pragma unroll
    for (int i = 0; i < 4; i++) {
        const int id = t + i * 256;
        const int row = id >> 3, c16 = id & 7;
        const uint32_t doff = SWZ((uint32_t)(row * 128 + c16 * 16));
        const size_t so = (size_t)row * aStr + kt + c16 * 8;
        cp16(stg + doff,          Ahi + so);
        cp16(stg + 16384 + doff,  Alo + so);
        const size_t sb = (size_t)row * bStr + kt + c16 * 8;
        cp16(stg + 32768 + doff,  B + sb);
    }
}

__device__ __forceinline__ void stage_compute_h(uint32_t stg, int wid, int lane,
                                                float acc[4][4][4])
{
    const int warp_row = wid >> 2;
    const int warp_col = wid & 3;
    const int lrow = lane & 15;
    const int chalf = (lane >= 16) ? 16 : 0;

#pragma unroll
    for (int ks = 0; ks < 4; ks++) {
        const uint32_t bcol = ks * 32 + chalf;
        uint32_t ahi[4][4], alo[4][4];
#pragma unroll
        for (int mi = 0; mi < 4; mi++) {
            const uint32_t off = SWZ((uint32_t)((warp_row * 64 + mi * 16 + lrow) * 128 + bcol));
            ldsm4(ahi[mi], stg + off);
            ldsm4(alo[mi], stg + 16384 + off);
        }
        uint32_t bp[2][4];
#pragma unroll
        for (int nh = 0; nh < 2; nh++) {
            const uint32_t off = SWZ((uint32_t)((warp_col * 32 + nh * 16 + lrow) * 128 + bcol));
            ldsm4(bp[nh], stg + 32768 + off);
        }
#pragma unroll
        for (int mi = 0; mi < 4; mi++)
#pragma unroll
            for (int ni = 0; ni < 4; ni++) {
                const int nh = ni >> 1, s = ni & 1;
                mma_f16(acc[mi][ni], ahi[mi], bp[nh][s], bp[nh][s + 2]);
                mma_f16(acc[mi][ni], alo[mi], bp[nh][s], bp[nh][s + 2]);
            }
    }
}

template <int KCHUNKS>
__device__ __forceinline__ void mma_mainloop_h(
    const __half* Ahi, const __half* Alo, size_t aStr,
    const __half* B, size_t bStr,
    uint32_t smemU32, int t, int wid, int lane, float acc[4][4][4])
{
    stage_load_h(Ahi, Alo, aStr, B, bStr, 0, smemU32, t);
    cp_commit();
    for (int c = 0; c < KCHUNKS; c++) {
        const bool more = (c + 1) < KCHUNKS;
        if (more) {
            stage_load_h(Ahi, Alo, aStr, B, bStr, (c + 1) * 64,
                         smemU32 + ((c + 1) & 1) * STG_H, t);
            cp_commit();
            asm volatile("cp.async.wait_group 1;" ::: "memory");
        } else {
            asm volatile("cp.async.wait_group 0;" ::: "memory");
        }
        __syncthreads();
        stage_compute_h(smemU32 + (c & 1) * STG_H, wid, lane, acc);
        __syncthreads();
    }
}

// ---------------- 1-pass fp16 (R11-proven): A single, B single ---------------
#define STG_1 32768
#define H1_SMEM_BYTES (2 * STG_1)

__device__ __forceinline__ void stage_load_1(
    const __half* __restrict__ A, size_t aStr,
    const __half* __restrict__ B, size_t bStr, int kt, uint32_t stg, int t)
{
#pragma unroll
    for (int i = 0; i < 4; i++) {
        const int id = t + i * 256;
        const int row = id >> 3, c16 = id & 7;
        const uint32_t doff = SWZ((uint32_t)(row * 128 + c16 * 16));
        cp16(stg + doff,          A + (size_t)row * aStr + kt + c16 * 8);
        cp16(stg + 16384 + doff,  B + (size_t)row * bStr + kt + c16 * 8);
    }
}

__device__ __forceinline__ void stage_compute_1(uint32_t stg, int wid, int lane,
                                                float acc[4][4][4])
{
    const int warp_row = wid >> 2;
    const int warp_col = wid & 3;
    const int lrow = lane & 15;
    const int chalf = (lane >= 16) ? 16 : 0;

#pragma unroll
    for (int ks = 0; ks < 4; ks++) {
        const uint32_t bcol = ks * 32 + chalf;
        uint32_t a[4][4];
#pragma unroll
        for (int mi = 0; mi < 4; mi++) {
            const uint32_t off = SWZ((uint32_t)((warp_row * 64 + mi * 16 + lrow) * 128 + bcol));
            ldsm4(a[mi], stg + off);
        }
        uint32_t bp[2][4];
#pragma unroll
        for (int nh = 0; nh < 2; nh++) {
            const uint32_t off = SWZ((uint32_t)((warp_col * 32 + nh * 16 + lrow) * 128 + bcol));
            ldsm4(bp[nh], stg + 16384 + off);
        }
#pragma unroll
        for (int mi = 0; mi < 4; mi++)
#pragma unroll
            for (int ni = 0; ni < 4; ni++) {
                const int nh = ni >> 1, s = ni & 1;
                mma_f16(acc[mi][ni], a[mi], bp[nh][s], bp[nh][s + 2]);
            }
    }
}

template <int KCHUNKS>
__device__ __forceinline__ void mma_mainloop_1(
    const __half* A, size_t aStr, const __half* B, size_t bStr,
    uint32_t smemU32, int t, int wid, int lane, float acc[4][4][4])
{
    stage_load_1(A, aStr, B, bStr, 0, smemU32, t);
    cp_commit();
    for (int c = 0; c < KCHUNKS; c++) {
        const bool more = (c + 1) < KCHUNKS;
        if (more) {
            stage_load_1(A, aStr, B, bStr, (c + 1) * 64,
                         smemU32 + ((c + 1) & 1) * STG_1, t);
            cp_commit();
            asm volatile("cp.async.wait_group 1;" ::: "memory");
        } else {
            asm volatile("cp.async.wait_group 0;" ::: "memory");
        }
        __syncthreads();
        stage_compute_1(smemU32 + (c & 1) * STG_1, wid, lane, acc);
        __syncthreads();
    }
}

// ============================================================================
// transpose + split: src [b][C][N] fp32 -> dst [b][N][C] bf16 hi/lo
//                    (+ optional fp16 single output for the v-proj B operand)
// ============================================================================
__global__ void __launch_bounds__(256)
transpose_split(const float* __restrict__ src,
                __nv_bfloat16* __restrict__ dhi, __nv_bfloat16* __restrict__ dlo,
                __half* __restrict__ dh16)
{
    __shared__ float tile[32][33];
    const int b = blockIdx.z;
    const int n0 = blockIdx.x * 32, c0 = blockIdx.y * 32;
    const int tx = threadIdx.x, ty = threadIdx.y;   // (32, 8)
    const float* S = src + (size_t)b * CC * NN;
#pragma unroll
    for (int i = 0; i < 4; i++)
        tile[ty * 4 + i][tx] = S[(size_t)(c0 + ty * 4 + i) * NN + n0 + tx];
    __syncthreads();
    __nv_bfloat16* H = dhi + (size_t)b * NN * CC;
    __nv_bfloat16* L = dlo + (size_t)b * NN * CC;
    __half* H16 = dh16 ? dh16 + (size_t)b * NN * CC : nullptr;
#pragma unroll
    for (int i = 0; i < 4; i++) {
        const float f = tile[tx][ty * 4 + i];
        const __nv_bfloat16 h = __float2bfloat16(f);
        const __nv_bfloat16 l = __float2bfloat16(f - __bfloat162float(h));
        const size_t idx = (size_t)(n0 + ty * 4 + i) * CC + c0 + tx;
        H[idx] = h;
        L[idx] = l;
        if (H16) H16[idx] = __float2half_rn(f);
    }
}

// ============================================================================
// weight split: the four q/k weights -> bf16 hi/lo (256 rows total)
// ============================================================================
__global__ void __launch_bounds__(256)
weight_split(const float* __restrict__ wq, const float* __restrict__ wk,
             const float* __restrict__ wqd, const float* __restrict__ wkd,
             __nv_bfloat16* __restrict__ wqk_hi, __nv_bfloat16* __restrict__ wqk_lo,
             __nv_bfloat16* __restrict__ wqkd_hi, __nv_bfloat16* __restrict__ wqkd_lo)
{
    const int idx = blockIdx.x * 256 + threadIdx.x;
    if (idx >= 256 * 512) return;
    const int row = idx >> 9, col = idx & 511;
    const float* src;
    __nv_bfloat16 *dh, *dl;
    int drow;
    if (row < 64)       { src = wq  + (size_t)row * 512;         dh = wqk_hi;  dl = wqk_lo;  drow = row; }
    else if (row < 128) { src = wk  + (size_t)(row - 64) * 512;  dh = wqk_hi;  dl = wqk_lo;  drow = row; }
    else if (row < 192) { src = wqd + (size_t)(row - 128) * 512; dh = wqkd_hi; dl = wqkd_lo; drow = row - 128; }
    else                { src = wkd + (size_t)(row - 192) * 512; dh = wqkd_hi; dl = wqkd_lo; drow = row - 128; }
    const float f = src[col];
    const __nv_bfloat16 h = __float2bfloat16(f);
    dh[(size_t)drow * 512 + col] = h;
    dl[(size_t)drow * 512 + col] = __float2bfloat16(f - __bfloat162float(h));
}

// wv -> fp16 hi/lo
__global__ void __launch_bounds__(256)
wv_split(const float* __restrict__ wv,
         __half* __restrict__ wv_hi, __half* __restrict__ wv_lo)
{
    const int idx = blockIdx.x * 256 + threadIdx.x;
    if (idx >= 512 * 512) return;
    const float f = wv[idx];
    const __half h = __float2half_rn(f);
    wv_hi[idx] = h;
    wv_lo[idx] = __float2half_rn(f - __half2float(h));
}

// ============================================================================
// proj qk (merged x/dep via blockIdx.y): [n][d] = in[n][c] . w[d][c]
// q -> fp16 hi/lo, k -> fp16 single.  bf16 3-pass, occ 1 (exp-sensitive path).
// ============================================================================
__global__ void __launch_bounds__(256, 1)
mma_proj_qk(const __nv_bfloat16* __restrict__ xt_hi, const __nv_bfloat16* __restrict__ xt_lo,
            const __nv_bfloat16* __restrict__ dt_hi, const __nv_bfloat16* __restrict__ dt_lo,
            const __nv_bfloat16* __restrict__ wqk_hi, const __nv_bfloat16* __restrict__ wqk_lo,
            const __nv_bfloat16* __restrict__ wqkd_hi, const __nv_bfloat16* __restrict__ wqkd_lo,
            const float* __restrict__ bq, const float* __restrict__ bk,
            const float* __restrict__ bqd, const float* __restrict__ bkd,
            __half* __restrict__ Qhi, __half* __restrict__ Qlo,
            __half* __restrict__ K)
{
    extern __shared__ char smem[];
    const uint32_t smemU32 = smem_to_u32(smem);
    const int t = threadIdx.x, wid = t >> 5, lane = t & 31;
    const int b = blockIdx.z;
    const int i0 = blockIdx.x * 128;
    const int sel = blockIdx.y;   // 0 = x path (d 0-63), 1 = dep path (d 64-127)

    const __nv_bfloat16* Ahi = sel ? dt_hi : xt_hi;
    const __nv_bfloat16* Alo = sel ? dt_lo : xt_lo;
    const __nv_bfloat16* Whi = sel ? wqkd_hi : wqk_hi;
    const __nv_bfloat16* Wlo = sel ? wqkd_lo : wqk_lo;
    const float* bias_q = sel ? bqd : bq;
    const float* bias_k = sel ? bkd : bk;
    const int d_off = sel ? CQ : 0;

    const size_t aoff = ((size_t)b * NN + i0) * CC;
    float acc[4][4][4] = {};
    mma_mainloop<8>(Ahi + aoff, Alo + aoff, CC, Whi, Wlo, CC,
                    smemU32, t, wid, lane, acc);

    const int warp_col = wid & 3;
    const bool isK = warp_col >= 2;
    const float* bias = isK ? bias_k : bias_q;
    const int csub = isK ? 64 : 0;

    const int rbase = i0 + (wid >> 2) * 64 + (lane >> 2);
    const int cbase = warp_col * 32 + (lane & 3) * 2;
#pragma unroll
    for (int mi = 0; mi < 4; mi++)
#pragma unroll
        for (int ni = 0; ni < 4; ni++) {
            const int col = cbase + ni * 8 - csub;   // 0..63
            const float2 bi = *(const float2*)&bias[col];
            const int r0 = rbase + mi * 16;
            const size_t a0 = ((size_t)b * NN + r0) * DD + d_off + col;
            const size_t a1 = ((size_t)b * NN + r0 + 8) * DD + d_off + col;
            if (!isK) {
                split_store2_h(acc[mi][ni][0] + bi.x, acc[mi][ni][1] + bi.y, Qhi + a0, Qlo + a0);
                split_store2_h(acc[mi][ni][2] + bi.x, acc[mi][ni][3] + bi.y, Qhi + a1, Qlo + a1);
            } else {
                store2_h(acc[mi][ni][0] + bi.x, acc[mi][ni][1] + bi.y, K + a0);
                store2_h(acc[mi][ni][2] + bi.x, acc[mi][ni][3] + bi.y, K + a1);
            }
        }
}

// ============================================================================
// proj v: [c][n] tile = wv[c][k] . xt[n][k]  -> fp16 single
// 2-pass split-fp16 (wv hi/lo fp16, xt single fp16), occ 2.
// ============================================================================
__global__ void __launch_bounds__(256, 2)
mma_proj_v(const __half* __restrict__ w_hi, const __half* __restrict__ w_lo,
           const __half* __restrict__ xt_h,
           const float* __restrict__ bias,
           __half* __restrict__ V)
{
    extern __shared__ char smem[];
    const uint32_t smemU32 = smem_to_u32(smem);
    const int t = threadIdx.x, wid = t >> 5, lane = t & 31;
    const int b = blockIdx.z;
    const int n0 = blockIdx.x * 128, m0 = blockIdx.y * 128;

    const size_t boff = ((size_t)b * NN + n0) * CC;
    float acc[4][4][4] = {};
    mma_mainloop_h<8>(w_hi + (size_t)m0 * CC, w_lo + (size_t)m0 * CC, CC,
                      xt_h + boff, CC,
                      smemU32, t, wid, lane, acc);

    const int rbase = m0 + (wid >> 2) * 64 + (lane >> 2);
    const int cbase = n0 + (wid & 3) * 32 + (lane & 3) * 2;
#pragma unroll
    for (int mi = 0; mi < 4; mi++) {
        const int ch0 = rbase + mi * 16;
        const float bi0 = bias[ch0], bi1 = bias[ch0 + 8];
#pragma unroll
        for (int ni = 0; ni < 4; ni++) {
            const int cn = cbase + ni * 8;
            store2_h(acc[mi][ni][0] + bi0, acc[mi][ni][1] + bi0,
                     V + ((size_t)b * CC + ch0) * NN + cn);
            store2_h(acc[mi][ni][2] + bi1, acc[mi][ni][3] + bi1,
                     V + ((size_t)b * CC + ch0 + 8) * NN + cn);
        }
    }
}

// ============================================================================
// Energy: E[b][i][j] = sum_d q[i][d] k[j][d]  (2-pass fp16; occ 2)
// ============================================================================
__global__ void __launch_bounds__(256, 2)
mma_energy(const __half* __restrict__ qhi, const __half* __restrict__ qlo,
           const __half* __restrict__ k,
           float* __restrict__ E)
{
    extern __shared__ char smem[];
    const uint32_t smemU32 = smem_to_u32(smem);
    const int t = threadIdx.x, wid = t >> 5, lane = t & 31;
    const int b = blockIdx.z;
    const int i0 = blockIdx.y * 128, j0 = blockIdx.x * 128;

    const size_t aoff = ((size_t)b * NN + i0) * DD;
    const size_t boff = ((size_t)b * NN + j0) * DD;

    float acc[4][4][4] = {};
    mma_mainloop_h<2>(qhi + aoff, qlo + aoff, DD, k + boff, DD,
                      smemU32, t, wid, lane, acc);

    float* Eb = E + (size_t)b * NN * NN;
    const int rbase = i0 + (wid >> 2) * 64 + (lane >> 2);
    const int cbase = j0 + (wid & 3) * 32 + (lane & 3) * 2;
#pragma unroll
    for (int mi = 0; mi < 4; mi++)
#pragma unroll
        for (int ni = 0; ni < 4; ni++) {
            const int r = rbase + mi * 16;
            const int cjj = cbase + ni * 8;
            *(float2*)&Eb[(size_t)r * NN + cjj]       = make_float2(acc[mi][ni][0], acc[mi][ni][1]);
            *(float2*)&Eb[(size_t)(r + 8) * NN + cjj] = make_float2(acc[mi][ni][2], acc[mi][ni][3]);
        }
}

// ============================================================================
// Out: out[b][c][i] = g * (sum_j v[c][j] p[i][j]) * inv[i] + x[c][i]
// 1-pass fp16, occ 2.
// ============================================================================
__global__ void __launch_bounds__(256, 2)
mma_out(const __half* __restrict__ v, const __half* __restrict__ p,
        const float* __restrict__ X, const float* __restrict__ gamma,
        const float* __restrict__ invs, float* __restrict__ Out)
{
    extern __shared__ char smem[];
    const uint32_t smemU32 = smem_to_u32(smem);
    const int t = threadIdx.x, wid = t >> 5, lane = t & 31;
    const int b = blockIdx.z;
    const int c0 = blockIdx.x * 128, i0 = blockIdx.y * 128;

    const size_t aoff = ((size_t)b * CC + c0) * NN;
    const size_t boff = ((size_t)b * NN + i0) * NN;

    float acc[4][4][4] = {};
    mma_mainloop_1<64>(v + aoff, NN, p + boff, NN, smemU32, t, wid, lane, acc);

    const float g = __ldg(gamma);
    const int rbase = c0 + (wid >> 2) * 64 + (lane >> 2);
    const int cbase = i0 + (wid & 3) * 32 + (lane & 3) * 2;
    const float* ivb = invs + b * NN;
#pragma unroll
    for (int mi = 0; mi < 4; mi++)
#pragma unroll
        for (int ni = 0; ni < 4; ni++) {
            const int ch = rbase + mi * 16;
            const int ci = cbase + ni * 8;
            const float2 iv = *(const float2*)&ivb[ci];
            {
                const size_t idx = ((size_t)b * CC + ch) * NN + ci;
                const float2 xv = *(const float2*)&X[idx];
                float2 o;
                o.x = g * acc[mi][ni][0] * iv.x + xv.x;
                o.y = g * acc[mi][ni][1] * iv.y + xv.y;
                *(float2*)&Out[idx] = o;
            }
            {
                const size_t idx = ((size_t)b * CC + ch + 8) * NN + ci;
                const float2 xv = *(const float2*)&X[idx];
                float2 o;
                o.x = g * acc[mi][ni][2] * iv.x + xv.x;
                o.y = g * acc[mi][ni][3] * iv.y + xv.y;
                *(float2*)&Out[idx] = o;
            }
        }
}

// ============================================================================
// Softmax: fp32 energy row -> unnormalized exp fp16 + 1/rowsum
// ============================================================================
__global__ void __launch_bounds__(256)
softmax_rows(const float* __restrict__ E,
             __half* __restrict__ P, float* __restrict__ invs)
{
    __shared__ float red[8];
    const float4* E4 = (const float4*)E;
    const size_t base4 = (size_t)blockIdx.x * (NN / 4);
    const int tid = threadIdx.x;
    const int lane = tid & 31, wid = tid >> 5;

    float4 v[4];
#pragma unroll
    for (int u = 0; u < 4; u++) v[u] = E4[base4 + u * 256 + tid];

    float m = -1e30f;
#pragma unroll
    for (int u = 0; u < 4; u++)
        m = fmaxf(m, fmaxf(fmaxf(v[u].x, v[u].y), fmaxf(v[u].z, v[u].w)));
#pragma unroll
    for (int off = 16; off > 0; off >>= 1)
        m = fmaxf(m, __shfl_xor_sync(0xffffffffu, m, off));
    if (lane == 0) red[wid] = m;
    __syncthreads();
    m = red[0];
#pragma unroll
    for (int w = 1; w < 8; w++) m = fmaxf(m, red[w]);
    __syncthreads();

    float s = 0.f;
#pragma unroll
    for (int u = 0; u < 4; u++) {
        v[u].x = __expf(v[u].x - m); v[u].y = __expf(v[u].y - m);
        v[u].z = __expf(v[u].z - m); v[u].w = __expf(v[u].w - m);
        s += v[u].x + v[u].y + v[u].z + v[u].w;
    }
#pragma unroll
    for (int off = 16; off > 0; off >>= 1)
        s += __shfl_xor_sync(0xffffffffu, s, off);
    if (lane == 0) red[wid] = s;
    __syncthreads();
    s = red[0];
#pragma unroll
    for (int w = 1; w < 8; w++) s += red[w];

#pragma unroll
    for (int u = 0; u < 4; u++) {
        const size_t el = base4 * 4 + (u * 256 + tid) * 4;
        __half h[4];
        h[0] = __float2half_rn(v[u].x); h[1] = __float2half_rn(v[u].y);
        h[2] = __float2half_rn(v[u].z); h[3] = __float2half_rn(v[u].w);
        *(uint2*)&P[el] = *(uint2*)h;
    }
    if (tid == 0) invs[blockIdx.x] = 1.0f / s;
}

// ============================================================================

extern "C" void kernel_launch(void* const* d_in, const int* in_sizes, int n_in,
                              void* d_out, int out_size)
{
    const float* x     = (const float*)d_in[0];
    const float* dep   = (const float*)d_in[1];
    const float* wq    = (const float*)d_in[2];
    const float* bq    = (const float*)d_in[3];
    const float* wqd   = (const float*)d_in[4];
    const float* bqd   = (const float*)d_in[5];
    const float* wk    = (const float*)d_in[6];
    const float* bk    = (const float*)d_in[7];
    const float* wkd   = (const float*)d_in[8];
    const float* bkd   = (const float*)d_in[9];
    const float* wv    = (const float*)d_in[10];
    const float* bv    = (const float*)d_in[11];
    const float* gamma = (const float*)d_in[12];
    float* out = (float*)d_out;

    __nv_bfloat16 *xt_hi, *xt_lo, *dt_hi, *dt_lo;
    __nv_bfloat16 *wqk_hi, *wqk_lo, *wqkd_hi, *wqkd_lo;
    __half *xt_h, *wv_hi, *wv_lo;
    __half *qhi, *qlo, *kk, *vv, *p;
    float *e, *s;
    cudaGetSymbolAddress((void**)&xt_hi, g_xt_hi);
    cudaGetSymbolAddress((void**)&xt_lo, g_xt_lo);
    cudaGetSymbolAddress((void**)&xt_h,  g_xt_h);
    cudaGetSymbolAddress((void**)&dt_hi, g_dt_hi);
    cudaGetSymbolAddress((void**)&dt_lo, g_dt_lo);
    cudaGetSymbolAddress((void**)&wqk_hi, g_wqk_hi);
    cudaGetSymbolAddress((void**)&wqk_lo, g_wqk_lo);
    cudaGetSymbolAddress((void**)&wqkd_hi, g_wqkd_hi);
    cudaGetSymbolAddress((void**)&wqkd_lo, g_wqkd_lo);
    cudaGetSymbolAddress((void**)&wv_hi, g_wv_hi);
    cudaGetSymbolAddress((void**)&wv_lo, g_wv_lo);
    cudaGetSymbolAddress((void**)&qhi, g_qhi);
    cudaGetSymbolAddress((void**)&qlo, g_qlo);
    cudaGetSymbolAddress((void**)&kk, g_k);
    cudaGetSymbolAddress((void**)&vv, g_v);
    cudaGetSymbolAddress((void**)&p, g_p);
    cudaGetSymbolAddress((void**)&e, g_e);
    cudaGetSymbolAddress((void**)&s, g_s);

    cudaFuncSetAttribute(mma_proj_qk, cudaFuncAttributeMaxDynamicSharedMemorySize, MMA_SMEM_BYTES);
    cudaFuncSetAttribute(mma_proj_v,  cudaFuncAttributeMaxDynamicSharedMemorySize, H2_SMEM_BYTES);
    cudaFuncSetAttribute(mma_energy,  cudaFuncAttributeMaxDynamicSharedMemorySize, H2_SMEM_BYTES);
    cudaFuncSetAttribute(mma_out,     cudaFuncAttributeMaxDynamicSharedMemorySize, H1_SMEM_BYTES);

    // Side stream + fork/join events (host objects; created per call, capturable).
    cudaStream_t sv;
    cudaStreamCreateWithFlags(&sv, cudaStreamNonBlocking);
    cudaEvent_t evRoot, evX, evV;
    cudaEventCreateWithFlags(&evRoot, cudaEventDisableTiming);
    cudaEventCreateWithFlags(&evX,    cudaEventDisableTiming);
    cudaEventCreateWithFlags(&evV,    cudaEventDisableTiming);

    // Fork: side stream joins the capture graph.
    cudaEventRecord(evRoot, 0);
    cudaStreamWaitEvent(sv, evRoot, 0);

    // Side stream: wv split (no deps) runs immediately.
    wv_split<<<(512 * 512 + 255) / 256, 256, 0, sv>>>(wv, wv_hi, wv_lo);

    // Main stream: input prep.
    dim3 tthr(32, 8);
    transpose_split<<<dim3(NN / 32, CC / 32, BB), tthr>>>(x,   xt_hi, xt_lo, xt_h);
    cudaEventRecord(evX, 0);                 // xt_h ready
    transpose_split<<<dim3(NN / 32, CC / 32, BB), tthr>>>(dep, dt_hi, dt_lo, (__half*)nullptr);
    weight_split<<<(256 * 512 + 255) / 256, 256>>>(wq, wk, wqd, wkd,
                                                   wqk_hi, wqk_lo, wqkd_hi, wqkd_lo);

    // Side stream: proj v (needs xt_h + wv splits).
    cudaStreamWaitEvent(sv, evX, 0);
    mma_proj_v<<<dim3(NN / 128, CC / 128, BB), 256, H2_SMEM_BYTES, sv>>>(
        wv_hi, wv_lo, xt_h, bv, vv);
    cudaEventRecord(evV, sv);

    // Main stream: q/k projections -> energy -> softmax.
    mma_proj_qk<<<dim3(NN / 128, 2, BB), 256, MMA_SMEM_BYTES>>>(
        xt_hi, xt_lo, dt_hi, dt_lo, wqk_hi, wqk_lo, wqkd_hi, wqkd_lo,
        bq, bk, bqd, bkd, qhi, qlo, kk);
    mma_energy<<<dim3(NN / 128, NN / 128, BB), 256, H2_SMEM_BYTES>>>(qhi, qlo, kk, e);
    softmax_rows<<<BB * NN, 256>>>(e, p, s);

    // Join: out needs v from the side stream.
    cudaStreamWaitEvent(0, evV, 0);
    mma_out<<<dim3(CC / 128, NN / 128, BB), 256, H1_SMEM_BYTES>>>(vv, p, x, gamma, s, out);
}

// round 16
// speedup vs baseline: 3.2100x; 1.1023x over previous
#include <cuda_runtime.h>
#include <cuda_bf16.h>
#include <cuda_fp16.h>
#include <cstdint>

#define BB 4
#define CC 512
#define CQ 64
#define DD 128   // 2*CQ
#define NN 4096  // H*W

// ---------------- scratch (device globals; no allocations allowed) ----------
__device__ __align__(256) __nv_bfloat16 g_xt_hi[BB * NN * CC];  // x^T [b][n][c] bf16 hi/lo
__device__ __align__(256) __nv_bfloat16 g_xt_lo[BB * NN * CC];
__device__ __align__(256) __half        g_xt_h[BB * NN * CC];   // x^T fp16 single
__device__ __align__(256) __nv_bfloat16 g_dt_hi[BB * NN * CC];  // dep^T bf16 hi/lo
__device__ __align__(256) __nv_bfloat16 g_dt_lo[BB * NN * CC];
__device__ __align__(256) __nv_bfloat16 g_wqk_hi[DD * CC];      // wq rows 0-63, wk 64-127
__device__ __align__(256) __nv_bfloat16 g_wqk_lo[DD * CC];
__device__ __align__(256) __nv_bfloat16 g_wqkd_hi[DD * CC];
__device__ __align__(256) __nv_bfloat16 g_wqkd_lo[DD * CC];
__device__ __align__(256) __half g_wv_hi[CC * CC];              // wv fp16 hi/lo
__device__ __align__(256) __half g_wv_lo[CC * CC];
__device__ __align__(256) __half g_q[BB * NN * DD];             // [b][i][d] fp16 single
__device__ __align__(256) __half g_k[BB * NN * DD];             // [b][j][d] fp16 single
__device__ __align__(256) __half g_v[BB * CC * NN];             // [b][c][n] fp16 single
__device__ __align__(256) float g_e[(size_t)BB * NN * NN];
__device__ __align__(256) __half g_p[(size_t)BB * NN * NN];     // exp, fp16 single
__device__ __align__(256) float g_s[BB * NN];

// ---------------- low-level helpers -----------------------------------------
__device__ __forceinline__ uint32_t smem_to_u32(const void* p) {
    uint32_t a;
    asm("{ .reg .u64 t; cvta.to.shared.u64 t, %1; cvt.u32.u64 %0, t; }" : "=r"(a) : "l"(p));
    return a;
}
#define SWZ(off) ((off) ^ (((off) >> 3) & 0x70))

__device__ __forceinline__ void cp16(uint32_t dst, const void* src) {
    asm volatile("cp.async.cg.shared.global [%0], [%1], 16;" :: "r"(dst), "l"(src));
}
__device__ __forceinline__ void cp_commit() {
    asm volatile("cp.async.commit_group;" ::: "memory");
}
__device__ __forceinline__ void ldsm4(uint32_t r[4], uint32_t addr) {
    asm volatile("ldmatrix.sync.aligned.m8n8.x4.shared.b16 {%0,%1,%2,%3}, [%4];"
                 : "=r"(r[0]), "=r"(r[1]), "=r"(r[2]), "=r"(r[3]) : "r"(addr));
}
__device__ __forceinline__ void mma_bf16(float acc[4], const uint32_t a[4],
                                         uint32_t b0, uint32_t b1) {
    asm volatile("mma.sync.aligned.m16n8k16.row.col.f32.bf16.bf16.f32 "
                 "{%0,%1,%2,%3}, {%4,%5,%6,%7}, {%8,%9}, {%0,%1,%2,%3};"
                 : "+f"(acc[0]), "+f"(acc[1]), "+f"(acc[2]), "+f"(acc[3])
                 : "r"(a[0]), "r"(a[1]), "r"(a[2]), "r"(a[3]), "r"(b0), "r"(b1));
}
__device__ __forceinline__ void mma_f16(float acc[4], const uint32_t a[4],
                                        uint32_t b0, uint32_t b1) {
    asm volatile("mma.sync.aligned.m16n8k16.row.col.f32.f16.f16.f32 "
                 "{%0,%1,%2,%3}, {%4,%5,%6,%7}, {%8,%9}, {%0,%1,%2,%3};"
                 : "+f"(acc[0]), "+f"(acc[1]), "+f"(acc[2]), "+f"(acc[3])
                 : "r"(a[0]), "r"(a[1]), "r"(a[2]), "r"(a[3]), "r"(b0), "r"(b1));
}
__device__ __forceinline__ void store2_h(float v0, float v1, __half* d)
{
    __half2 H; H.x = __float2half_rn(v0); H.y = __float2half_rn(v1);
    *(__half2*)d = H;
}

// ---------------- 3-pass split-bf16 machinery (R8-proven, EXACT) -------------
#define STG 65536
#define MMA_SMEM_BYTES (2 * STG)

__device__ __forceinline__ void stage_load(
    const __nv_bfloat16* __restrict__ Ahi, const __nv_bfloat16* __restrict__ Alo,
    size_t aStr,
    const __nv_bfloat16* __restrict__ Bhi, const __nv_bfloat16* __restrict__ Blo,
    size_t bStr, int kt, uint32_t stageU32, int t)
{
#pragma unroll
    for (int i = 0; i < 4; i++) {
        const int id = t + i * 256;
        const int row = id >> 3, c16 = id & 7;
        const uint32_t doff = SWZ((uint32_t)(row * 128 + c16 * 16));
        const size_t so = (size_t)row * aStr + kt + c16 * 8;
        cp16(stageU32 + doff,          Ahi + so);
        cp16(stageU32 + 16384 + doff,  Alo + so);
        const size_t sb = (size_t)row * bStr + kt + c16 * 8;
        cp16(stageU32 + 32768 + doff,  Bhi + sb);
        cp16(stageU32 + 49152 + doff,  Blo + sb);
    }
}

__device__ __forceinline__ void stage_compute(uint32_t stageU32, int wid, int lane,
                                              float acc[4][4][4])
{
    const int warp_row = wid >> 2;
    const int warp_col = wid & 3;
    const int lrow = lane & 15;
    const int chalf = (lane >= 16) ? 16 : 0;

#pragma unroll
    for (int ks = 0; ks < 4; ks++) {
        const uint32_t bcol = ks * 32 + chalf;
        uint32_t ahi[4][4], alo[4][4];
#pragma unroll
        for (int mi = 0; mi < 4; mi++) {
            const uint32_t off = SWZ((uint32_t)((warp_row * 64 + mi * 16 + lrow) * 128 + bcol));
            ldsm4(ahi[mi], stageU32 + off);
            ldsm4(alo[mi], stageU32 + 16384 + off);
        }
        uint32_t bhi[2][4], blo[2][4];
#pragma unroll
        for (int nh = 0; nh < 2; nh++) {
            const uint32_t off = SWZ((uint32_t)((warp_col * 32 + nh * 16 + lrow) * 128 + bcol));
            ldsm4(bhi[nh], stageU32 + 32768 + off);
            ldsm4(blo[nh], stageU32 + 49152 + off);
        }
#pragma unroll
        for (int mi = 0; mi < 4; mi++)
#pragma unroll
            for (int ni = 0; ni < 4; ni++) {
                const int nh = ni >> 1, s = ni & 1;
                mma_bf16(acc[mi][ni], ahi[mi], bhi[nh][s], bhi[nh][s + 2]);
                mma_bf16(acc[mi][ni], alo[mi], bhi[nh][s], bhi[nh][s + 2]);
                mma_bf16(acc[mi][ni], ahi[mi], blo[nh][s], blo[nh][s + 2]);
            }
    }
}

template <int KCHUNKS>
__device__ __forceinline__ void mma_mainloop(
    const __nv_bfloat16* Ahi, const __nv_bfloat16* Alo, size_t aStr,
    const __nv_bfloat16* Bhi, const __nv_bfloat16* Blo, size_t bStr,
    uint32_t smemU32, int t, int wid, int lane, float acc[4][4][4])
{
    stage_load(Ahi, Alo, aStr, Bhi, Blo, bStr, 0, smemU32, t);
    cp_commit();
    for (int c = 0; c < KCHUNKS; c++) {
        const bool more = (c + 1) < KCHUNKS;
        if (more) {
            stage_load(Ahi, Alo, aStr, Bhi, Blo, bStr, (c + 1) * 64,
                       smemU32 + ((c + 1) & 1) * STG, t);
            cp_commit();
            asm volatile("cp.async.wait_group 1;" ::: "memory");
        } else {
            asm volatile("cp.async.wait_group 0;" ::: "memory");
        }
        __syncthreads();
        stage_compute(smemU32 + (c & 1) * STG, wid, lane, acc);
        __syncthreads();
    }
}

// ---------------- 2-pass split-fp16 (R10-proven, EXACT): A hi/lo, B single ---
#define STG_H 49152
#define H2_SMEM_BYTES (2 * STG_H)

__device__ __forceinline__ void stage_load_h(
    const __half* __restrict__ Ahi, const __half* __restrict__ Alo, size_t aStr,
    const __half* __restrict__ B, size_t bStr, int kt, uint32_t stg, int t)
{
#pragma unroll
    for (int i = 0; i < 4; i++) {
        const int id = t + i * 256;
        const int row = id >> 3, c16 = id & 7;
        const uint32_t doff = SWZ((uint32_t)(row * 128 + c16 * 16));
        const size_t so = (size_t)row * aStr + kt + c16 * 8;
        cp16(stg + doff,          Ahi + so);
        cp16(stg + 16384 + doff,  Alo + so);
        const size_t sb = (size_t)row * bStr + kt + c16 * 8;
        cp16(stg + 32768 + doff,  B + sb);
    }
}

__device__ __forceinline__ void stage_compute_h(uint32_t stg, int wid, int lane,
                                                float acc[4][4][4])
{
    const int warp_row = wid >> 2;
    const int warp_col = wid & 3;
    const int lrow = lane & 15;
    const int chalf = (lane >= 16) ? 16 : 0;

#pragma unroll
    for (int ks = 0; ks < 4; ks++) {
        const uint32_t bcol = ks * 32 + chalf;
        uint32_t ahi[4][4], alo[4][4];
#pragma unroll
        for (int mi = 0; mi < 4; mi++) {
            const uint32_t off = SWZ((uint32_t)((warp_row * 64 + mi * 16 + lrow) * 128 + bcol));
            ldsm4(ahi[mi], stg + off);
            ldsm4(alo[mi], stg + 16384 + off);
        }
        uint32_t bp[2][4];
#pragma unroll
        for (int nh = 0; nh < 2; nh++) {
            const uint32_t off = SWZ((uint32_t)((warp_col * 32 + nh * 16 + lrow) * 128 + bcol));
            ldsm4(bp[nh], stg + 32768 + off);
        }
#pragma unroll
        for (int mi = 0; mi < 4; mi++)
#pragma unroll
            for (int ni = 0; ni < 4; ni++) {
                const int nh = ni >> 1, s = ni & 1;
                mma_f16(acc[mi][ni], ahi[mi], bp[nh][s], bp[nh][s + 2]);
                mma_f16(acc[mi][ni], alo[mi], bp[nh][s], bp[nh][s + 2]);
            }
    }
}

template <int KCHUNKS>
__device__ __forceinline__ void mma_mainloop_h(
    const __half* Ahi, const __half* Alo, size_t aStr,
    const __half* B, size_t bStr,
    uint32_t smemU32, int t, int wid, int lane, float acc[4][4][4])
{
    stage_load_h(Ahi, Alo, aStr, B, bStr, 0, smemU32, t);
    cp_commit();
    for (int c = 0; c < KCHUNKS; c++) {
        const bool more = (c + 1) < KCHUNKS;
        if (more) {
            stage_load_h(Ahi, Alo, aStr, B, bStr, (c + 1) * 64,
                         smemU32 + ((c + 1) & 1) * STG_H, t);
            cp_commit();
            asm volatile("cp.async.wait_group 1;" ::: "memory");
        } else {
            asm volatile("cp.async.wait_group 0;" ::: "memory");
        }
        __syncthreads();
        stage_compute_h(smemU32 + (c & 1) * STG_H, wid, lane, acc);
        __syncthreads();
    }
}

// ---------------- 1-pass fp16 (R11-proven): A single, B single ---------------
#define STG_1 32768
#define H1_SMEM_BYTES (2 * STG_1)

__device__ __forceinline__ void stage_load_1(
    const __half* __restrict__ A, size_t aStr,
    const __half* __restrict__ B, size_t bStr, int kt, uint32_t stg, int t)
{
#pragma unroll
    for (int i = 0; i < 4; i++) {
        const int id = t + i * 256;
        const int row = id >> 3, c16 = id & 7;
        const uint32_t doff = SWZ((uint32_t)(row * 128 + c16 * 16));
        cp16(stg + doff,          A + (size_t)row * aStr + kt + c16 * 8);
        cp16(stg + 16384 + doff,  B + (size_t)row * bStr + kt + c16 * 8);
    }
}

__device__ __forceinline__ void stage_compute_1(uint32_t stg, int wid, int lane,
                                                float acc[4][4][4])
{
    const int warp_row = wid >> 2;
    const int warp_col = wid & 3;
    const int lrow = lane & 15;
    const int chalf = (lane >= 16) ? 16 : 0;

#pragma unroll
    for (int ks = 0; ks < 4; ks++) {
        const uint32_t bcol = ks * 32 + chalf;
        uint32_t a[4][4];
#pragma unroll
        for (int mi = 0; mi < 4; mi++) {
            const uint32_t off = SWZ((uint32_t)((warp_row * 64 + mi * 16 + lrow) * 128 + bcol));
            ldsm4(a[mi], stg + off);
        }
        uint32_t bp[2][4];
#pragma unroll
        for (int nh = 0; nh < 2; nh++) {
            const uint32_t off = SWZ((uint32_t)((warp_col * 32 + nh * 16 + lrow) * 128 + bcol));
            ldsm4(bp[nh], stg + 16384 + off);
        }
#pragma unroll
        for (int mi = 0; mi < 4; mi++)
#pragma unroll
            for (int ni = 0; ni < 4; ni++) {
                const int nh = ni >> 1, s = ni & 1;
                mma_f16(acc[mi][ni], a[mi], bp[nh][s], bp[nh][s + 2]);
            }
    }
}

template <int KCHUNKS>
__device__ __forceinline__ void mma_mainloop_1(
    const __half* A, size_t aStr, const __half* B, size_t bStr,
    uint32_t smemU32, int t, int wid, int lane, float acc[4][4][4])
{
    stage_load_1(A, aStr, B, bStr, 0, smemU32, t);
    cp_commit();
    for (int c = 0; c < KCHUNKS; c++) {
        const bool more = (c + 1) < KCHUNKS;
        if (more) {
            stage_load_1(A, aStr, B, bStr, (c + 1) * 64,
                         smemU32 + ((c + 1) & 1) * STG_1, t);
            cp_commit();
            asm volatile("cp.async.wait_group 1;" ::: "memory");
        } else {
            asm volatile("cp.async.wait_group 0;" ::: "memory");
        }
        __syncthreads();
        stage_compute_1(smemU32 + (c & 1) * STG_1, wid, lane, acc);
        __syncthreads();
    }
}

// ============================================================================
// transpose + split: src [b][C][N] fp32 -> dst [b][N][C] bf16 hi/lo
//                    (+ optional fp16 single output for the v-proj B operand)
// ============================================================================
__global__ void __launch_bounds__(256)
transpose_split(const float* __restrict__ src,
                __nv_bfloat16* __restrict__ dhi, __nv_bfloat16* __restrict__ dlo,
                __half* __restrict__ dh16)
{
    __shared__ float tile[32][33];
    const int b = blockIdx.z;
    const int n0 = blockIdx.x * 32, c0 = blockIdx.y * 32;
    const int tx = threadIdx.x, ty = threadIdx.y;   // (32, 8)
    const float* S = src + (size_t)b * CC * NN;
#pragma unroll
    for (int i = 0; i < 4; i++)
        tile[ty * 4 + i][tx] = S[(size_t)(c0 + ty * 4 + i) * NN + n0 + tx];
    __syncthreads();
    __nv_bfloat16* H = dhi + (size_t)b * NN * CC;
    __nv_bfloat16* L = dlo + (size_t)b * NN * CC;
    __half* H16 = dh16 ? dh16 + (size_t)b * NN * CC : nullptr;
#pragma unroll
    for (int i = 0; i < 4; i++) {
        const float f = tile[tx][ty * 4 + i];
        const __nv_bfloat16 h = __float2bfloat16(f);
        const __nv_bfloat16 l = __float2bfloat16(f - __bfloat162float(h));
        const size_t idx = (size_t)(n0 + ty * 4 + i) * CC + c0 + tx;
        H[idx] = h;
        L[idx] = l;
        if (H16) H16[idx] = __float2half_rn(f);
    }
}

// ============================================================================
// weight split: the four q/k weights -> bf16 hi/lo (256 rows total)
// ============================================================================
__global__ void __launch_bounds__(256)
weight_split(const float* __restrict__ wq, const float* __restrict__ wk,
             const float* __restrict__ wqd, const float* __restrict__ wkd,
             __nv_bfloat16* __restrict__ wqk_hi, __nv_bfloat16* __restrict__ wqk_lo,
             __nv_bfloat16* __restrict__ wqkd_hi, __nv_bfloat16* __restrict__ wqkd_lo)
{
    const int idx = blockIdx.x * 256 + threadIdx.x;
    if (idx >= 256 * 512) return;
    const int row = idx >> 9, col = idx & 511;
    const float* src;
    __nv_bfloat16 *dh, *dl;
    int drow;
    if (row < 64)       { src = wq  + (size_t)row * 512;         dh = wqk_hi;  dl = wqk_lo;  drow = row; }
    else if (row < 128) { src = wk  + (size_t)(row - 64) * 512;  dh = wqk_hi;  dl = wqk_lo;  drow = row; }
    else if (row < 192) { src = wqd + (size_t)(row - 128) * 512; dh = wqkd_hi; dl = wqkd_lo; drow = row - 128; }
    else                { src = wkd + (size_t)(row - 192) * 512; dh = wqkd_hi; dl = wqkd_lo; drow = row - 128; }
    const float f = src[col];
    const __nv_bfloat16 h = __float2bfloat16(f);
    dh[(size_t)drow * 512 + col] = h;
    dl[(size_t)drow * 512 + col] = __float2bfloat16(f - __bfloat162float(h));
}

// wv -> fp16 hi/lo
__global__ void __launch_bounds__(256)
wv_split(const float* __restrict__ wv,
         __half* __restrict__ wv_hi, __half* __restrict__ wv_lo)
{
    const int idx = blockIdx.x * 256 + threadIdx.x;
    if (idx >= 512 * 512) return;
    const float f = wv[idx];
    const __half h = __float2half_rn(f);
    wv_hi[idx] = h;
    wv_lo[idx] = __float2half_rn(f - __half2float(h));
}

// ============================================================================
// proj qk (merged x/dep via blockIdx.y): [n][d] = in[n][c] . w[d][c]
// q and k both -> fp16 single.  bf16 3-pass, occ 1 (input quality preserved).
// ============================================================================
__global__ void __launch_bounds__(256, 1)
mma_proj_qk(const __nv_bfloat16* __restrict__ xt_hi, const __nv_bfloat16* __restrict__ xt_lo,
            const __nv_bfloat16* __restrict__ dt_hi, const __nv_bfloat16* __restrict__ dt_lo,
            const __nv_bfloat16* __restrict__ wqk_hi, const __nv_bfloat16* __restrict__ wqk_lo,
            const __nv_bfloat16* __restrict__ wqkd_hi, const __nv_bfloat16* __restrict__ wqkd_lo,
            const float* __restrict__ bq, const float* __restrict__ bk,
            const float* __restrict__ bqd, const float* __restrict__ bkd,
            __half* __restrict__ Q, __half* __restrict__ K)
{
    extern __shared__ char smem[];
    const uint32_t smemU32 = smem_to_u32(smem);
    const int t = threadIdx.x, wid = t >> 5, lane = t & 31;
    const int b = blockIdx.z;
    const int i0 = blockIdx.x * 128;
    const int sel = blockIdx.y;   // 0 = x path (d 0-63), 1 = dep path (d 64-127)

    const __nv_bfloat16* Ahi = sel ? dt_hi : xt_hi;
    const __nv_bfloat16* Alo = sel ? dt_lo : xt_lo;
    const __nv_bfloat16* Whi = sel ? wqkd_hi : wqk_hi;
    const __nv_bfloat16* Wlo = sel ? wqkd_lo : wqk_lo;
    const float* bias_q = sel ? bqd : bq;
    const float* bias_k = sel ? bkd : bk;
    const int d_off = sel ? CQ : 0;

    const size_t aoff = ((size_t)b * NN + i0) * CC;
    float acc[4][4][4] = {};
    mma_mainloop<8>(Ahi + aoff, Alo + aoff, CC, Whi, Wlo, CC,
                    smemU32, t, wid, lane, acc);

    const int warp_col = wid & 3;
    const bool isK = warp_col >= 2;
    const float* bias = isK ? bias_k : bias_q;
    __half* D = isK ? K : Q;
    const int csub = isK ? 64 : 0;

    const int rbase = i0 + (wid >> 2) * 64 + (lane >> 2);
    const int cbase = warp_col * 32 + (lane & 3) * 2;
#pragma unroll
    for (int mi = 0; mi < 4; mi++)
#pragma unroll
        for (int ni = 0; ni < 4; ni++) {
            const int col = cbase + ni * 8 - csub;   // 0..63
            const float2 bi = *(const float2*)&bias[col];
            const int r0 = rbase + mi * 16;
            const size_t a0 = ((size_t)b * NN + r0) * DD + d_off + col;
            const size_t a1 = ((size_t)b * NN + r0 + 8) * DD + d_off + col;
            store2_h(acc[mi][ni][0] + bi.x, acc[mi][ni][1] + bi.y, D + a0);
            store2_h(acc[mi][ni][2] + bi.x, acc[mi][ni][3] + bi.y, D + a1);
        }
}

// ============================================================================
// proj v: [c][n] tile = wv[c][k] . xt[n][k]  -> fp16 single
// 2-pass split-fp16 (wv hi/lo fp16, xt single fp16), occ 2.
// ============================================================================
__global__ void __launch_bounds__(256, 2)
mma_proj_v(const __half* __restrict__ w_hi, const __half* __restrict__ w_lo,
           const __half* __restrict__ xt_h,
           const float* __restrict__ bias,
           __half* __restrict__ V)
{
    extern __shared__ char smem[];
    const uint32_t smemU32 = smem_to_u32(smem);
    const int t = threadIdx.x, wid = t >> 5, lane = t & 31;
    const int b = blockIdx.z;
    const int n0 = blockIdx.x * 128, m0 = blockIdx.y * 128;

    const size_t boff = ((size_t)b * NN + n0) * CC;
    float acc[4][4][4] = {};
    mma_mainloop_h<8>(w_hi + (size_t)m0 * CC, w_lo + (size_t)m0 * CC, CC,
                      xt_h + boff, CC,
                      smemU32, t, wid, lane, acc);

    const int rbase = m0 + (wid >> 2) * 64 + (lane >> 2);
    const int cbase = n0 + (wid & 3) * 32 + (lane & 3) * 2;
#pragma unroll
    for (int mi = 0; mi < 4; mi++) {
        const int ch0 = rbase + mi * 16;
        const float bi0 = bias[ch0], bi1 = bias[ch0 + 8];
#pragma unroll
        for (int ni = 0; ni < 4; ni++) {
            const int cn = cbase + ni * 8;
            store2_h(acc[mi][ni][0] + bi0, acc[mi][ni][1] + bi0,
                     V + ((size_t)b * CC + ch0) * NN + cn);
            store2_h(acc[mi][ni][2] + bi1, acc[mi][ni][3] + bi1,
                     V + ((size_t)b * CC + ch0 + 8) * NN + cn);
        }
    }
}

// ============================================================================
// Energy: E[b][i][j] = sum_d q[i][d] k[j][d]  (1-pass fp16; occ 2)
// ============================================================================
__global__ void __launch_bounds__(256, 2)
mma_energy(const __half* __restrict__ q, const __half* __restrict__ k,
           float* __restrict__ E)
{
    extern __shared__ char smem[];
    const uint32_t smemU32 = smem_to_u32(smem);
    const int t = threadIdx.x, wid = t >> 5, lane = t & 31;
    const int b = blockIdx.z;
    const int i0 = blockIdx.y * 128, j0 = blockIdx.x * 128;

    const size_t aoff = ((size_t)b * NN + i0) * DD;
    const size_t boff = ((size_t)b * NN + j0) * DD;

    float acc[4][4][4] = {};
    mma_mainloop_1<2>(q + aoff, DD, k + boff, DD, smemU32, t, wid, lane, acc);

    float* Eb = E + (size_t)b * NN * NN;
    const int rbase = i0 + (wid >> 2) * 64 + (lane >> 2);
    const int cbase = j0 + (wid & 3) * 32 + (lane & 3) * 2;
#pragma unroll
    for (int mi = 0; mi < 4; mi++)
#pragma unroll
        for (int ni = 0; ni < 4; ni++) {
            const int r = rbase + mi * 16;
            const int cjj = cbase + ni * 8;
            *(float2*)&Eb[(size_t)r * NN + cjj]       = make_float2(acc[mi][ni][0], acc[mi][ni][1]);
            *(float2*)&Eb[(size_t)(r + 8) * NN + cjj] = make_float2(acc[mi][ni][2], acc[mi][ni][3]);
        }
}

// ============================================================================
// Out: out[b][c][i] = g * (sum_j v[c][j] p[i][j]) * inv[i] + x[c][i]
// 1-pass fp16, occ 2.
// ============================================================================
__global__ void __launch_bounds__(256, 2)
mma_out(const __half* __restrict__ v, const __half* __restrict__ p,
        const float* __restrict__ X, const float* __restrict__ gamma,
        const float* __restrict__ invs, float* __restrict__ Out)
{
    extern __shared__ char smem[];
    const uint32_t smemU32 = smem_to_u32(smem);
    const int t = threadIdx.x, wid = t >> 5, lane = t & 31;
    const int b = blockIdx.z;
    const int c0 = blockIdx.x * 128, i0 = blockIdx.y * 128;

    const size_t aoff = ((size_t)b * CC + c0) * NN;
    const size_t boff = ((size_t)b * NN + i0) * NN;

    float acc[4][4][4] = {};
    mma_mainloop_1<64>(v + aoff, NN, p + boff, NN, smemU32, t, wid, lane, acc);

    const float g = __ldg(gamma);
    const int rbase = c0 + (wid >> 2) * 64 + (lane >> 2);
    const int cbase = i0 + (wid & 3) * 32 + (lane & 3) * 2;
    const float* ivb = invs + b * NN;
#pragma unroll
    for (int mi = 0; mi < 4; mi++)
#pragma unroll
        for (int ni = 0; ni < 4; ni++) {
            const int ch = rbase + mi * 16;
            const int ci = cbase + ni * 8;
            const float2 iv = *(const float2*)&ivb[ci];
            {
                const size_t idx = ((size_t)b * CC + ch) * NN + ci;
                const float2 xv = *(const float2*)&X[idx];
                float2 o;
                o.x = g * acc[mi][ni][0] * iv.x + xv.x;
                o.y = g * acc[mi][ni][1] * iv.y + xv.y;
                *(float2*)&Out[idx] = o;
            }
            {
                const size_t idx = ((size_t)b * CC + ch + 8) * NN + ci;
                const float2 xv = *(const float2*)&X[idx];
                float2 o;
                o.x = g * acc[mi][ni][2] * iv.x + xv.x;
                o.y = g * acc[mi][ni][3] * iv.y + xv.y;
                *(float2*)&Out[idx] = o;
            }
        }
}

// ============================================================================
// Softmax: fp32 energy row -> unnormalized exp fp16 + 1/rowsum
// ============================================================================
__global__ void __launch_bounds__(256)
softmax_rows(const float* __restrict__ E,
             __half* __restrict__ P, float* __restrict__ invs)
{
    __shared__ float red[8];
    const float4* E4 = (const float4*)E;
    const size_t base4 = (size_t)blockIdx.x * (NN / 4);
    const int tid = threadIdx.x;
    const int lane = tid & 31, wid = tid >> 5;

    float4 v[4];
#pragma unroll
    for (int u = 0; u < 4; u++) v[u] = E4[base4 + u * 256 + tid];

    float m = -1e30f;
#pragma unroll
    for (int u = 0; u < 4; u++)
        m = fmaxf(m, fmaxf(fmaxf(v[u].x, v[u].y), fmaxf(v[u].z, v[u].w)));
#pragma unroll
    for (int off = 16; off > 0; off >>= 1)
        m = fmaxf(m, __shfl_xor_sync(0xffffffffu, m, off));
    if (lane == 0) red[wid] = m;
    __syncthreads();
    m = red[0];
#pragma unroll
    for (int w = 1; w < 8; w++) m = fmaxf(m, red[w]);
    __syncthreads();

    float s = 0.f;
#pragma unroll
    for (int u = 0; u < 4; u++) {
        v[u].x = __expf(v[u].x - m); v[u].y = __expf(v[u].y - m);
        v[u].z = __expf(v[u].z - m); v[u].w = __expf(v[u].w - m);
        s += v[u].x + v[u].y + v[u].z + v[u].w;
    }
#pragma unroll
    for (int off = 16; off > 0; off >>= 1)
        s += __shfl_xor_sync(0xffffffffu, s, off);
    if (lane == 0) red[wid] = s;
    __syncthreads();
    s = red[0];
#pragma unroll
    for (int w = 1; w < 8; w++) s += red[w];

#pragma unroll
    for (int u = 0; u < 4; u++) {
        const size_t el = base4 * 4 + (u * 256 + tid) * 4;
        __half h[4];
        h[0] = __float2half_rn(v[u].x); h[1] = __float2half_rn(v[u].y);
        h[2] = __float2half_rn(v[u].z); h[3] = __float2half_rn(v[u].w);
        *(uint2*)&P[el] = *(uint2*)h;
    }
    if (tid == 0) invs[blockIdx.x] = 1.0f / s;
}

// ============================================================================

extern "C" void kernel_launch(void* const* d_in, const int* in_sizes, int n_in,
                              void* d_out, int out_size)
{
    const float* x     = (const float*)d_in[0];
    const float* dep   = (const float*)d_in[1];
    const float* wq    = (const float*)d_in[2];
    const float* bq    = (const float*)d_in[3];
    const float* wqd   = (const float*)d_in[4];
    const float* bqd   = (const float*)d_in[5];
    const float* wk    = (const float*)d_in[6];
    const float* bk    = (const float*)d_in[7];
    const float* wkd   = (const float*)d_in[8];
    const float* bkd   = (const float*)d_in[9];
    const float* wv    = (const float*)d_in[10];
    const float* bv    = (const float*)d_in[11];
    const float* gamma = (const float*)d_in[12];
    float* out = (float*)d_out;

    __nv_bfloat16 *xt_hi, *xt_lo, *dt_hi, *dt_lo;
    __nv_bfloat16 *wqk_hi, *wqk_lo, *wqkd_hi, *wqkd_lo;
    __half *xt_h, *wv_hi, *wv_lo;
    __half *qq, *kk, *vv, *p;
    float *e, *s;
    cudaGetSymbolAddress((void**)&xt_hi, g_xt_hi);
    cudaGetSymbolAddress((void**)&xt_lo, g_xt_lo);
    cudaGetSymbolAddress((void**)&xt_h,  g_xt_h);
    cudaGetSymbolAddress((void**)&dt_hi, g_dt_hi);
    cudaGetSymbolAddress((void**)&dt_lo, g_dt_lo);
    cudaGetSymbolAddress((void**)&wqk_hi, g_wqk_hi);
    cudaGetSymbolAddress((void**)&wqk_lo, g_wqk_lo);
    cudaGetSymbolAddress((void**)&wqkd_hi, g_wqkd_hi);
    cudaGetSymbolAddress((void**)&wqkd_lo, g_wqkd_lo);
    cudaGetSymbolAddress((void**)&wv_hi, g_wv_hi);
    cudaGetSymbolAddress((void**)&wv_lo, g_wv_lo);
    cudaGetSymbolAddress((void**)&qq, g_q);
    cudaGetSymbolAddress((void**)&kk, g_k);
    cudaGetSymbolAddress((void**)&vv, g_v);
    cudaGetSymbolAddress((void**)&p, g_p);
    cudaGetSymbolAddress((void**)&e, g_e);
    cudaGetSymbolAddress((void**)&s, g_s);

    cudaFuncSetAttribute(mma_proj_qk, cudaFuncAttributeMaxDynamicSharedMemorySize, MMA_SMEM_BYTES);
    cudaFuncSetAttribute(mma_proj_v,  cudaFuncAttributeMaxDynamicSharedMemorySize, H2_SMEM_BYTES);
    cudaFuncSetAttribute(mma_energy,  cudaFuncAttributeMaxDynamicSharedMemorySize, H1_SMEM_BYTES);
    cudaFuncSetAttribute(mma_out,     cudaFuncAttributeMaxDynamicSharedMemorySize, H1_SMEM_BYTES);

    // Side stream + fork/join events (host objects; created per call, capturable).
    cudaStream_t sv;
    cudaStreamCreateWithFlags(&sv, cudaStreamNonBlocking);
    cudaEvent_t evRoot, evX, evV;
    cudaEventCreateWithFlags(&evRoot, cudaEventDisableTiming);
    cudaEventCreateWithFlags(&evX,    cudaEventDisableTiming);
    cudaEventCreateWithFlags(&evV,    cudaEventDisableTiming);

    // Fork: side stream joins the capture graph.
    cudaEventRecord(evRoot, 0);
    cudaStreamWaitEvent(sv, evRoot, 0);

    // Side stream: wv split (no deps).
    wv_split<<<(512 * 512 + 255) / 256, 256, 0, sv>>>(wv, wv_hi, wv_lo);

    // Main stream: input prep.
    dim3 tthr(32, 8);
    transpose_split<<<dim3(NN / 32, CC / 32, BB), tthr>>>(x,   xt_hi, xt_lo, xt_h);
    cudaEventRecord(evX, 0);                 // xt_h ready
    transpose_split<<<dim3(NN / 32, CC / 32, BB), tthr>>>(dep, dt_hi, dt_lo, (__half*)nullptr);
    weight_split<<<(256 * 512 + 255) / 256, 256>>>(wq, wk, wqd, wkd,
                                                   wqk_hi, wqk_lo, wqkd_hi, wqkd_lo);

    // Side stream: proj v (needs xt_h + wv splits).
    cudaStreamWaitEvent(sv, evX, 0);
    mma_proj_v<<<dim3(NN / 128, CC / 128, BB), 256, H2_SMEM_BYTES, sv>>>(
        wv_hi, wv_lo, xt_h, bv, vv);
    cudaEventRecord(evV, sv);

    // Main stream: q/k projections -> energy -> softmax.
    mma_proj_qk<<<dim3(NN / 128, 2, BB), 256, MMA_SMEM_BYTES>>>(
        xt_hi, xt_lo, dt_hi, dt_lo, wqk_hi, wqk_lo, wqkd_hi, wqkd_lo,
        bq, bk, bqd, bkd, qq, kk);
    mma_energy<<<dim3(NN / 128, NN / 128, BB), 256, H1_SMEM_BYTES>>>(qq, kk, e);
    softmax_rows<<<BB * NN, 256>>>(e, p, s);

    // Join: out needs v from the side stream.
    cudaStreamWaitEvent(0, evV, 0);
    mma_out<<<dim3(CC / 128, NN / 128, BB), 256, H1_SMEM_BYTES>>>(vv, p, x, gamma, s, out);
}

// round 17
// speedup vs baseline: 3.2928x; 1.0258x over previous
#include <cuda_runtime.h>
#include <cuda_bf16.h>
#include <cuda_fp16.h>
#include <cstdint>

#define BB 4
#define CC 512
#define CQ 64
#define DD 128   // 2*CQ
#define NN 4096  // H*W

// ---------------- scratch (device globals; no allocations allowed) ----------
__device__ __align__(256) __nv_bfloat16 g_xt_hi[BB * NN * CC];  // x^T [b][n][c] bf16 hi/lo
__device__ __align__(256) __nv_bfloat16 g_xt_lo[BB * NN * CC];
__device__ __align__(256) __half        g_xt_h[BB * NN * CC];   // x^T fp16 single
__device__ __align__(256) __nv_bfloat16 g_dt_hi[BB * NN * CC];  // dep^T bf16 hi/lo
__device__ __align__(256) __nv_bfloat16 g_dt_lo[BB * NN * CC];
__device__ __align__(256) __nv_bfloat16 g_wqk_hi[DD * CC];      // wq rows 0-63, wk 64-127
__device__ __align__(256) __nv_bfloat16 g_wqk_lo[DD * CC];
__device__ __align__(256) __nv_bfloat16 g_wqkd_hi[DD * CC];
__device__ __align__(256) __nv_bfloat16 g_wqkd_lo[DD * CC];
__device__ __align__(256) __half g_wv_hi[CC * CC];              // wv fp16 hi/lo
__device__ __align__(256) __half g_wv_lo[CC * CC];
__device__ __align__(256) __half g_q[BB * NN * DD];             // [b][i][d] fp16 single
__device__ __align__(256) __half g_k[BB * NN * DD];             // [b][j][d] fp16 single
__device__ __align__(256) __half g_v[BB * CC * NN];             // [b][c][n] fp16 single
__device__ __align__(256) float g_e[(size_t)BB * NN * NN];
__device__ __align__(256) __half g_p[(size_t)BB * NN * NN];     // exp, fp16 single
__device__ __align__(256) float g_s[BB * NN];

// ---------------- low-level helpers -----------------------------------------
__device__ __forceinline__ uint32_t smem_to_u32(const void* p) {
    uint32_t a;
    asm("{ .reg .u64 t; cvta.to.shared.u64 t, %1; cvt.u32.u64 %0, t; }" : "=r"(a) : "l"(p));
    return a;
}
#define SWZ(off) ((off) ^ (((off) >> 3) & 0x70))

__device__ __forceinline__ void cp16(uint32_t dst, const void* src) {
    asm volatile("cp.async.cg.shared.global [%0], [%1], 16;" :: "r"(dst), "l"(src));
}
__device__ __forceinline__ void cp_commit() {
    asm volatile("cp.async.commit_group;" ::: "memory");
}
__device__ __forceinline__ void ldsm4(uint32_t r[4], uint32_t addr) {
    asm volatile("ldmatrix.sync.aligned.m8n8.x4.shared.b16 {%0,%1,%2,%3}, [%4];"
                 : "=r"(r[0]), "=r"(r[1]), "=r"(r[2]), "=r"(r[3]) : "r"(addr));
}
__device__ __forceinline__ void mma_bf16(float acc[4], const uint32_t a[4],
                                         uint32_t b0, uint32_t b1) {
    asm volatile("mma.sync.aligned.m16n8k16.row.col.f32.bf16.bf16.f32 "
                 "{%0,%1,%2,%3}, {%4,%5,%6,%7}, {%8,%9}, {%0,%1,%2,%3};"
                 : "+f"(acc[0]), "+f"(acc[1]), "+f"(acc[2]), "+f"(acc[3])
                 : "r"(a[0]), "r"(a[1]), "r"(a[2]), "r"(a[3]), "r"(b0), "r"(b1));
}
__device__ __forceinline__ void mma_f16(float acc[4], const uint32_t a[4],
                                        uint32_t b0, uint32_t b1) {
    asm volatile("mma.sync.aligned.m16n8k16.row.col.f32.f16.f16.f32 "
                 "{%0,%1,%2,%3}, {%4,%5,%6,%7}, {%8,%9}, {%0,%1,%2,%3};"
                 : "+f"(acc[0]), "+f"(acc[1]), "+f"(acc[2]), "+f"(acc[3])
                 : "r"(a[0]), "r"(a[1]), "r"(a[2]), "r"(a[3]), "r"(b0), "r"(b1));
}
__device__ __forceinline__ void store2_h(float v0, float v1, __half* d)
{
    __half2 H; H.x = __float2half_rn(v0); H.y = __float2half_rn(v1);
    *(__half2*)d = H;
}

// ---------------- 3-pass split-bf16 machinery (R8-proven, EXACT) -------------
#define STG 65536
#define MMA_SMEM_BYTES (2 * STG)

__device__ __forceinline__ void stage_load(
    const __nv_bfloat16* __restrict__ Ahi, const __nv_bfloat16* __restrict__ Alo,
    size_t aStr,
    const __nv_bfloat16* __restrict__ Bhi, const __nv_bfloat16* __restrict__ Blo,
    size_t bStr, int kt, uint32_t stageU32, int t)
{
#pragma unroll
    for (int i = 0; i < 4; i++) {
        const int id = t + i * 256;
        const int row = id >> 3, c16 = id & 7;
        const uint32_t doff = SWZ((uint32_t)(row * 128 + c16 * 16));
        const size_t so = (size_t)row * aStr + kt + c16 * 8;
        cp16(stageU32 + doff,          Ahi + so);
        cp16(stageU32 + 16384 + doff,  Alo + so);
        const size_t sb = (size_t)row * bStr + kt + c16 * 8;
        cp16(stageU32 + 32768 + doff,  Bhi + sb);
        cp16(stageU32 + 49152 + doff,  Blo + sb);
    }
}

__device__ __forceinline__ void stage_compute(uint32_t stageU32, int wid, int lane,
                                              float acc[4][4][4])
{
    const int warp_row = wid >> 2;
    const int warp_col = wid & 3;
    const int lrow = lane & 15;
    const int chalf = (lane >= 16) ? 16 : 0;

#pragma unroll
    for (int ks = 0; ks < 4; ks++) {
        const uint32_t bcol = ks * 32 + chalf;
        uint32_t ahi[4][4], alo[4][4];
#pragma unroll
        for (int mi = 0; mi < 4; mi++) {
            const uint32_t off = SWZ((uint32_t)((warp_row * 64 + mi * 16 + lrow) * 128 + bcol));
            ldsm4(ahi[mi], stageU32 + off);
            ldsm4(alo[mi], stageU32 + 16384 + off);
        }
        uint32_t bhi[2][4], blo[2][4];
#pragma unroll
        for (int nh = 0; nh < 2; nh++) {
            const uint32_t off = SWZ((uint32_t)((warp_col * 32 + nh * 16 + lrow) * 128 + bcol));
            ldsm4(bhi[nh], stageU32 + 32768 + off);
            ldsm4(blo[nh], stageU32 + 49152 + off);
        }
#pragma unroll
        for (int mi = 0; mi < 4; mi++)
#pragma unroll
            for (int ni = 0; ni < 4; ni++) {
                const int nh = ni >> 1, s = ni & 1;
                mma_bf16(acc[mi][ni], ahi[mi], bhi[nh][s], bhi[nh][s + 2]);
                mma_bf16(acc[mi][ni], alo[mi], bhi[nh][s], bhi[nh][s + 2]);
                mma_bf16(acc[mi][ni], ahi[mi], blo[nh][s], blo[nh][s + 2]);
            }
    }
}

template <int KCHUNKS>
__device__ __forceinline__ void mma_mainloop(
    const __nv_bfloat16* Ahi, const __nv_bfloat16* Alo, size_t aStr,
    const __nv_bfloat16* Bhi, const __nv_bfloat16* Blo, size_t bStr,
    uint32_t smemU32, int t, int wid, int lane, float acc[4][4][4])
{
    stage_load(Ahi, Alo, aStr, Bhi, Blo, bStr, 0, smemU32, t);
    cp_commit();
    for (int c = 0; c < KCHUNKS; c++) {
        const bool more = (c + 1) < KCHUNKS;
        if (more) {
            stage_load(Ahi, Alo, aStr, Bhi, Blo, bStr, (c + 1) * 64,
                       smemU32 + ((c + 1) & 1) * STG, t);
            cp_commit();
            asm volatile("cp.async.wait_group 1;" ::: "memory");
        } else {
            asm volatile("cp.async.wait_group 0;" ::: "memory");
        }
        __syncthreads();
        stage_compute(smemU32 + (c & 1) * STG, wid, lane, acc);
        __syncthreads();
    }
}

// ---------------- 2-pass split-fp16 (R10-proven, EXACT): A hi/lo, B single ---
#define STG_H 49152
#define H2_SMEM_BYTES (2 * STG_H)

__device__ __forceinline__ void stage_load_h(
    const __half* __restrict__ Ahi, const __half* __restrict__ Alo, size_t aStr,
    const __half* __restrict__ B, size_t bStr, int kt, uint32_t stg, int t)
{
#pragma unroll
    for (int i = 0; i < 4; i++) {
        const int id = t + i * 256;
        const int row = id >> 3, c16 = id & 7;
        const uint32_t doff = SWZ((uint32_t)(row * 128 + c16 * 16));
        const size_t so = (size_t)row * aStr + kt + c16 * 8;
        cp16(stg + doff,          Ahi + so);
        cp16(stg + 16384 + doff,  Alo + so);
        const size_t sb = (size_t)row * bStr + kt + c16 * 8;
        cp16(stg + 32768 + doff,  B + sb);
    }
}

__device__ __forceinline__ void stage_compute_h(uint32_t stg, int wid, int lane,
                                                float acc[4][4][4])
{
    const int warp_row = wid >> 2;
    const int warp_col = wid & 3;
    const int lrow = lane & 15;
    const int chalf = (lane >= 16) ? 16 : 0;

#pragma unroll
    for (int ks = 0; ks < 4; ks++) {
        const uint32_t bcol = ks * 32 + chalf;
        uint32_t ahi[4][4], alo[4][4];
#pragma unroll
        for (int mi = 0; mi < 4; mi++) {
            const uint32_t off = SWZ((uint32_t)((warp_row * 64 + mi * 16 + lrow) * 128 + bcol));
            ldsm4(ahi[mi], stg + off);
            ldsm4(alo[mi], stg + 16384 + off);
        }
        uint32_t bp[2][4];
#pragma unroll
        for (int nh = 0; nh < 2; nh++) {
            const uint32_t off = SWZ((uint32_t)((warp_col * 32 + nh * 16 + lrow) * 128 + bcol));
            ldsm4(bp[nh], stg + 32768 + off);
        }
#pragma unroll
        for (int mi = 0; mi < 4; mi++)
#pragma unroll
            for (int ni = 0; ni < 4; ni++) {
                const int nh = ni >> 1, s = ni & 1;
                mma_f16(acc[mi][ni], ahi[mi], bp[nh][s], bp[nh][s + 2]);
                mma_f16(acc[mi][ni], alo[mi], bp[nh][s], bp[nh][s + 2]);
            }
    }
}

template <int KCHUNKS>
__device__ __forceinline__ void mma_mainloop_h(
    const __half* Ahi, const __half* Alo, size_t aStr,
    const __half* B, size_t bStr,
    uint32_t smemU32, int t, int wid, int lane, float acc[4][4][4])
{
    stage_load_h(Ahi, Alo, aStr, B, bStr, 0, smemU32, t);
    cp_commit();
    for (int c = 0; c < KCHUNKS; c++) {
        const bool more = (c + 1) < KCHUNKS;
        if (more) {
            stage_load_h(Ahi, Alo, aStr, B, bStr, (c + 1) * 64,
                         smemU32 + ((c + 1) & 1) * STG_H, t);
            cp_commit();
            asm volatile("cp.async.wait_group 1;" ::: "memory");
        } else {
            asm volatile("cp.async.wait_group 0;" ::: "memory");
        }
        __syncthreads();
        stage_compute_h(smemU32 + (c & 1) * STG_H, wid, lane, acc);
        __syncthreads();
    }
}

// ---------------- 1-pass fp16 (R11-proven): A single, B single ---------------
#define STG_1 32768
#define H1_SMEM_BYTES (2 * STG_1)

__device__ __forceinline__ void stage_load_1(
    const __half* __restrict__ A, size_t aStr,
    const __half* __restrict__ B, size_t bStr, int kt, uint32_t stg, int t)
{
#pragma unroll
    for (int i = 0; i < 4; i++) {
        const int id = t + i * 256;
        const int row = id >> 3, c16 = id & 7;
        const uint32_t doff = SWZ((uint32_t)(row * 128 + c16 * 16));
        cp16(stg + doff,          A + (size_t)row * aStr + kt + c16 * 8);
        cp16(stg + 16384 + doff,  B + (size_t)row * bStr + kt + c16 * 8);
    }
}

__device__ __forceinline__ void stage_compute_1(uint32_t stg, int wid, int lane,
                                                float acc[4][4][4])
{
    const int warp_row = wid >> 2;
    const int warp_col = wid & 3;
    const int lrow = lane & 15;
    const int chalf = (lane >= 16) ? 16 : 0;

#pragma unroll
    for (int ks = 0; ks < 4; ks++) {
        const uint32_t bcol = ks * 32 + chalf;
        uint32_t a[4][4];
#pragma unroll
        for (int mi = 0; mi < 4; mi++) {
            const uint32_t off = SWZ((uint32_t)((warp_row * 64 + mi * 16 + lrow) * 128 + bcol));
            ldsm4(a[mi], stg + off);
        }
        uint32_t bp[2][4];
#pragma unroll
        for (int nh = 0; nh < 2; nh++) {
            const uint32_t off = SWZ((uint32_t)((warp_col * 32 + nh * 16 + lrow) * 128 + bcol));
            ldsm4(bp[nh], stg + 16384 + off);
        }
#pragma unroll
        for (int mi = 0; mi < 4; mi++)
#pragma unroll
            for (int ni = 0; ni < 4; ni++) {
                const int nh = ni >> 1, s = ni & 1;
                mma_f16(acc[mi][ni], a[mi], bp[nh][s], bp[nh][s + 2]);
            }
    }
}

template <int KCHUNKS>
__device__ __forceinline__ void mma_mainloop_1(
    const __half* A, size_t aStr, const __half* B, size_t bStr,
    uint32_t smemU32, int t, int wid, int lane, float acc[4][4][4])
{
    stage_load_1(A, aStr, B, bStr, 0, smemU32, t);
    cp_commit();
    for (int c = 0; c < KCHUNKS; c++) {
        const bool more = (c + 1) < KCHUNKS;
        if (more) {
            stage_load_1(A, aStr, B, bStr, (c + 1) * 64,
                         smemU32 + ((c + 1) & 1) * STG_1, t);
            cp_commit();
            asm volatile("cp.async.wait_group 1;" ::: "memory");
        } else {
            asm volatile("cp.async.wait_group 0;" ::: "memory");
        }
        __syncthreads();
        stage_compute_1(smemU32 + (c & 1) * STG_1, wid, lane, acc);
        __syncthreads();
    }
}

// ============================================================================
// merged transpose + split: grid.z = 2*BB; sel 0 -> x (+fp16 out), 1 -> dep
// ============================================================================
__global__ void __launch_bounds__(256)
transpose_all(const float* __restrict__ x, const float* __restrict__ dep,
              __nv_bfloat16* __restrict__ xhi, __nv_bfloat16* __restrict__ xlo,
              __half* __restrict__ xh16,
              __nv_bfloat16* __restrict__ dhi, __nv_bfloat16* __restrict__ dlo)
{
    __shared__ float tile[32][33];
    const int z = blockIdx.z;
    const int b = z >> 1, sel = z & 1;
    const float* src = sel ? dep : x;
    __nv_bfloat16* H = (sel ? dhi : xhi) + (size_t)b * NN * CC;
    __nv_bfloat16* L = (sel ? dlo : xlo) + (size_t)b * NN * CC;
    __half* H16 = sel ? nullptr : (xh16 + (size_t)b * NN * CC);

    const int n0 = blockIdx.x * 32, c0 = blockIdx.y * 32;
    const int tx = threadIdx.x, ty = threadIdx.y;   // (32, 8)
    const float* S = src + (size_t)b * CC * NN;
#pragma unroll
    for (int i = 0; i < 4; i++)
        tile[ty * 4 + i][tx] = S[(size_t)(c0 + ty * 4 + i) * NN + n0 + tx];
    __syncthreads();
#pragma unroll
    for (int i = 0; i < 4; i++) {
        const float f = tile[tx][ty * 4 + i];
        const __nv_bfloat16 h = __float2bfloat16(f);
        const __nv_bfloat16 l = __float2bfloat16(f - __bfloat162float(h));
        const size_t idx = (size_t)(n0 + ty * 4 + i) * CC + c0 + tx;
        H[idx] = h;
        L[idx] = l;
        if (H16) H16[idx] = __float2half_rn(f);
    }
}

// ============================================================================
// merged weight split: rows 0-255 -> q/k bf16 hi/lo, rows 256-767 -> wv fp16
// ============================================================================
__global__ void __launch_bounds__(256)
weights_split(const float* __restrict__ wq, const float* __restrict__ wk,
              const float* __restrict__ wqd, const float* __restrict__ wkd,
              const float* __restrict__ wv,
              __nv_bfloat16* __restrict__ wqk_hi, __nv_bfloat16* __restrict__ wqk_lo,
              __nv_bfloat16* __restrict__ wqkd_hi, __nv_bfloat16* __restrict__ wqkd_lo,
              __half* __restrict__ wv_hi, __half* __restrict__ wv_lo)
{
    const int idx = blockIdx.x * 256 + threadIdx.x;
    if (idx >= 768 * 512) return;
    const int row = idx >> 9, col = idx & 511;
    if (row < 256) {
        const float* src;
        __nv_bfloat16 *dh, *dl;
        int drow;
        if (row < 64)       { src = wq  + (size_t)row * 512;         dh = wqk_hi;  dl = wqk_lo;  drow = row; }
        else if (row < 128) { src = wk  + (size_t)(row - 64) * 512;  dh = wqk_hi;  dl = wqk_lo;  drow = row; }
        else if (row < 192) { src = wqd + (size_t)(row - 128) * 512; dh = wqkd_hi; dl = wqkd_lo; drow = row - 128; }
        else                { src = wkd + (size_t)(row - 192) * 512; dh = wqkd_hi; dl = wqkd_lo; drow = row - 128; }
        const float f = src[col];
        const __nv_bfloat16 h = __float2bfloat16(f);
        dh[(size_t)drow * 512 + col] = h;
        dl[(size_t)drow * 512 + col] = __float2bfloat16(f - __bfloat162float(h));
    } else {
        const int widx = (row - 256) * 512 + col;
        const float f = wv[widx];
        const __half h = __float2half_rn(f);
        wv_hi[widx] = h;
        wv_lo[widx] = __float2half_rn(f - __half2float(h));
    }
}

// ============================================================================
// proj qk (merged x/dep via blockIdx.y): [n][d] = in[n][c] . w[d][c]
// ============================================================================
__global__ void __launch_bounds__(256, 1)
mma_proj_qk(const __nv_bfloat16* __restrict__ xt_hi, const __nv_bfloat16* __restrict__ xt_lo,
            const __nv_bfloat16* __restrict__ dt_hi, const __nv_bfloat16* __restrict__ dt_lo,
            const __nv_bfloat16* __restrict__ wqk_hi, const __nv_bfloat16* __restrict__ wqk_lo,
            const __nv_bfloat16* __restrict__ wqkd_hi, const __nv_bfloat16* __restrict__ wqkd_lo,
            const float* __restrict__ bq, const float* __restrict__ bk,
            const float* __restrict__ bqd, const float* __restrict__ bkd,
            __half* __restrict__ Q, __half* __restrict__ K)
{
    extern __shared__ char smem[];
    const uint32_t smemU32 = smem_to_u32(smem);
    const int t = threadIdx.x, wid = t >> 5, lane = t & 31;
    const int b = blockIdx.z;
    const int i0 = blockIdx.x * 128;
    const int sel = blockIdx.y;

    const __nv_bfloat16* Ahi = sel ? dt_hi : xt_hi;
    const __nv_bfloat16* Alo = sel ? dt_lo : xt_lo;
    const __nv_bfloat16* Whi = sel ? wqkd_hi : wqk_hi;
    const __nv_bfloat16* Wlo = sel ? wqkd_lo : wqk_lo;
    const float* bias_q = sel ? bqd : bq;
    const float* bias_k = sel ? bkd : bk;
    const int d_off = sel ? CQ : 0;

    const size_t aoff = ((size_t)b * NN + i0) * CC;
    float acc[4][4][4] = {};
    mma_mainloop<8>(Ahi + aoff, Alo + aoff, CC, Whi, Wlo, CC,
                    smemU32, t, wid, lane, acc);

    const int warp_col = wid & 3;
    const bool isK = warp_col >= 2;
    const float* bias = isK ? bias_k : bias_q;
    __half* D = isK ? K : Q;
    const int csub = isK ? 64 : 0;

    const int rbase = i0 + (wid >> 2) * 64 + (lane >> 2);
    const int cbase = warp_col * 32 + (lane & 3) * 2;
#pragma unroll
    for (int mi = 0; mi < 4; mi++)
#pragma unroll
        for (int ni = 0; ni < 4; ni++) {
            const int col = cbase + ni * 8 - csub;   // 0..63
            const float2 bi = *(const float2*)&bias[col];
            const int r0 = rbase + mi * 16;
            const size_t a0 = ((size_t)b * NN + r0) * DD + d_off + col;
            const size_t a1 = ((size_t)b * NN + r0 + 8) * DD + d_off + col;
            store2_h(acc[mi][ni][0] + bi.x, acc[mi][ni][1] + bi.y, D + a0);
            store2_h(acc[mi][ni][2] + bi.x, acc[mi][ni][3] + bi.y, D + a1);
        }
}

// ============================================================================
// proj v: [c][n] tile = wv[c][k] . xt[n][k]  -> fp16 single  (2-pass, occ 2)
// ============================================================================
__global__ void __launch_bounds__(256, 2)
mma_proj_v(const __half* __restrict__ w_hi, const __half* __restrict__ w_lo,
           const __half* __restrict__ xt_h,
           const float* __restrict__ bias,
           __half* __restrict__ V)
{
    extern __shared__ char smem[];
    const uint32_t smemU32 = smem_to_u32(smem);
    const int t = threadIdx.x, wid = t >> 5, lane = t & 31;
    const int b = blockIdx.z;
    const int n0 = blockIdx.x * 128, m0 = blockIdx.y * 128;

    const size_t boff = ((size_t)b * NN + n0) * CC;
    float acc[4][4][4] = {};
    mma_mainloop_h<8>(w_hi + (size_t)m0 * CC, w_lo + (size_t)m0 * CC, CC,
                      xt_h + boff, CC,
                      smemU32, t, wid, lane, acc);

    const int rbase = m0 + (wid >> 2) * 64 + (lane >> 2);
    const int cbase = n0 + (wid & 3) * 32 + (lane & 3) * 2;
#pragma unroll
    for (int mi = 0; mi < 4; mi++) {
        const int ch0 = rbase + mi * 16;
        const float bi0 = bias[ch0], bi1 = bias[ch0 + 8];
#pragma unroll
        for (int ni = 0; ni < 4; ni++) {
            const int cn = cbase + ni * 8;
            store2_h(acc[mi][ni][0] + bi0, acc[mi][ni][1] + bi0,
                     V + ((size_t)b * CC + ch0) * NN + cn);
            store2_h(acc[mi][ni][2] + bi1, acc[mi][ni][3] + bi1,
                     V + ((size_t)b * CC + ch0 + 8) * NN + cn);
        }
    }
}

// ============================================================================
// Energy (1-pass fp16, occ 2).  E stores use streaming hint (write-once).
// ============================================================================
__global__ void __launch_bounds__(256, 2)
mma_energy(const __half* __restrict__ q, const __half* __restrict__ k,
           float* __restrict__ E)
{
    extern __shared__ char smem[];
    const uint32_t smemU32 = smem_to_u32(smem);
    const int t = threadIdx.x, wid = t >> 5, lane = t & 31;
    const int b = blockIdx.z;
    const int i0 = blockIdx.y * 128, j0 = blockIdx.x * 128;

    const size_t aoff = ((size_t)b * NN + i0) * DD;
    const size_t boff = ((size_t)b * NN + j0) * DD;

    float acc[4][4][4] = {};
    mma_mainloop_1<2>(q + aoff, DD, k + boff, DD, smemU32, t, wid, lane, acc);

    float* Eb = E + (size_t)b * NN * NN;
    const int rbase = i0 + (wid >> 2) * 64 + (lane >> 2);
    const int cbase = j0 + (wid & 3) * 32 + (lane & 3) * 2;
#pragma unroll
    for (int mi = 0; mi < 4; mi++)
#pragma unroll
        for (int ni = 0; ni < 4; ni++) {
            const int r = rbase + mi * 16;
            const int cjj = cbase + ni * 8;
            __stcs((float2*)&Eb[(size_t)r * NN + cjj],
                   make_float2(acc[mi][ni][0], acc[mi][ni][1]));
            __stcs((float2*)&Eb[(size_t)(r + 8) * NN + cjj],
                   make_float2(acc[mi][ni][2], acc[mi][ni][3]));
        }
}

// ============================================================================
// Out (1-pass fp16, occ 2)
// ============================================================================
__global__ void __launch_bounds__(256, 2)
mma_out(const __half* __restrict__ v, const __half* __restrict__ p,
        const float* __restrict__ X, const float* __restrict__ gamma,
        const float* __restrict__ invs, float* __restrict__ Out)
{
    extern __shared__ char smem[];
    const uint32_t smemU32 = smem_to_u32(smem);
    const int t = threadIdx.x, wid = t >> 5, lane = t & 31;
    const int b = blockIdx.z;
    const int c0 = blockIdx.x * 128, i0 = blockIdx.y * 128;

    const size_t aoff = ((size_t)b * CC + c0) * NN;
    const size_t boff = ((size_t)b * NN + i0) * NN;

    float acc[4][4][4] = {};
    mma_mainloop_1<64>(v + aoff, NN, p + boff, NN, smemU32, t, wid, lane, acc);

    const float g = __ldg(gamma);
    const int rbase = c0 + (wid >> 2) * 64 + (lane >> 2);
    const int cbase = i0 + (wid & 3) * 32 + (lane & 3) * 2;
    const float* ivb = invs + b * NN;
#pragma unroll
    for (int mi = 0; mi < 4; mi++)
#pragma unroll
        for (int ni = 0; ni < 4; ni++) {
            const int ch = rbase + mi * 16;
            const int ci = cbase + ni * 8;
            const float2 iv = *(const float2*)&ivb[ci];
            {
                const size_t idx = ((size_t)b * CC + ch) * NN + ci;
                const float2 xv = *(const float2*)&X[idx];
                float2 o;
                o.x = g * acc[mi][ni][0] * iv.x + xv.x;
                o.y = g * acc[mi][ni][1] * iv.y + xv.y;
                *(float2*)&Out[idx] = o;
            }
            {
                const size_t idx = ((size_t)b * CC + ch + 8) * NN + ci;
                const float2 xv = *(const float2*)&X[idx];
                float2 o;
                o.x = g * acc[mi][ni][2] * iv.x + xv.x;
                o.y = g * acc[mi][ni][3] * iv.y + xv.y;
                *(float2*)&Out[idx] = o;
            }
        }
}

// ============================================================================
// Softmax: streaming read of E (read-once), exp fp16 + 1/rowsum
// ============================================================================
__global__ void __launch_bounds__(256)
softmax_rows(const float* __restrict__ E,
             __half* __restrict__ P, float* __restrict__ invs)
{
    __shared__ float red[8];
    const float4* E4 = (const float4*)E;
    const size_t base4 = (size_t)blockIdx.x * (NN / 4);
    const int tid = threadIdx.x;
    const int lane = tid & 31, wid = tid >> 5;

    float4 v[4];
#pragma unroll
    for (int u = 0; u < 4; u++) v[u] = __ldcs(&E4[base4 + u * 256 + tid]);

    float m = -1e30f;
#pragma unroll
    for (int u = 0; u < 4; u++)
        m = fmaxf(m, fmaxf(fmaxf(v[u].x, v[u].y), fmaxf(v[u].z, v[u].w)));
#pragma unroll
    for (int off = 16; off > 0; off >>= 1)
        m = fmaxf(m, __shfl_xor_sync(0xffffffffu, m, off));
    if (lane == 0) red[wid] = m;
    __syncthreads();
    m = red[0];
#pragma unroll
    for (int w = 1; w < 8; w++) m = fmaxf(m, red[w]);
    __syncthreads();

    float s = 0.f;
#pragma unroll
    for (int u = 0; u < 4; u++) {
        v[u].x = __expf(v[u].x - m); v[u].y = __expf(v[u].y - m);
        v[u].z = __expf(v[u].z - m); v[u].w = __expf(v[u].w - m);
        s += v[u].x + v[u].y + v[u].z + v[u].w;
    }
#pragma unroll
    for (int off = 16; off > 0; off >>= 1)
        s += __shfl_xor_sync(0xffffffffu, s, off);
    if (lane == 0) red[wid] = s;
    __syncthreads();
    s = red[0];
#pragma unroll
    for (int w = 1; w < 8; w++) s += red[w];

#pragma unroll
    for (int u = 0; u < 4; u++) {
        const size_t el = base4 * 4 + (u * 256 + tid) * 4;
        __half h[4];
        h[0] = __float2half_rn(v[u].x); h[1] = __float2half_rn(v[u].y);
        h[2] = __float2half_rn(v[u].z); h[3] = __float2half_rn(v[u].w);
        *(uint2*)&P[el] = *(uint2*)h;
    }
    if (tid == 0) invs[blockIdx.x] = 1.0f / s;
}

// ============================================================================

extern "C" void kernel_launch(void* const* d_in, const int* in_sizes, int n_in,
                              void* d_out, int out_size)
{
    const float* x     = (const float*)d_in[0];
    const float* dep   = (const float*)d_in[1];
    const float* wq    = (const float*)d_in[2];
    const float* bq    = (const float*)d_in[3];
    const float* wqd   = (const float*)d_in[4];
    const float* bqd   = (const float*)d_in[5];
    const float* wk    = (const float*)d_in[6];
    const float* bk    = (const float*)d_in[7];
    const float* wkd   = (const float*)d_in[8];
    const float* bkd   = (const float*)d_in[9];
    const float* wv    = (const float*)d_in[10];
    const float* bv    = (const float*)d_in[11];
    const float* gamma = (const float*)d_in[12];
    float* out = (float*)d_out;

    __nv_bfloat16 *xt_hi, *xt_lo, *dt_hi, *dt_lo;
    __nv_bfloat16 *wqk_hi, *wqk_lo, *wqkd_hi, *wqkd_lo;
    __half *xt_h, *wv_hi, *wv_lo;
    __half *qq, *kk, *vv, *p;
    float *e, *s;
    cudaGetSymbolAddress((void**)&xt_hi, g_xt_hi);
    cudaGetSymbolAddress((void**)&xt_lo, g_xt_lo);
    cudaGetSymbolAddress((void**)&xt_h,  g_xt_h);
    cudaGetSymbolAddress((void**)&dt_hi, g_dt_hi);
    cudaGetSymbolAddress((void**)&dt_lo, g_dt_lo);
    cudaGetSymbolAddress((void**)&wqk_hi, g_wqk_hi);
    cudaGetSymbolAddress((void**)&wqk_lo, g_wqk_lo);
    cudaGetSymbolAddress((void**)&wqkd_hi, g_wqkd_hi);
    cudaGetSymbolAddress((void**)&wqkd_lo, g_wqkd_lo);
    cudaGetSymbolAddress((void**)&wv_hi, g_wv_hi);
    cudaGetSymbolAddress((void**)&wv_lo, g_wv_lo);
    cudaGetSymbolAddress((void**)&qq, g_q);
    cudaGetSymbolAddress((void**)&kk, g_k);
    cudaGetSymbolAddress((void**)&vv, g_v);
    cudaGetSymbolAddress((void**)&p, g_p);
    cudaGetSymbolAddress((void**)&e, g_e);
    cudaGetSymbolAddress((void**)&s, g_s);

    cudaFuncSetAttribute(mma_proj_qk, cudaFuncAttributeMaxDynamicSharedMemorySize, MMA_SMEM_BYTES);
    cudaFuncSetAttribute(mma_proj_v,  cudaFuncAttributeMaxDynamicSharedMemorySize, H2_SMEM_BYTES);
    cudaFuncSetAttribute(mma_energy,  cudaFuncAttributeMaxDynamicSharedMemorySize, H1_SMEM_BYTES);
    cudaFuncSetAttribute(mma_out,     cudaFuncAttributeMaxDynamicSharedMemorySize, H1_SMEM_BYTES);

    // Side stream + fork/join events (host objects; capturable pattern).
    cudaStream_t sv;
    cudaStreamCreateWithFlags(&sv, cudaStreamNonBlocking);
    cudaEvent_t evRoot, evX, evW, evV;
    cudaEventCreateWithFlags(&evRoot, cudaEventDisableTiming);
    cudaEventCreateWithFlags(&evX,    cudaEventDisableTiming);
    cudaEventCreateWithFlags(&evW,    cudaEventDisableTiming);
    cudaEventCreateWithFlags(&evV,    cudaEventDisableTiming);

    // Fork.
    cudaEventRecord(evRoot, 0);
    cudaStreamWaitEvent(sv, evRoot, 0);

    // Side stream: all weight splits (off the critical path).
    weights_split<<<(768 * 512 + 255) / 256, 256, 0, sv>>>(
        wq, wk, wqd, wkd, wv,
        wqk_hi, wqk_lo, wqkd_hi, wqkd_lo, wv_hi, wv_lo);
    cudaEventRecord(evW, sv);

    // Main stream: both transposes in one launch.
    dim3 tthr(32, 8);
    transpose_all<<<dim3(NN / 32, CC / 32, 2 * BB), tthr>>>(
        x, dep, xt_hi, xt_lo, xt_h, dt_hi, dt_lo);
    cudaEventRecord(evX, 0);

    // Side stream: proj v (needs xt_h + wv splits; both on/visible to sv).
    cudaStreamWaitEvent(sv, evX, 0);
    mma_proj_v<<<dim3(NN / 128, CC / 128, BB), 256, H2_SMEM_BYTES, sv>>>(
        wv_hi, wv_lo, xt_h, bv, vv);
    cudaEventRecord(evV, sv);

    // Main stream: q/k projections (wait for weights) -> energy -> softmax.
    cudaStreamWaitEvent(0, evW, 0);
    mma_proj_qk<<<dim3(NN / 128, 2, BB), 256, MMA_SMEM_BYTES>>>(
        xt_hi, xt_lo, dt_hi, dt_lo, wqk_hi, wqk_lo, wqkd_hi, wqkd_lo,
        bq, bk, bqd, bkd, qq, kk);
    mma_energy<<<dim3(NN / 128, NN / 128, BB), 256, H1_SMEM_BYTES>>>(qq, kk, e);
    softmax_rows<<<BB * NN, 256>>>(e, p, s);

    // Join: out needs v.
    cudaStreamWaitEvent(0, evV, 0);
    mma_out<<<dim3(CC / 128, NN / 128, BB), 256, H1_SMEM_BYTES>>>(vv, p, x, gamma, s, out);
}